// round 1
// baseline (speedup 1.0000x reference)
#include <cuda_runtime.h>
#include <math.h>

#define B_SZ   4
#define S_LEN  2048
#define D_MOD  1024
#define NH     16
#define DKH    64
#define MROWS  (B_SZ * S_LEN)   // 8192

// Scratch (allocation-free rule: __device__ globals)
__device__ float g_Q[MROWS * D_MOD];
__device__ float g_K[MROWS * D_MOD];
__device__ float g_V[MROWS * D_MOD];
__device__ float g_O[MROWS * D_MOD];

// ---------------------------------------------------------------------------
// SGEMM: C[M,N] = A[M,K] @ W[N,K]^T + bias[N]
// 128x128 block tile, BK=16, 256 threads, 8x8 per-thread micro-tile.
// ---------------------------------------------------------------------------
__global__ __launch_bounds__(256) void sgemm_bias_kernel(
    const float* __restrict__ A, const float* __restrict__ W,
    const float* __restrict__ bias, float* __restrict__ C,
    int M, int N, int K)
{
    __shared__ float As[16][132];   // [k][m], padded stride 132 (528B, 16B-aligned)
    __shared__ float Bs[16][132];   // [k][n]

    const int bm = blockIdx.y * 128;
    const int bn = blockIdx.x * 128;
    const int tid = threadIdx.x;
    const int ty = tid >> 4;        // 0..15 -> rows ty*8..ty*8+7
    const int tx = tid & 15;        // 0..15 -> cols tx*8..tx*8+7
    const int ar = tid >> 2;        // 0..63
    const int ac = (tid & 3) << 2;  // 0,4,8,12

    float acc[8][8];
#pragma unroll
    for (int i = 0; i < 8; ++i)
#pragma unroll
        for (int j = 0; j < 8; ++j) acc[i][j] = 0.f;

    for (int k0 = 0; k0 < K; k0 += 16) {
        float4 a0 = *(const float4*)(A + (size_t)(bm + ar)      * K + k0 + ac);
        float4 a1 = *(const float4*)(A + (size_t)(bm + ar + 64) * K + k0 + ac);
        float4 b0 = *(const float4*)(W + (size_t)(bn + ar)      * K + k0 + ac);
        float4 b1 = *(const float4*)(W + (size_t)(bn + ar + 64) * K + k0 + ac);
        __syncthreads();
        As[ac + 0][ar] = a0.x; As[ac + 1][ar] = a0.y;
        As[ac + 2][ar] = a0.z; As[ac + 3][ar] = a0.w;
        As[ac + 0][ar + 64] = a1.x; As[ac + 1][ar + 64] = a1.y;
        As[ac + 2][ar + 64] = a1.z; As[ac + 3][ar + 64] = a1.w;
        Bs[ac + 0][ar] = b0.x; Bs[ac + 1][ar] = b0.y;
        Bs[ac + 2][ar] = b0.z; Bs[ac + 3][ar] = b0.w;
        Bs[ac + 0][ar + 64] = b1.x; Bs[ac + 1][ar + 64] = b1.y;
        Bs[ac + 2][ar + 64] = b1.z; Bs[ac + 3][ar + 64] = b1.w;
        __syncthreads();
#pragma unroll
        for (int k = 0; k < 16; ++k) {
            float ra[8], rb[8];
            *(float4*)(ra)     = *(const float4*)(&As[k][ty * 8]);
            *(float4*)(ra + 4) = *(const float4*)(&As[k][ty * 8 + 4]);
            *(float4*)(rb)     = *(const float4*)(&Bs[k][tx * 8]);
            *(float4*)(rb + 4) = *(const float4*)(&Bs[k][tx * 8 + 4]);
#pragma unroll
            for (int i = 0; i < 8; ++i)
#pragma unroll
                for (int j = 0; j < 8; ++j)
                    acc[i][j] = fmaf(ra[i], rb[j], acc[i][j]);
        }
    }

    float bv[8];
    *(float4*)(bv)     = *(const float4*)(bias + bn + tx * 8);
    *(float4*)(bv + 4) = *(const float4*)(bias + bn + tx * 8 + 4);
#pragma unroll
    for (int i = 0; i < 8; ++i) {
        const size_t row = (size_t)(bm + ty * 8 + i);
        float4 c0, c1;
        c0.x = acc[i][0] + bv[0]; c0.y = acc[i][1] + bv[1];
        c0.z = acc[i][2] + bv[2]; c0.w = acc[i][3] + bv[3];
        c1.x = acc[i][4] + bv[4]; c1.y = acc[i][5] + bv[5];
        c1.z = acc[i][6] + bv[6]; c1.w = acc[i][7] + bv[7];
        *(float4*)(C + row * N + bn + tx * 8)     = c0;
        *(float4*)(C + row * N + bn + tx * 8 + 4) = c1;
    }
}

// ---------------------------------------------------------------------------
// Flash attention, fp32, causal. BM=128 q-rows, BN=64 kv-cols, DK=64.
// 256 threads: ty=tid>>4 owns 8 q-rows, tx=tid&15 owns 4 kv-cols / 4 dv-cols.
// Dynamic smem: sQt[64][128] + sKt[64][64] + sV[64][64] + sPt[64][128] = 96KB.
// ---------------------------------------------------------------------------
__global__ __launch_bounds__(256, 2) void flash_kernel(
    const float* __restrict__ Q, const float* __restrict__ K,
    const float* __restrict__ V, float* __restrict__ O)
{
    extern __shared__ float sm[];
    float* sQt = sm;                 // [d][m]  d-major, stride 128
    float* sKt = sQt + 64 * 128;     // [d][n]  stride 64
    float* sV  = sKt + 64 * 64;      // [c][dv] natural, stride 64
    float* sPt = sV  + 64 * 64;      // [c][m]  stride 128

    const int qb  = blockIdx.x;      // 0..15 (q tile of 128 rows)
    const int h   = blockIdx.y;
    const int b   = blockIdx.z;
    const int tid = threadIdx.x;
    const int ty  = tid >> 4;
    const int tx  = tid & 15;
    const size_t base = (size_t)b * S_LEN * D_MOD + (size_t)h * DKH;

    // Stage Q tile (coalesced global, scattered smem stores — one-time cost)
#pragma unroll
    for (int t = 0; t < 8; ++t) {
        int idx = tid + t * 256;
        int r  = idx >> 4;
        int c4 = (idx & 15) << 2;
        float4 v = *(const float4*)(Q + base + (size_t)(qb * 128 + r) * D_MOD + c4);
        sQt[(c4 + 0) * 128 + r] = v.x;
        sQt[(c4 + 1) * 128 + r] = v.y;
        sQt[(c4 + 2) * 128 + r] = v.z;
        sQt[(c4 + 3) * 128 + r] = v.w;
    }

    float m_i[8], l_i[8], o[8][4];
#pragma unroll
    for (int i = 0; i < 8; ++i) {
        m_i[i] = -1e30f; l_i[i] = 0.f;
#pragma unroll
        for (int j = 0; j < 4; ++j) o[i][j] = 0.f;
    }

    const float scale = 0.125f;      // 1/sqrt(64)
    const int jmax = 2 * qb + 1;

    for (int j = 0; j <= jmax; ++j) {
        __syncthreads();  // prior-iter readers of sKt/sV done (also orders sQt on j=0)
#pragma unroll
        for (int t = 0; t < 4; ++t) {
            int idx = tid + t * 256;
            int r  = idx >> 4;
            int c4 = (idx & 15) << 2;
            float4 kv = *(const float4*)(K + base + (size_t)(j * 64 + r) * D_MOD + c4);
            sKt[(c4 + 0) * 64 + r] = kv.x;
            sKt[(c4 + 1) * 64 + r] = kv.y;
            sKt[(c4 + 2) * 64 + r] = kv.z;
            sKt[(c4 + 3) * 64 + r] = kv.w;
            float4 vv = *(const float4*)(V + base + (size_t)(j * 64 + r) * D_MOD + c4);
            *(float4*)(sV + r * 64 + c4) = vv;
        }
        __syncthreads();

        // S = scale * Q K^T   (s[8][4] per thread)
        float s[8][4];
#pragma unroll
        for (int i = 0; i < 8; ++i)
#pragma unroll
            for (int jj = 0; jj < 4; ++jj) s[i][jj] = 0.f;
#pragma unroll 16
        for (int d = 0; d < 64; ++d) {
            float ra[8], rb[4];
            *(float4*)(ra)     = *(const float4*)(sQt + d * 128 + ty * 8);
            *(float4*)(ra + 4) = *(const float4*)(sQt + d * 128 + ty * 8 + 4);
            *(float4*)(rb)     = *(const float4*)(sKt + d * 64 + tx * 4);
#pragma unroll
            for (int i = 0; i < 8; ++i)
#pragma unroll
                for (int jj = 0; jj < 4; ++jj)
                    s[i][jj] = fmaf(ra[i], rb[jj], s[i][jj]);
        }

        const bool diag = (j >= 2 * qb);
#pragma unroll
        for (int i = 0; i < 8; ++i) {
#pragma unroll
            for (int jj = 0; jj < 4; ++jj) {
                s[i][jj] *= scale;
                if (diag && (j * 64 + tx * 4 + jj > qb * 128 + ty * 8 + i))
                    s[i][jj] = -1e30f;
            }
        }

        // Online softmax update
        float alpha[8];
#pragma unroll
        for (int i = 0; i < 8; ++i) {
            float mt = fmaxf(fmaxf(s[i][0], s[i][1]), fmaxf(s[i][2], s[i][3]));
#pragma unroll
            for (int off = 1; off < 16; off <<= 1)
                mt = fmaxf(mt, __shfl_xor_sync(0xffffffffu, mt, off));
            float mn = fmaxf(m_i[i], mt);
            alpha[i] = __expf(m_i[i] - mn);
            m_i[i] = mn;
        }
#pragma unroll
        for (int i = 0; i < 8; ++i) {
            float rs = 0.f;
#pragma unroll
            for (int jj = 0; jj < 4; ++jj) {
                float p = __expf(s[i][jj] - m_i[i]);
                s[i][jj] = p;
                rs += p;
            }
#pragma unroll
            for (int off = 1; off < 16; off <<= 1)
                rs += __shfl_xor_sync(0xffffffffu, rs, off);
            l_i[i] = l_i[i] * alpha[i] + rs;
#pragma unroll
            for (int jj = 0; jj < 4; ++jj) o[i][jj] *= alpha[i];
        }

        // Stage P transposed [c][m]
#pragma unroll
        for (int i = 0; i < 8; ++i)
#pragma unroll
            for (int jj = 0; jj < 4; ++jj)
                sPt[(tx * 4 + jj) * 128 + ty * 8 + i] = s[i][jj];
        __syncthreads();

        // O += P @ V
#pragma unroll 16
        for (int c = 0; c < 64; ++c) {
            float rp[8], rv[4];
            *(float4*)(rp)     = *(const float4*)(sPt + c * 128 + ty * 8);
            *(float4*)(rp + 4) = *(const float4*)(sPt + c * 128 + ty * 8 + 4);
            *(float4*)(rv)     = *(const float4*)(sV + c * 64 + tx * 4);
#pragma unroll
            for (int i = 0; i < 8; ++i)
#pragma unroll
                for (int jj = 0; jj < 4; ++jj)
                    o[i][jj] = fmaf(rp[i], rv[jj], o[i][jj]);
        }
    }

    // Epilogue: normalize and write in [b*S+s, h*DK+dv] layout
#pragma unroll
    for (int i = 0; i < 8; ++i) {
        float inv = 1.0f / l_i[i];
        float4 w;
        w.x = o[i][0] * inv; w.y = o[i][1] * inv;
        w.z = o[i][2] * inv; w.w = o[i][3] * inv;
        *(float4*)(O + base + (size_t)(qb * 128 + ty * 8 + i) * D_MOD + tx * 4) = w;
    }
}

// ---------------------------------------------------------------------------
extern "C" void kernel_launch(void* const* d_in, const int* in_sizes, int n_in,
                              void* d_out, int out_size)
{
    const float* query = (const float*)d_in[0];
    const float* key_  = (const float*)d_in[1];
    const float* value = (const float*)d_in[2];
    const float* Wq = (const float*)d_in[3];
    const float* bq = (const float*)d_in[4];
    const float* Wk = (const float*)d_in[5];
    const float* bk = (const float*)d_in[6];
    const float* Wv = (const float*)d_in[7];
    const float* bv = (const float*)d_in[8];
    const float* Wo = (const float*)d_in[9];
    const float* bo = (const float*)d_in[10];
    // d_in[11] = causal mask (bool) — causality implemented analytically.

    float *Qp, *Kp, *Vp, *Op;
    cudaGetSymbolAddress((void**)&Qp, g_Q);
    cudaGetSymbolAddress((void**)&Kp, g_K);
    cudaGetSymbolAddress((void**)&Vp, g_V);
    cudaGetSymbolAddress((void**)&Op, g_O);

    cudaFuncSetAttribute(flash_kernel,
                         cudaFuncAttributeMaxDynamicSharedMemorySize, 98304);

    dim3 gg(D_MOD / 128, MROWS / 128);  // (8, 64)
    sgemm_bias_kernel<<<gg, 256>>>(query, Wq, bq, Qp, MROWS, D_MOD, D_MOD);
    sgemm_bias_kernel<<<gg, 256>>>(key_,  Wk, bk, Kp, MROWS, D_MOD, D_MOD);
    sgemm_bias_kernel<<<gg, 256>>>(value, Wv, bv, Vp, MROWS, D_MOD, D_MOD);

    flash_kernel<<<dim3(S_LEN / 128, NH, B_SZ), 256, 98304>>>(Qp, Kp, Vp, Op);

    sgemm_bias_kernel<<<gg, 256>>>(Op, Wo, bo, (float*)d_out, MROWS, D_MOD, D_MOD);
}

// round 2
// speedup vs baseline: 1.5730x; 1.5730x over previous
#include <cuda_runtime.h>
#include <math.h>
#include <stdint.h>

#define B_SZ   4
#define S_LEN  2048
#define D_MOD  1024
#define NH     16
#define DKH    64
#define MROWS  (B_SZ * S_LEN)   // 8192

// Scratch (allocation-free rule: __device__ globals)
__device__ float g_Q[MROWS * D_MOD];
__device__ float g_K[MROWS * D_MOD];
__device__ float g_V[MROWS * D_MOD];
__device__ float g_O[MROWS * D_MOD];

__device__ __forceinline__ uint32_t f2tf32(float x) {
    uint32_t r;
    asm("cvt.rna.tf32.f32 %0, %1;" : "=r"(r) : "f"(x));
    return r;
}

// ---------------------------------------------------------------------------
// TF32 tensor-core GEMM: C[M,N] = A[M,K] @ W[N,K]^T + bias[N]
// 128x128 block tile, BK=32, 256 threads (8 warps in 2m x 4n grid),
// each warp: 64x32 via 4x4 tiles of mma.sync.m16n8k8.
// Smem stride 36 words (== 4 mod 32) -> conflict-free fragment LDS.
// ---------------------------------------------------------------------------
__global__ __launch_bounds__(256, 2) void sgemm_tf32_kernel(
    const float* __restrict__ A, const float* __restrict__ W,
    const float* __restrict__ bias, float* __restrict__ C,
    int M, int N, int K)
{
    __shared__ uint32_t As[128][36];
    __shared__ uint32_t Ws[128][36];

    const int bm = blockIdx.y * 128;
    const int bn = blockIdx.x * 128;
    const int tid  = threadIdx.x;
    const int wid  = tid >> 5;
    const int lane = tid & 31;
    const int wm = (wid & 1) * 64;     // warp m-offset
    const int wn = (wid >> 1) * 32;    // warp n-offset
    const int lr  = tid >> 3;          // staging row 0..31
    const int lc4 = (tid & 7) << 2;    // staging col 0,4,...,28

    float acc[4][4][4];
#pragma unroll
    for (int mt = 0; mt < 4; ++mt)
#pragma unroll
        for (int nt = 0; nt < 4; ++nt)
#pragma unroll
            for (int i = 0; i < 4; ++i) acc[mt][nt][i] = 0.f;

    const int gq = lane >> 2;   // quad group 0..7
    const int gr = lane & 3;    // in-quad 0..3

    for (int k0 = 0; k0 < K; k0 += 32) {
        float4 av[4], wv[4];
#pragma unroll
        for (int p = 0; p < 4; ++p) {
            av[p] = *(const float4*)(A + (size_t)(bm + lr + p * 32) * K + k0 + lc4);
            wv[p] = *(const float4*)(W + (size_t)(bn + lr + p * 32) * K + k0 + lc4);
        }
        __syncthreads();
#pragma unroll
        for (int p = 0; p < 4; ++p) {
            As[lr + p * 32][lc4 + 0] = f2tf32(av[p].x);
            As[lr + p * 32][lc4 + 1] = f2tf32(av[p].y);
            As[lr + p * 32][lc4 + 2] = f2tf32(av[p].z);
            As[lr + p * 32][lc4 + 3] = f2tf32(av[p].w);
            Ws[lr + p * 32][lc4 + 0] = f2tf32(wv[p].x);
            Ws[lr + p * 32][lc4 + 1] = f2tf32(wv[p].y);
            Ws[lr + p * 32][lc4 + 2] = f2tf32(wv[p].z);
            Ws[lr + p * 32][lc4 + 3] = f2tf32(wv[p].w);
        }
        __syncthreads();

#pragma unroll
        for (int c = 0; c < 4; ++c) {
            const int kk = c * 8 + gr;
            uint32_t a[4][4], b[4][2];
#pragma unroll
            for (int mt = 0; mt < 4; ++mt) {
                const int r0 = wm + mt * 16 + gq;
                a[mt][0] = As[r0][kk];
                a[mt][1] = As[r0 + 8][kk];
                a[mt][2] = As[r0][kk + 4];
                a[mt][3] = As[r0 + 8][kk + 4];
            }
#pragma unroll
            for (int nt = 0; nt < 4; ++nt) {
                const int n0 = wn + nt * 8 + gq;
                b[nt][0] = Ws[n0][kk];
                b[nt][1] = Ws[n0][kk + 4];
            }
#pragma unroll
            for (int mt = 0; mt < 4; ++mt)
#pragma unroll
                for (int nt = 0; nt < 4; ++nt)
                    asm volatile(
                        "mma.sync.aligned.m16n8k8.row.col.f32.tf32.tf32.f32 "
                        "{%0,%1,%2,%3}, {%4,%5,%6,%7}, {%8,%9}, {%0,%1,%2,%3};"
                        : "+f"(acc[mt][nt][0]), "+f"(acc[mt][nt][1]),
                          "+f"(acc[mt][nt][2]), "+f"(acc[mt][nt][3])
                        : "r"(a[mt][0]), "r"(a[mt][1]), "r"(a[mt][2]), "r"(a[mt][3]),
                          "r"(b[nt][0]), "r"(b[nt][1]));
        }
    }

    // Epilogue: acc fragment layout m16n8: c0/c1 at (row gq, cols 2*gr, 2*gr+1),
    // c2/c3 at row gq+8.
    const int c2 = gr * 2;
#pragma unroll
    for (int mt = 0; mt < 4; ++mt) {
#pragma unroll
        for (int nt = 0; nt < 4; ++nt) {
            const int col = bn + wn + nt * 8 + c2;
            const float b0 = bias[col], b1 = bias[col + 1];
            const size_t row0 = (size_t)(bm + wm + mt * 16 + gq);
            float2 v0, v1;
            v0.x = acc[mt][nt][0] + b0; v0.y = acc[mt][nt][1] + b1;
            v1.x = acc[mt][nt][2] + b0; v1.y = acc[mt][nt][3] + b1;
            *(float2*)(C + row0 * N + col)       = v0;
            *(float2*)(C + (row0 + 8) * N + col) = v1;
        }
    }
}

// ---------------------------------------------------------------------------
// Flash attention, fp32, causal. BM=128 q-rows, BN=64 kv-cols, DK=64.
// 256 threads: ty=tid>>4 owns 8 q-rows, tx=tid&15 owns 4 kv-cols / 4 dv-cols.
// Dynamic smem: sQt[64][128] + sKt[64][64] + sV[64][64] + sPt[64][128] = 96KB.
// ---------------------------------------------------------------------------
__global__ __launch_bounds__(256, 2) void flash_kernel(
    const float* __restrict__ Q, const float* __restrict__ K,
    const float* __restrict__ V, float* __restrict__ O)
{
    extern __shared__ float sm[];
    float* sQt = sm;                 // [d][m]  d-major, stride 128
    float* sKt = sQt + 64 * 128;     // [d][n]  stride 64
    float* sV  = sKt + 64 * 64;      // [c][dv] natural, stride 64
    float* sPt = sV  + 64 * 64;      // [c][m]  stride 128

    const int qb  = blockIdx.x;      // 0..15 (q tile of 128 rows)
    const int h   = blockIdx.y;
    const int b   = blockIdx.z;
    const int tid = threadIdx.x;
    const int ty  = tid >> 4;
    const int tx  = tid & 15;
    const size_t base = (size_t)b * S_LEN * D_MOD + (size_t)h * DKH;

#pragma unroll
    for (int t = 0; t < 8; ++t) {
        int idx = tid + t * 256;
        int r  = idx >> 4;
        int c4 = (idx & 15) << 2;
        float4 v = *(const float4*)(Q + base + (size_t)(qb * 128 + r) * D_MOD + c4);
        sQt[(c4 + 0) * 128 + r] = v.x;
        sQt[(c4 + 1) * 128 + r] = v.y;
        sQt[(c4 + 2) * 128 + r] = v.z;
        sQt[(c4 + 3) * 128 + r] = v.w;
    }

    float m_i[8], l_i[8], o[8][4];
#pragma unroll
    for (int i = 0; i < 8; ++i) {
        m_i[i] = -1e30f; l_i[i] = 0.f;
#pragma unroll
        for (int j = 0; j < 4; ++j) o[i][j] = 0.f;
    }

    const float scale = 0.125f;      // 1/sqrt(64)
    const int jmax = 2 * qb + 1;

    for (int j = 0; j <= jmax; ++j) {
        __syncthreads();
#pragma unroll
        for (int t = 0; t < 4; ++t) {
            int idx = tid + t * 256;
            int r  = idx >> 4;
            int c4 = (idx & 15) << 2;
            float4 kv = *(const float4*)(K + base + (size_t)(j * 64 + r) * D_MOD + c4);
            sKt[(c4 + 0) * 64 + r] = kv.x;
            sKt[(c4 + 1) * 64 + r] = kv.y;
            sKt[(c4 + 2) * 64 + r] = kv.z;
            sKt[(c4 + 3) * 64 + r] = kv.w;
            float4 vv = *(const float4*)(V + base + (size_t)(j * 64 + r) * D_MOD + c4);
            *(float4*)(sV + r * 64 + c4) = vv;
        }
        __syncthreads();

        float s[8][4];
#pragma unroll
        for (int i = 0; i < 8; ++i)
#pragma unroll
            for (int jj = 0; jj < 4; ++jj) s[i][jj] = 0.f;
#pragma unroll 16
        for (int d = 0; d < 64; ++d) {
            float ra[8], rb[4];
            *(float4*)(ra)     = *(const float4*)(sQt + d * 128 + ty * 8);
            *(float4*)(ra + 4) = *(const float4*)(sQt + d * 128 + ty * 8 + 4);
            *(float4*)(rb)     = *(const float4*)(sKt + d * 64 + tx * 4);
#pragma unroll
            for (int i = 0; i < 8; ++i)
#pragma unroll
                for (int jj = 0; jj < 4; ++jj)
                    s[i][jj] = fmaf(ra[i], rb[jj], s[i][jj]);
        }

        const bool diag = (j >= 2 * qb);
#pragma unroll
        for (int i = 0; i < 8; ++i) {
#pragma unroll
            for (int jj = 0; jj < 4; ++jj) {
                s[i][jj] *= scale;
                if (diag && (j * 64 + tx * 4 + jj > qb * 128 + ty * 8 + i))
                    s[i][jj] = -1e30f;
            }
        }

        float alpha[8];
#pragma unroll
        for (int i = 0; i < 8; ++i) {
            float mt = fmaxf(fmaxf(s[i][0], s[i][1]), fmaxf(s[i][2], s[i][3]));
#pragma unroll
            for (int off = 1; off < 16; off <<= 1)
                mt = fmaxf(mt, __shfl_xor_sync(0xffffffffu, mt, off));
            float mn = fmaxf(m_i[i], mt);
            alpha[i] = __expf(m_i[i] - mn);
            m_i[i] = mn;
        }
#pragma unroll
        for (int i = 0; i < 8; ++i) {
            float rs = 0.f;
#pragma unroll
            for (int jj = 0; jj < 4; ++jj) {
                float p = __expf(s[i][jj] - m_i[i]);
                s[i][jj] = p;
                rs += p;
            }
#pragma unroll
            for (int off = 1; off < 16; off <<= 1)
                rs += __shfl_xor_sync(0xffffffffu, rs, off);
            l_i[i] = l_i[i] * alpha[i] + rs;
#pragma unroll
            for (int jj = 0; jj < 4; ++jj) o[i][jj] *= alpha[i];
        }

#pragma unroll
        for (int i = 0; i < 8; ++i)
#pragma unroll
            for (int jj = 0; jj < 4; ++jj)
                sPt[(tx * 4 + jj) * 128 + ty * 8 + i] = s[i][jj];
        __syncthreads();

#pragma unroll 16
        for (int c = 0; c < 64; ++c) {
            float rp[8], rv[4];
            *(float4*)(rp)     = *(const float4*)(sPt + c * 128 + ty * 8);
            *(float4*)(rp + 4) = *(const float4*)(sPt + c * 128 + ty * 8 + 4);
            *(float4*)(rv)     = *(const float4*)(sV + c * 64 + tx * 4);
#pragma unroll
            for (int i = 0; i < 8; ++i)
#pragma unroll
                for (int jj = 0; jj < 4; ++jj)
                    o[i][jj] = fmaf(rp[i], rv[jj], o[i][jj]);
        }
    }

#pragma unroll
    for (int i = 0; i < 8; ++i) {
        float inv = 1.0f / l_i[i];
        float4 w;
        w.x = o[i][0] * inv; w.y = o[i][1] * inv;
        w.z = o[i][2] * inv; w.w = o[i][3] * inv;
        *(float4*)(O + base + (size_t)(qb * 128 + ty * 8 + i) * D_MOD + tx * 4) = w;
    }
}

// ---------------------------------------------------------------------------
extern "C" void kernel_launch(void* const* d_in, const int* in_sizes, int n_in,
                              void* d_out, int out_size)
{
    const float* query = (const float*)d_in[0];
    const float* key_  = (const float*)d_in[1];
    const float* value = (const float*)d_in[2];
    const float* Wq = (const float*)d_in[3];
    const float* bq = (const float*)d_in[4];
    const float* Wk = (const float*)d_in[5];
    const float* bk = (const float*)d_in[6];
    const float* Wv = (const float*)d_in[7];
    const float* bv = (const float*)d_in[8];
    const float* Wo = (const float*)d_in[9];
    const float* bo = (const float*)d_in[10];
    // d_in[11] = causal mask (bool) — causality implemented analytically.

    float *Qp, *Kp, *Vp, *Op;
    cudaGetSymbolAddress((void**)&Qp, g_Q);
    cudaGetSymbolAddress((void**)&Kp, g_K);
    cudaGetSymbolAddress((void**)&Vp, g_V);
    cudaGetSymbolAddress((void**)&Op, g_O);

    cudaFuncSetAttribute(flash_kernel,
                         cudaFuncAttributeMaxDynamicSharedMemorySize, 98304);

    dim3 gg(D_MOD / 128, MROWS / 128);  // (8, 64)
    sgemm_tf32_kernel<<<gg, 256>>>(query, Wq, bq, Qp, MROWS, D_MOD, D_MOD);
    sgemm_tf32_kernel<<<gg, 256>>>(key_,  Wk, bk, Kp, MROWS, D_MOD, D_MOD);
    sgemm_tf32_kernel<<<gg, 256>>>(value, Wv, bv, Vp, MROWS, D_MOD, D_MOD);

    flash_kernel<<<dim3(S_LEN / 128, NH, B_SZ), 256, 98304>>>(Qp, Kp, Vp, Op);

    sgemm_tf32_kernel<<<gg, 256>>>(Op, Wo, bo, (float*)d_out, MROWS, D_MOD, D_MOD);
}

// round 3
// speedup vs baseline: 1.6581x; 1.0541x over previous
#include <cuda_runtime.h>
#include <math.h>
#include <stdint.h>

#define B_SZ   4
#define S_LEN  2048
#define D_MOD  1024
#define NH     16
#define DKH    64
#define MROWS  (B_SZ * S_LEN)   // 8192

// Scratch (allocation-free rule: __device__ globals)
__device__ float g_Q[MROWS * D_MOD];
__device__ float g_K[MROWS * D_MOD];
__device__ float g_V[MROWS * D_MOD];
__device__ float g_O[MROWS * D_MOD];

__device__ __forceinline__ uint32_t f2tf32(float x) {
    uint32_t r;
    asm("cvt.rna.tf32.f32 %0, %1;" : "=r"(r) : "f"(x));
    return r;
}

// ---------------------------------------------------------------------------
// TF32 tensor-core GEMM, double-buffered: C[M,N] = A[M,K] @ W[N,K]^T + bias[N]
// 128x128 block tile, BK=32, 2-stage smem ping-pong, 256 threads
// (8 warps 2m x 4n), each warp 64x32 via 4x4 tiles of mma.sync.m16n8k8.
// Smem stride 36 words (== 4 mod 32) -> conflict-free fragment LDS.
// Dynamic smem: 2 stages * (A 128x36 + W 128x36) * 4B = 73728 B.
// ---------------------------------------------------------------------------
#define GEMM_SMEM_BYTES (4 * 128 * 36 * 4)

__global__ __launch_bounds__(256, 2) void sgemm_tf32_kernel(
    const float* __restrict__ A, const float* __restrict__ W,
    const float* __restrict__ bias, float* __restrict__ C,
    int M, int N, int K)
{
    extern __shared__ uint32_t sm_u[];
    uint32_t* const Ast0 = sm_u;
    uint32_t* const Ast1 = sm_u + 128 * 36;
    uint32_t* const Wst0 = sm_u + 2 * 128 * 36;
    uint32_t* const Wst1 = sm_u + 3 * 128 * 36;

    const int bm = blockIdx.y * 128;
    const int bn = blockIdx.x * 128;
    const int tid  = threadIdx.x;
    const int wid  = tid >> 5;
    const int lane = tid & 31;
    const int wm = (wid & 1) * 64;     // warp m-offset
    const int wn = (wid >> 1) * 32;    // warp n-offset
    const int lr  = tid >> 3;          // staging row 0..31
    const int lc4 = (tid & 7) << 2;    // staging k-col 0,4,...,28
    const int gq = lane >> 2;          // quad group 0..7
    const int gr = lane & 3;           // in-quad 0..3

    float acc[4][4][4];
#pragma unroll
    for (int mt = 0; mt < 4; ++mt)
#pragma unroll
        for (int nt = 0; nt < 4; ++nt)
#pragma unroll
            for (int i = 0; i < 4; ++i) acc[mt][nt][i] = 0.f;

    const float* Ag = A + (size_t)(bm + lr) * K + lc4;
    const float* Wg = W + (size_t)(bn + lr) * K + lc4;

    float4 av[4], wv[4];
#pragma unroll
    for (int p = 0; p < 4; ++p) {
        av[p] = *(const float4*)(Ag + (size_t)(p * 32) * K);
        wv[p] = *(const float4*)(Wg + (size_t)(p * 32) * K);
    }
    // STS stage 0
#pragma unroll
    for (int p = 0; p < 4; ++p) {
        uint32_t* as = Ast0 + (lr + p * 32) * 36 + lc4;
        uint32_t* ws = Wst0 + (lr + p * 32) * 36 + lc4;
        as[0] = f2tf32(av[p].x); as[1] = f2tf32(av[p].y);
        as[2] = f2tf32(av[p].z); as[3] = f2tf32(av[p].w);
        ws[0] = f2tf32(wv[p].x); ws[1] = f2tf32(wv[p].y);
        ws[2] = f2tf32(wv[p].z); ws[3] = f2tf32(wv[p].w);
    }
    __syncthreads();

    const int nIter = K >> 5;          // 32
    for (int it = 0; it < nIter; ++it) {
        const bool more = (it + 1 < nIter);
        if (more) {
            const int k1 = (it + 1) << 5;
#pragma unroll
            for (int p = 0; p < 4; ++p) {
                av[p] = *(const float4*)(Ag + (size_t)(p * 32) * K + k1);
                wv[p] = *(const float4*)(Wg + (size_t)(p * 32) * K + k1);
            }
        }

        const uint32_t* Acur = (it & 1) ? Ast1 : Ast0;
        const uint32_t* Wcur = (it & 1) ? Wst1 : Wst0;
#pragma unroll
        for (int c = 0; c < 4; ++c) {
            const int kk = c * 8 + gr;
            uint32_t a[4][4], b[4][2];
#pragma unroll
            for (int mt = 0; mt < 4; ++mt) {
                const int r0 = wm + mt * 16 + gq;
                a[mt][0] = Acur[r0 * 36 + kk];
                a[mt][1] = Acur[(r0 + 8) * 36 + kk];
                a[mt][2] = Acur[r0 * 36 + kk + 4];
                a[mt][3] = Acur[(r0 + 8) * 36 + kk + 4];
            }
#pragma unroll
            for (int nt = 0; nt < 4; ++nt) {
                const int n0 = wn + nt * 8 + gq;
                b[nt][0] = Wcur[n0 * 36 + kk];
                b[nt][1] = Wcur[n0 * 36 + kk + 4];
            }
#pragma unroll
            for (int mt = 0; mt < 4; ++mt)
#pragma unroll
                for (int nt = 0; nt < 4; ++nt)
                    asm volatile(
                        "mma.sync.aligned.m16n8k8.row.col.f32.tf32.tf32.f32 "
                        "{%0,%1,%2,%3}, {%4,%5,%6,%7}, {%8,%9}, {%0,%1,%2,%3};"
                        : "+f"(acc[mt][nt][0]), "+f"(acc[mt][nt][1]),
                          "+f"(acc[mt][nt][2]), "+f"(acc[mt][nt][3])
                        : "r"(a[mt][0]), "r"(a[mt][1]), "r"(a[mt][2]), "r"(a[mt][3]),
                          "r"(b[nt][0]), "r"(b[nt][1]));
        }

        if (more) {
            __syncthreads();   // WAR: stage (it+1)&1 readers (iter it-1) all done
            uint32_t* Anx = ((it + 1) & 1) ? Ast1 : Ast0;
            uint32_t* Wnx = ((it + 1) & 1) ? Wst1 : Wst0;
#pragma unroll
            for (int p = 0; p < 4; ++p) {
                uint32_t* as = Anx + (lr + p * 32) * 36 + lc4;
                uint32_t* ws = Wnx + (lr + p * 32) * 36 + lc4;
                as[0] = f2tf32(av[p].x); as[1] = f2tf32(av[p].y);
                as[2] = f2tf32(av[p].z); as[3] = f2tf32(av[p].w);
                ws[0] = f2tf32(wv[p].x); ws[1] = f2tf32(wv[p].y);
                ws[2] = f2tf32(wv[p].z); ws[3] = f2tf32(wv[p].w);
            }
            __syncthreads();   // RAW: stage visible before next compute
        }
    }

    // Epilogue: m16n8 acc layout: c0/c1 at (row gq, cols 2gr,2gr+1), c2/c3 row gq+8.
    const int c2 = gr * 2;
#pragma unroll
    for (int mt = 0; mt < 4; ++mt) {
#pragma unroll
        for (int nt = 0; nt < 4; ++nt) {
            const int col = bn + wn + nt * 8 + c2;
            const float b0 = bias[col], b1 = bias[col + 1];
            const size_t row0 = (size_t)(bm + wm + mt * 16 + gq);
            float2 v0, v1;
            v0.x = acc[mt][nt][0] + b0; v0.y = acc[mt][nt][1] + b1;
            v1.x = acc[mt][nt][2] + b0; v1.y = acc[mt][nt][3] + b1;
            *(float2*)(C + row0 * N + col)       = v0;
            *(float2*)(C + (row0 + 8) * N + col) = v1;
        }
    }
}

// ---------------------------------------------------------------------------
// Flash attention, fp32, causal. BM=128 q-rows, BN=64 kv-cols, DK=64.
// 256 threads: ty=tid>>4 owns 8 q-rows, tx=tid&15 owns 4 kv-cols / 4 dv-cols.
// Dynamic smem: sQt[64][128] + sKt[64][64] + sV[64][64] + sPt[64][128] = 96KB.
// ---------------------------------------------------------------------------
__global__ __launch_bounds__(256, 2) void flash_kernel(
    const float* __restrict__ Q, const float* __restrict__ K,
    const float* __restrict__ V, float* __restrict__ O)
{
    extern __shared__ float sm[];
    float* sQt = sm;                 // [d][m]  d-major, stride 128
    float* sKt = sQt + 64 * 128;     // [d][n]  stride 64
    float* sV  = sKt + 64 * 64;      // [c][dv] natural, stride 64
    float* sPt = sV  + 64 * 64;      // [c][m]  stride 128

    const int qb  = blockIdx.x;      // 0..15 (q tile of 128 rows)
    const int h   = blockIdx.y;
    const int b   = blockIdx.z;
    const int tid = threadIdx.x;
    const int ty  = tid >> 4;
    const int tx  = tid & 15;
    const size_t base = (size_t)b * S_LEN * D_MOD + (size_t)h * DKH;

#pragma unroll
    for (int t = 0; t < 8; ++t) {
        int idx = tid + t * 256;
        int r  = idx >> 4;
        int c4 = (idx & 15) << 2;
        float4 v = *(const float4*)(Q + base + (size_t)(qb * 128 + r) * D_MOD + c4);
        sQt[(c4 + 0) * 128 + r] = v.x;
        sQt[(c4 + 1) * 128 + r] = v.y;
        sQt[(c4 + 2) * 128 + r] = v.z;
        sQt[(c4 + 3) * 128 + r] = v.w;
    }

    float m_i[8], l_i[8], o[8][4];
#pragma unroll
    for (int i = 0; i < 8; ++i) {
        m_i[i] = -1e30f; l_i[i] = 0.f;
#pragma unroll
        for (int j = 0; j < 4; ++j) o[i][j] = 0.f;
    }

    const float scale = 0.125f;      // 1/sqrt(64)
    const int jmax = 2 * qb + 1;

    for (int j = 0; j <= jmax; ++j) {
        __syncthreads();
#pragma unroll
        for (int t = 0; t < 4; ++t) {
            int idx = tid + t * 256;
            int r  = idx >> 4;
            int c4 = (idx & 15) << 2;
            float4 kv = *(const float4*)(K + base + (size_t)(j * 64 + r) * D_MOD + c4);
            sKt[(c4 + 0) * 64 + r] = kv.x;
            sKt[(c4 + 1) * 64 + r] = kv.y;
            sKt[(c4 + 2) * 64 + r] = kv.z;
            sKt[(c4 + 3) * 64 + r] = kv.w;
            float4 vv = *(const float4*)(V + base + (size_t)(j * 64 + r) * D_MOD + c4);
            *(float4*)(sV + r * 64 + c4) = vv;
        }
        __syncthreads();

        float s[8][4];
#pragma unroll
        for (int i = 0; i < 8; ++i)
#pragma unroll
            for (int jj = 0; jj < 4; ++jj) s[i][jj] = 0.f;
#pragma unroll 16
        for (int d = 0; d < 64; ++d) {
            float ra[8], rb[4];
            *(float4*)(ra)     = *(const float4*)(sQt + d * 128 + ty * 8);
            *(float4*)(ra + 4) = *(const float4*)(sQt + d * 128 + ty * 8 + 4);
            *(float4*)(rb)     = *(const float4*)(sKt + d * 64 + tx * 4);
#pragma unroll
            for (int i = 0; i < 8; ++i)
#pragma unroll
                for (int jj = 0; jj < 4; ++jj)
                    s[i][jj] = fmaf(ra[i], rb[jj], s[i][jj]);
        }

        const bool diag = (j >= 2 * qb);
#pragma unroll
        for (int i = 0; i < 8; ++i) {
#pragma unroll
            for (int jj = 0; jj < 4; ++jj) {
                s[i][jj] *= scale;
                if (diag && (j * 64 + tx * 4 + jj > qb * 128 + ty * 8 + i))
                    s[i][jj] = -1e30f;
            }
        }

        float alpha[8];
#pragma unroll
        for (int i = 0; i < 8; ++i) {
            float mt = fmaxf(fmaxf(s[i][0], s[i][1]), fmaxf(s[i][2], s[i][3]));
#pragma unroll
            for (int off = 1; off < 16; off <<= 1)
                mt = fmaxf(mt, __shfl_xor_sync(0xffffffffu, mt, off));
            float mn = fmaxf(m_i[i], mt);
            alpha[i] = __expf(m_i[i] - mn);
            m_i[i] = mn;
        }
#pragma unroll
        for (int i = 0; i < 8; ++i) {
            float rs = 0.f;
#pragma unroll
            for (int jj = 0; jj < 4; ++jj) {
                float p = __expf(s[i][jj] - m_i[i]);
                s[i][jj] = p;
                rs += p;
            }
#pragma unroll
            for (int off = 1; off < 16; off <<= 1)
                rs += __shfl_xor_sync(0xffffffffu, rs, off);
            l_i[i] = l_i[i] * alpha[i] + rs;
#pragma unroll
            for (int jj = 0; jj < 4; ++jj) o[i][jj] *= alpha[i];
        }

#pragma unroll
        for (int i = 0; i < 8; ++i)
#pragma unroll
            for (int jj = 0; jj < 4; ++jj)
                sPt[(tx * 4 + jj) * 128 + ty * 8 + i] = s[i][jj];
        __syncthreads();

#pragma unroll 16
        for (int c = 0; c < 64; ++c) {
            float rp[8], rv[4];
            *(float4*)(rp)     = *(const float4*)(sPt + c * 128 + ty * 8);
            *(float4*)(rp + 4) = *(const float4*)(sPt + c * 128 + ty * 8 + 4);
            *(float4*)(rv)     = *(const float4*)(sV + c * 64 + tx * 4);
#pragma unroll
            for (int i = 0; i < 8; ++i)
#pragma unroll
                for (int jj = 0; jj < 4; ++jj)
                    o[i][jj] = fmaf(rp[i], rv[jj], o[i][jj]);
        }
    }

#pragma unroll
    for (int i = 0; i < 8; ++i) {
        float inv = 1.0f / l_i[i];
        float4 w;
        w.x = o[i][0] * inv; w.y = o[i][1] * inv;
        w.z = o[i][2] * inv; w.w = o[i][3] * inv;
        *(float4*)(O + base + (size_t)(qb * 128 + ty * 8 + i) * D_MOD + tx * 4) = w;
    }
}

// ---------------------------------------------------------------------------
extern "C" void kernel_launch(void* const* d_in, const int* in_sizes, int n_in,
                              void* d_out, int out_size)
{
    const float* query = (const float*)d_in[0];
    const float* key_  = (const float*)d_in[1];
    const float* value = (const float*)d_in[2];
    const float* Wq = (const float*)d_in[3];
    const float* bq = (const float*)d_in[4];
    const float* Wk = (const float*)d_in[5];
    const float* bk = (const float*)d_in[6];
    const float* Wv = (const float*)d_in[7];
    const float* bv = (const float*)d_in[8];
    const float* Wo = (const float*)d_in[9];
    const float* bo = (const float*)d_in[10];
    // d_in[11] = causal mask (bool) — causality implemented analytically.

    float *Qp, *Kp, *Vp, *Op;
    cudaGetSymbolAddress((void**)&Qp, g_Q);
    cudaGetSymbolAddress((void**)&Kp, g_K);
    cudaGetSymbolAddress((void**)&Vp, g_V);
    cudaGetSymbolAddress((void**)&Op, g_O);

    cudaFuncSetAttribute(flash_kernel,
                         cudaFuncAttributeMaxDynamicSharedMemorySize, 98304);
    cudaFuncSetAttribute(sgemm_tf32_kernel,
                         cudaFuncAttributeMaxDynamicSharedMemorySize, GEMM_SMEM_BYTES);

    dim3 gg(D_MOD / 128, MROWS / 128);  // (8, 64)
    sgemm_tf32_kernel<<<gg, 256, GEMM_SMEM_BYTES>>>(query, Wq, bq, Qp, MROWS, D_MOD, D_MOD);
    sgemm_tf32_kernel<<<gg, 256, GEMM_SMEM_BYTES>>>(key_,  Wk, bk, Kp, MROWS, D_MOD, D_MOD);
    sgemm_tf32_kernel<<<gg, 256, GEMM_SMEM_BYTES>>>(value, Wv, bv, Vp, MROWS, D_MOD, D_MOD);

    flash_kernel<<<dim3(S_LEN / 128, NH, B_SZ), 256, 98304>>>(Qp, Kp, Vp, Op);

    sgemm_tf32_kernel<<<gg, 256, GEMM_SMEM_BYTES>>>(Op, Wo, bo, (float*)d_out, MROWS, D_MOD, D_MOD);
}

// round 4
// speedup vs baseline: 2.6374x; 1.5906x over previous
#include <cuda_runtime.h>
#include <cuda_fp16.h>
#include <math.h>
#include <stdint.h>

#define B_SZ   4
#define S_LEN  2048
#define D_MOD  1024
#define NH     16
#define DKH    64
#define MROWS  (B_SZ * S_LEN)   // 8192

// Scratch (allocation-free rule: __device__ globals)
__device__ float g_Q[MROWS * D_MOD];
__device__ float g_K[MROWS * D_MOD];
__device__ float g_V[MROWS * D_MOD];
__device__ float g_O[MROWS * D_MOD];

__device__ __forceinline__ uint32_t f2tf32(float x) {
    uint32_t r;
    asm("cvt.rna.tf32.f32 %0, %1;" : "=r"(r) : "f"(x));
    return r;
}
__device__ __forceinline__ uint32_t packh2(float x, float y) {
    __half2 h = __floats2half2_rn(x, y);
    return *(uint32_t*)&h;
}

#define MMA_TF32(ACC, A0, A1, A2, A3, B0, B1)                                 \
    asm volatile(                                                             \
        "mma.sync.aligned.m16n8k8.row.col.f32.tf32.tf32.f32 "                 \
        "{%0,%1,%2,%3}, {%4,%5,%6,%7}, {%8,%9}, {%0,%1,%2,%3};"               \
        : "+f"((ACC)[0]), "+f"((ACC)[1]), "+f"((ACC)[2]), "+f"((ACC)[3])      \
        : "r"(A0), "r"(A1), "r"(A2), "r"(A3), "r"(B0), "r"(B1))

#define MMA_F16(ACC, A0, A1, A2, A3, B0, B1)                                  \
    asm volatile(                                                             \
        "mma.sync.aligned.m16n8k16.row.col.f32.f16.f16.f32 "                  \
        "{%0,%1,%2,%3}, {%4,%5,%6,%7}, {%8,%9}, {%0,%1,%2,%3};"               \
        : "+f"((ACC)[0]), "+f"((ACC)[1]), "+f"((ACC)[2]), "+f"((ACC)[3])      \
        : "r"(A0), "r"(A1), "r"(A2), "r"(A3), "r"(B0), "r"(B1))

// ---------------------------------------------------------------------------
// TF32 tensor-core GEMM, double-buffered: C[M,N] = A[M,K] @ W[N,K]^T + bias[N]
// (unchanged from round 3)
// ---------------------------------------------------------------------------
#define GEMM_SMEM_BYTES (4 * 128 * 36 * 4)

__global__ __launch_bounds__(256, 2) void sgemm_tf32_kernel(
    const float* __restrict__ A, const float* __restrict__ W,
    const float* __restrict__ bias, float* __restrict__ C,
    int M, int N, int K)
{
    extern __shared__ uint32_t sm_u[];
    uint32_t* const Ast0 = sm_u;
    uint32_t* const Ast1 = sm_u + 128 * 36;
    uint32_t* const Wst0 = sm_u + 2 * 128 * 36;
    uint32_t* const Wst1 = sm_u + 3 * 128 * 36;

    const int bm = blockIdx.y * 128;
    const int bn = blockIdx.x * 128;
    const int tid  = threadIdx.x;
    const int wid  = tid >> 5;
    const int lane = tid & 31;
    const int wm = (wid & 1) * 64;
    const int wn = (wid >> 1) * 32;
    const int lr  = tid >> 3;
    const int lc4 = (tid & 7) << 2;
    const int gq = lane >> 2;
    const int gr = lane & 3;

    float acc[4][4][4];
#pragma unroll
    for (int mt = 0; mt < 4; ++mt)
#pragma unroll
        for (int nt = 0; nt < 4; ++nt)
#pragma unroll
            for (int i = 0; i < 4; ++i) acc[mt][nt][i] = 0.f;

    const float* Ag = A + (size_t)(bm + lr) * K + lc4;
    const float* Wg = W + (size_t)(bn + lr) * K + lc4;

    float4 av[4], wv[4];
#pragma unroll
    for (int p = 0; p < 4; ++p) {
        av[p] = *(const float4*)(Ag + (size_t)(p * 32) * K);
        wv[p] = *(const float4*)(Wg + (size_t)(p * 32) * K);
    }
#pragma unroll
    for (int p = 0; p < 4; ++p) {
        uint32_t* as = Ast0 + (lr + p * 32) * 36 + lc4;
        uint32_t* ws = Wst0 + (lr + p * 32) * 36 + lc4;
        as[0] = f2tf32(av[p].x); as[1] = f2tf32(av[p].y);
        as[2] = f2tf32(av[p].z); as[3] = f2tf32(av[p].w);
        ws[0] = f2tf32(wv[p].x); ws[1] = f2tf32(wv[p].y);
        ws[2] = f2tf32(wv[p].z); ws[3] = f2tf32(wv[p].w);
    }
    __syncthreads();

    const int nIter = K >> 5;
    for (int it = 0; it < nIter; ++it) {
        const bool more = (it + 1 < nIter);
        if (more) {
            const int k1 = (it + 1) << 5;
#pragma unroll
            for (int p = 0; p < 4; ++p) {
                av[p] = *(const float4*)(Ag + (size_t)(p * 32) * K + k1);
                wv[p] = *(const float4*)(Wg + (size_t)(p * 32) * K + k1);
            }
        }

        const uint32_t* Acur = (it & 1) ? Ast1 : Ast0;
        const uint32_t* Wcur = (it & 1) ? Wst1 : Wst0;
#pragma unroll
        for (int c = 0; c < 4; ++c) {
            const int kk = c * 8 + gr;
            uint32_t a[4][4], b[4][2];
#pragma unroll
            for (int mt = 0; mt < 4; ++mt) {
                const int r0 = wm + mt * 16 + gq;
                a[mt][0] = Acur[r0 * 36 + kk];
                a[mt][1] = Acur[(r0 + 8) * 36 + kk];
                a[mt][2] = Acur[r0 * 36 + kk + 4];
                a[mt][3] = Acur[(r0 + 8) * 36 + kk + 4];
            }
#pragma unroll
            for (int nt = 0; nt < 4; ++nt) {
                const int n0 = wn + nt * 8 + gq;
                b[nt][0] = Wcur[n0 * 36 + kk];
                b[nt][1] = Wcur[n0 * 36 + kk + 4];
            }
#pragma unroll
            for (int mt = 0; mt < 4; ++mt)
#pragma unroll
                for (int nt = 0; nt < 4; ++nt)
                    MMA_TF32(acc[mt][nt], a[mt][0], a[mt][1], a[mt][2], a[mt][3],
                             b[nt][0], b[nt][1]);
        }

        if (more) {
            __syncthreads();
            uint32_t* Anx = ((it + 1) & 1) ? Ast1 : Ast0;
            uint32_t* Wnx = ((it + 1) & 1) ? Wst1 : Wst0;
#pragma unroll
            for (int p = 0; p < 4; ++p) {
                uint32_t* as = Anx + (lr + p * 32) * 36 + lc4;
                uint32_t* ws = Wnx + (lr + p * 32) * 36 + lc4;
                as[0] = f2tf32(av[p].x); as[1] = f2tf32(av[p].y);
                as[2] = f2tf32(av[p].z); as[3] = f2tf32(av[p].w);
                ws[0] = f2tf32(wv[p].x); ws[1] = f2tf32(wv[p].y);
                ws[2] = f2tf32(wv[p].z); ws[3] = f2tf32(wv[p].w);
            }
            __syncthreads();
        }
    }

    const int c2 = gr * 2;
#pragma unroll
    for (int mt = 0; mt < 4; ++mt) {
#pragma unroll
        for (int nt = 0; nt < 4; ++nt) {
            const int col = bn + wn + nt * 8 + c2;
            const float b0 = bias[col], b1 = bias[col + 1];
            const size_t row0 = (size_t)(bm + wm + mt * 16 + gq);
            float2 v0, v1;
            v0.x = acc[mt][nt][0] + b0; v0.y = acc[mt][nt][1] + b1;
            v1.x = acc[mt][nt][2] + b0; v1.y = acc[mt][nt][3] + b1;
            *(float2*)(C + row0 * N + col)       = v0;
            *(float2*)(C + (row0 + 8) * N + col) = v1;
        }
    }
}

// ---------------------------------------------------------------------------
// Tensor-core flash attention, causal. BM=128 q-rows, BN=64 kv, DK=64.
// 8 warps, each owns 16 q-rows (m16), full 64 kv via 8 n8 tiles.
// QK^T: 3xTF32 (near-fp32 accuracy). PV: fp16 m16n8k16, S-frag -> A-frag
// direct register pack (no smem round trip for P).
// Smem: sQ[128][68] fp32 + sK[64][68] fp32 + sVt[64][72] fp16 = 60 KB.
// ---------------------------------------------------------------------------
#define FLASH_SMEM_BYTES (128 * 68 * 4 + 64 * 68 * 4 + 64 * 72 * 2)

__global__ __launch_bounds__(256, 2) void flash_tc_kernel(
    const float* __restrict__ Q, const float* __restrict__ K,
    const float* __restrict__ V, float* __restrict__ O)
{
    extern __shared__ char smraw[];
    float*  sQ  = (float*)smraw;               // [128][68]
    float*  sK  = sQ + 128 * 68;               // [64][68]
    __half* sVt = (__half*)(sK + 64 * 68);     // [dv=64][kv stride 72]

    const int qb  = blockIdx.x;
    const int h   = blockIdx.y;
    const int b   = blockIdx.z;
    const int tid = threadIdx.x;
    const int wid = tid >> 5;
    const int lane = tid & 31;
    const int gq = lane >> 2;    // 0..7
    const int gr = lane & 3;     // 0..3
    const size_t base = (size_t)b * S_LEN * D_MOD + (size_t)h * DKH;

    // Stage Q tile: 128 rows x 64 cols fp32
#pragma unroll
    for (int t = 0; t < 8; ++t) {
        int idx = tid + t * 256;
        int r  = idx >> 4;
        int c4 = (idx & 15) << 2;
        float4 v = *(const float4*)(Q + base + (size_t)(qb * 128 + r) * D_MOD + c4);
        *(float4*)(sQ + r * 68 + c4) = v;
    }

    float o[8][4];
#pragma unroll
    for (int nt = 0; nt < 8; ++nt)
#pragma unroll
        for (int i = 0; i < 4; ++i) o[nt][i] = 0.f;
    float m0 = -1e30f, m1 = -1e30f, l0 = 0.f, l1 = 0.f;

    const int row0 = qb * 128 + wid * 16 + gq;   // global q row (first)
    const int row1 = row0 + 8;
    const float scale = 0.125f;                  // 1/sqrt(64)
    const int jmax = 2 * qb + 1;

    for (int j = 0; j <= jmax; ++j) {
        __syncthreads();   // prior-iter readers done (orders Q staging on j=0)
        // Stage K (fp32) and V (fp16, transposed [dv][kv])
#pragma unroll
        for (int t = 0; t < 4; ++t) {
            int idx = tid + t * 256;
            int r  = idx >> 4;                   // kv row 0..63
            int c4 = (idx & 15) << 2;            // d col
            float4 kv = *(const float4*)(K + base + (size_t)(j * 64 + r) * D_MOD + c4);
            *(float4*)(sK + r * 68 + c4) = kv;
            float4 vv = *(const float4*)(V + base + (size_t)(j * 64 + r) * D_MOD + c4);
            sVt[(c4 + 0) * 72 + r] = __float2half(vv.x);
            sVt[(c4 + 1) * 72 + r] = __float2half(vv.y);
            sVt[(c4 + 2) * 72 + r] = __float2half(vv.z);
            sVt[(c4 + 3) * 72 + r] = __float2half(vv.w);
        }
        __syncthreads();

        // ---- S = Q K^T via 3xTF32 ----
        float s[8][4];
#pragma unroll
        for (int nt = 0; nt < 8; ++nt)
#pragma unroll
            for (int i = 0; i < 4; ++i) s[nt][i] = 0.f;

#pragma unroll
        for (int c = 0; c < 8; ++c) {
            const float* qp = sQ + (wid * 16 + gq) * 68 + c * 8 + gr;
            float af[4];
            af[0] = qp[0];
            af[1] = qp[8 * 68];
            af[2] = qp[4];
            af[3] = qp[8 * 68 + 4];
            uint32_t ah[4], al[4];
#pragma unroll
            for (int i = 0; i < 4; ++i) {
                ah[i] = f2tf32(af[i]);
                al[i] = f2tf32(af[i] - __uint_as_float(ah[i]));
            }
#pragma unroll
            for (int nt = 0; nt < 8; ++nt) {
                const float* kp = sK + (nt * 8 + gq) * 68 + c * 8 + gr;
                float b0f = kp[0], b1f = kp[4];
                uint32_t bh0 = f2tf32(b0f), bh1 = f2tf32(b1f);
                uint32_t bl0 = f2tf32(b0f - __uint_as_float(bh0));
                uint32_t bl1 = f2tf32(b1f - __uint_as_float(bh1));
                MMA_TF32(s[nt], ah[0], ah[1], ah[2], ah[3], bh0, bh1);
                MMA_TF32(s[nt], al[0], al[1], al[2], al[3], bh0, bh1);
                MMA_TF32(s[nt], ah[0], ah[1], ah[2], ah[3], bl0, bl1);
            }
        }

        // ---- scale + causal mask ----
        const bool diag = (j >= 2 * qb);
#pragma unroll
        for (int nt = 0; nt < 8; ++nt) {
            const int colb = j * 64 + nt * 8 + 2 * gr;
#pragma unroll
            for (int e = 0; e < 4; ++e) {
                s[nt][e] *= scale;
                if (diag) {
                    const int col = colb + (e & 1);
                    const int row = (e < 2) ? row0 : row1;
                    if (col > row) s[nt][e] = -1e30f;
                }
            }
        }

        // ---- online softmax (rows gq and gq+8; quad = 4 lanes share a row) ----
        float mt0 = -1e30f, mt1 = -1e30f;
#pragma unroll
        for (int nt = 0; nt < 8; ++nt) {
            mt0 = fmaxf(mt0, fmaxf(s[nt][0], s[nt][1]));
            mt1 = fmaxf(mt1, fmaxf(s[nt][2], s[nt][3]));
        }
        mt0 = fmaxf(mt0, __shfl_xor_sync(0xffffffffu, mt0, 1));
        mt0 = fmaxf(mt0, __shfl_xor_sync(0xffffffffu, mt0, 2));
        mt1 = fmaxf(mt1, __shfl_xor_sync(0xffffffffu, mt1, 1));
        mt1 = fmaxf(mt1, __shfl_xor_sync(0xffffffffu, mt1, 2));
        const float mn0 = fmaxf(m0, mt0);
        const float mn1 = fmaxf(m1, mt1);
        const float alpha0 = __expf(m0 - mn0);
        const float alpha1 = __expf(m1 - mn1);
        m0 = mn0; m1 = mn1;

        float rs0 = 0.f, rs1 = 0.f;
#pragma unroll
        for (int nt = 0; nt < 8; ++nt) {
            s[nt][0] = __expf(s[nt][0] - m0);
            s[nt][1] = __expf(s[nt][1] - m0);
            s[nt][2] = __expf(s[nt][2] - m1);
            s[nt][3] = __expf(s[nt][3] - m1);
            rs0 += s[nt][0] + s[nt][1];
            rs1 += s[nt][2] + s[nt][3];
        }
        rs0 += __shfl_xor_sync(0xffffffffu, rs0, 1);
        rs0 += __shfl_xor_sync(0xffffffffu, rs0, 2);
        rs1 += __shfl_xor_sync(0xffffffffu, rs1, 1);
        rs1 += __shfl_xor_sync(0xffffffffu, rs1, 2);
        l0 = l0 * alpha0 + rs0;
        l1 = l1 * alpha1 + rs1;
#pragma unroll
        for (int nt = 0; nt < 8; ++nt) {
            o[nt][0] *= alpha0; o[nt][1] *= alpha0;
            o[nt][2] *= alpha1; o[nt][3] *= alpha1;
        }

        // ---- O += P V : fp16 m16n8k16, P from registers ----
#pragma unroll
        for (int c = 0; c < 4; ++c) {
            uint32_t pa0 = packh2(s[2 * c][0],     s[2 * c][1]);
            uint32_t pa1 = packh2(s[2 * c][2],     s[2 * c][3]);
            uint32_t pa2 = packh2(s[2 * c + 1][0], s[2 * c + 1][1]);
            uint32_t pa3 = packh2(s[2 * c + 1][2], s[2 * c + 1][3]);
#pragma unroll
            for (int nt = 0; nt < 8; ++nt) {
                const __half* vp = sVt + (nt * 8 + gq) * 72 + c * 16 + 2 * gr;
                uint32_t vb0 = *(const uint32_t*)vp;
                uint32_t vb1 = *(const uint32_t*)(vp + 8);
                MMA_F16(o[nt], pa0, pa1, pa2, pa3, vb0, vb1);
            }
        }
    }

    // ---- epilogue ----
    const float inv0 = 1.0f / l0;
    const float inv1 = 1.0f / l1;
#pragma unroll
    for (int nt = 0; nt < 8; ++nt) {
        const int dv = nt * 8 + 2 * gr;
        float2 w0, w1;
        w0.x = o[nt][0] * inv0; w0.y = o[nt][1] * inv0;
        w1.x = o[nt][2] * inv1; w1.y = o[nt][3] * inv1;
        *(float2*)(O + base + (size_t)row0 * D_MOD + dv) = w0;
        *(float2*)(O + base + (size_t)row1 * D_MOD + dv) = w1;
    }
}

// ---------------------------------------------------------------------------
extern "C" void kernel_launch(void* const* d_in, const int* in_sizes, int n_in,
                              void* d_out, int out_size)
{
    const float* query = (const float*)d_in[0];
    const float* key_  = (const float*)d_in[1];
    const float* value = (const float*)d_in[2];
    const float* Wq = (const float*)d_in[3];
    const float* bq = (const float*)d_in[4];
    const float* Wk = (const float*)d_in[5];
    const float* bk = (const float*)d_in[6];
    const float* Wv = (const float*)d_in[7];
    const float* bv = (const float*)d_in[8];
    const float* Wo = (const float*)d_in[9];
    const float* bo = (const float*)d_in[10];
    // d_in[11] = causal mask (bool) — causality implemented analytically.

    float *Qp, *Kp, *Vp, *Op;
    cudaGetSymbolAddress((void**)&Qp, g_Q);
    cudaGetSymbolAddress((void**)&Kp, g_K);
    cudaGetSymbolAddress((void**)&Vp, g_V);
    cudaGetSymbolAddress((void**)&Op, g_O);

    cudaFuncSetAttribute(sgemm_tf32_kernel,
                         cudaFuncAttributeMaxDynamicSharedMemorySize, GEMM_SMEM_BYTES);
    cudaFuncSetAttribute(flash_tc_kernel,
                         cudaFuncAttributeMaxDynamicSharedMemorySize, FLASH_SMEM_BYTES);

    dim3 gg(D_MOD / 128, MROWS / 128);  // (8, 64)
    sgemm_tf32_kernel<<<gg, 256, GEMM_SMEM_BYTES>>>(query, Wq, bq, Qp, MROWS, D_MOD, D_MOD);
    sgemm_tf32_kernel<<<gg, 256, GEMM_SMEM_BYTES>>>(key_,  Wk, bk, Kp, MROWS, D_MOD, D_MOD);
    sgemm_tf32_kernel<<<gg, 256, GEMM_SMEM_BYTES>>>(value, Wv, bv, Vp, MROWS, D_MOD, D_MOD);

    flash_tc_kernel<<<dim3(S_LEN / 128, NH, B_SZ), 256, FLASH_SMEM_BYTES>>>(Qp, Kp, Vp, Op);

    sgemm_tf32_kernel<<<gg, 256, GEMM_SMEM_BYTES>>>(Op, Wo, bo, (float*)d_out, MROWS, D_MOD, D_MOD);
}

// round 7
// speedup vs baseline: 3.2283x; 1.2240x over previous
#include <cuda_runtime.h>
#include <cuda_fp16.h>
#include <math.h>
#include <stdint.h>

#define B_SZ   4
#define S_LEN  2048
#define D_MOD  1024
#define NH     16
#define DKH    64
#define MROWS  (B_SZ * S_LEN)   // 8192

// Scratch (allocation-free rule: __device__ globals)
__device__ float g_Q[MROWS * D_MOD];
__device__ float g_K[MROWS * D_MOD];
__device__ float g_V[MROWS * D_MOD];
__device__ float g_O[MROWS * D_MOD];

__device__ __forceinline__ uint32_t f2tf32(float x) {
    uint32_t r;
    asm("cvt.rna.tf32.f32 %0, %1;" : "=r"(r) : "f"(x));
    return r;
}
__device__ __forceinline__ uint32_t packh2(float x, float y) {
    __half2 h = __floats2half2_rn(x, y);
    return *(uint32_t*)&h;
}

#define MMA_TF32(ACC, A0, A1, A2, A3, B0, B1)                                 \
    asm volatile(                                                             \
        "mma.sync.aligned.m16n8k8.row.col.f32.tf32.tf32.f32 "                 \
        "{%0,%1,%2,%3}, {%4,%5,%6,%7}, {%8,%9}, {%0,%1,%2,%3};"               \
        : "+f"((ACC)[0]), "+f"((ACC)[1]), "+f"((ACC)[2]), "+f"((ACC)[3])      \
        : "r"(A0), "r"(A1), "r"(A2), "r"(A3), "r"(B0), "r"(B1))

#define MMA_F16(ACC, A0, A1, A2, A3, B0, B1)                                  \
    asm volatile(                                                             \
        "mma.sync.aligned.m16n8k16.row.col.f32.f16.f16.f32 "                  \
        "{%0,%1,%2,%3}, {%4,%5,%6,%7}, {%8,%9}, {%0,%1,%2,%3};"               \
        : "+f"((ACC)[0]), "+f"((ACC)[1]), "+f"((ACC)[2]), "+f"((ACC)[3])      \
        : "r"(A0), "r"(A1), "r"(A2), "r"(A3), "r"(B0), "r"(B1))

// ---------------------------------------------------------------------------
// TF32 tensor-core GEMM, double-buffered (unchanged): C = A @ W^T + bias
// ---------------------------------------------------------------------------
#define GEMM_SMEM_BYTES (4 * 128 * 36 * 4)

__global__ __launch_bounds__(256, 2) void sgemm_tf32_kernel(
    const float* __restrict__ A, const float* __restrict__ W,
    const float* __restrict__ bias, float* __restrict__ C,
    int M, int N, int K)
{
    extern __shared__ uint32_t sm_u[];
    uint32_t* const Ast0 = sm_u;
    uint32_t* const Ast1 = sm_u + 128 * 36;
    uint32_t* const Wst0 = sm_u + 2 * 128 * 36;
    uint32_t* const Wst1 = sm_u + 3 * 128 * 36;

    const int bm = blockIdx.y * 128;
    const int bn = blockIdx.x * 128;
    const int tid  = threadIdx.x;
    const int wid  = tid >> 5;
    const int lane = tid & 31;
    const int wm = (wid & 1) * 64;
    const int wn = (wid >> 1) * 32;
    const int lr  = tid >> 3;
    const int lc4 = (tid & 7) << 2;
    const int gq = lane >> 2;
    const int gr = lane & 3;

    float acc[4][4][4];
#pragma unroll
    for (int mt = 0; mt < 4; ++mt)
#pragma unroll
        for (int nt = 0; nt < 4; ++nt)
#pragma unroll
            for (int i = 0; i < 4; ++i) acc[mt][nt][i] = 0.f;

    const float* Ag = A + (size_t)(bm + lr) * K + lc4;
    const float* Wg = W + (size_t)(bn + lr) * K + lc4;

    float4 av[4], wv[4];
#pragma unroll
    for (int p = 0; p < 4; ++p) {
        av[p] = *(const float4*)(Ag + (size_t)(p * 32) * K);
        wv[p] = *(const float4*)(Wg + (size_t)(p * 32) * K);
    }
#pragma unroll
    for (int p = 0; p < 4; ++p) {
        uint32_t* as = Ast0 + (lr + p * 32) * 36 + lc4;
        uint32_t* ws = Wst0 + (lr + p * 32) * 36 + lc4;
        as[0] = f2tf32(av[p].x); as[1] = f2tf32(av[p].y);
        as[2] = f2tf32(av[p].z); as[3] = f2tf32(av[p].w);
        ws[0] = f2tf32(wv[p].x); ws[1] = f2tf32(wv[p].y);
        ws[2] = f2tf32(wv[p].z); ws[3] = f2tf32(wv[p].w);
    }
    __syncthreads();

    const int nIter = K >> 5;
    for (int it = 0; it < nIter; ++it) {
        const bool more = (it + 1 < nIter);
        if (more) {
            const int k1 = (it + 1) << 5;
#pragma unroll
            for (int p = 0; p < 4; ++p) {
                av[p] = *(const float4*)(Ag + (size_t)(p * 32) * K + k1);
                wv[p] = *(const float4*)(Wg + (size_t)(p * 32) * K + k1);
            }
        }

        const uint32_t* Acur = (it & 1) ? Ast1 : Ast0;
        const uint32_t* Wcur = (it & 1) ? Wst1 : Wst0;
#pragma unroll
        for (int c = 0; c < 4; ++c) {
            const int kk = c * 8 + gr;
            uint32_t a[4][4], b[4][2];
#pragma unroll
            for (int mt = 0; mt < 4; ++mt) {
                const int r0 = wm + mt * 16 + gq;
                a[mt][0] = Acur[r0 * 36 + kk];
                a[mt][1] = Acur[(r0 + 8) * 36 + kk];
                a[mt][2] = Acur[r0 * 36 + kk + 4];
                a[mt][3] = Acur[(r0 + 8) * 36 + kk + 4];
            }
#pragma unroll
            for (int nt = 0; nt < 4; ++nt) {
                const int n0 = wn + nt * 8 + gq;
                b[nt][0] = Wcur[n0 * 36 + kk];
                b[nt][1] = Wcur[n0 * 36 + kk + 4];
            }
#pragma unroll
            for (int mt = 0; mt < 4; ++mt)
#pragma unroll
                for (int nt = 0; nt < 4; ++nt)
                    MMA_TF32(acc[mt][nt], a[mt][0], a[mt][1], a[mt][2], a[mt][3],
                             b[nt][0], b[nt][1]);
        }

        if (more) {
            __syncthreads();
            uint32_t* Anx = ((it + 1) & 1) ? Ast1 : Ast0;
            uint32_t* Wnx = ((it + 1) & 1) ? Wst1 : Wst0;
#pragma unroll
            for (int p = 0; p < 4; ++p) {
                uint32_t* as = Anx + (lr + p * 32) * 36 + lc4;
                uint32_t* ws = Wnx + (lr + p * 32) * 36 + lc4;
                as[0] = f2tf32(av[p].x); as[1] = f2tf32(av[p].y);
                as[2] = f2tf32(av[p].z); as[3] = f2tf32(av[p].w);
                ws[0] = f2tf32(wv[p].x); ws[1] = f2tf32(wv[p].y);
                ws[2] = f2tf32(wv[p].z); ws[3] = f2tf32(wv[p].w);
            }
            __syncthreads();
        }
    }

    const int c2 = gr * 2;
#pragma unroll
    for (int mt = 0; mt < 4; ++mt) {
#pragma unroll
        for (int nt = 0; nt < 4; ++nt) {
            const int col = bn + wn + nt * 8 + c2;
            const float b0 = bias[col], b1 = bias[col + 1];
            const size_t row0 = (size_t)(bm + wm + mt * 16 + gq);
            float2 v0, v1;
            v0.x = acc[mt][nt][0] + b0; v0.y = acc[mt][nt][1] + b1;
            v1.x = acc[mt][nt][2] + b0; v1.y = acc[mt][nt][3] + b1;
            *(float2*)(C + row0 * N + col)       = v0;
            *(float2*)(C + (row0 + 8) * N + col) = v1;
        }
    }
}

// ---------------------------------------------------------------------------
// Tensor-core flash attention v3 (round-4 layouts + hoisted conversions).
// BM=128, BN=64, DK=64, 8 warps x m16.
// Q pre-split into tf32 hi/lo planes ONCE per CTA (row-major stride 68,
// identical indexing to round 4's sQ). K pre-converted to tf32 hi ONCE per
// tile (stride 68). Inner loop = pure LDS + MMA: (Qh+Ql).Kh, 2 tf32 MMA per
// (c,nt). PV: fp16 m16n8k16, V layout byte-identical to round 4 ([dv][72]).
// Smem: sQh[128][68]f32 + sQl[128][68]f32 + sKh[64][68]f32 + sVt[64][72]f16
//     = 34816 + 34816 + 17408 + 9216 = 96256 B.
// ---------------------------------------------------------------------------
#define FLASH_SMEM_BYTES (96256)

__global__ __launch_bounds__(256, 2) void flash_tc_kernel(
    const float* __restrict__ Q, const float* __restrict__ K,
    const float* __restrict__ V, float* __restrict__ O)
{
    extern __shared__ char smraw[];
    float*  sQh = (float*)smraw;               // [128][68] tf32 bits
    float*  sQl = sQh + 128 * 68;              // [128][68] tf32 bits (residual)
    float*  sKh = sQl + 128 * 68;              // [64][68]  tf32 bits
    __half* sVt = (__half*)(sKh + 64 * 68);    // [dv=64][kv stride 72]

    const int qb  = blockIdx.x;
    const int h   = blockIdx.y;
    const int b   = blockIdx.z;
    const int tid = threadIdx.x;
    const int wid = tid >> 5;
    const int lane = tid & 31;
    const int gq = lane >> 2;    // 0..7
    const int gr = lane & 3;     // 0..3
    const size_t base = (size_t)b * S_LEN * D_MOD + (size_t)h * DKH;

    // ---- Stage Q once: hi/lo tf32 planes, round-4 row-major layout ----
#pragma unroll
    for (int t = 0; t < 8; ++t) {
        int idx = tid + t * 256;
        int r  = idx >> 4;
        int c4 = (idx & 15) << 2;
        float4 v = *(const float4*)(Q + base + (size_t)(qb * 128 + r) * D_MOD + c4);
        float hx = __uint_as_float(f2tf32(v.x));
        float hy = __uint_as_float(f2tf32(v.y));
        float hz = __uint_as_float(f2tf32(v.z));
        float hw = __uint_as_float(f2tf32(v.w));
        float* dh = sQh + r * 68 + c4;
        float* dl = sQl + r * 68 + c4;
        dh[0] = hx; dh[1] = hy; dh[2] = hz; dh[3] = hw;
        dl[0] = __uint_as_float(f2tf32(v.x - hx));
        dl[1] = __uint_as_float(f2tf32(v.y - hy));
        dl[2] = __uint_as_float(f2tf32(v.z - hz));
        dl[3] = __uint_as_float(f2tf32(v.w - hw));
    }

    float o[8][4];
#pragma unroll
    for (int nt = 0; nt < 8; ++nt)
#pragma unroll
        for (int i = 0; i < 4; ++i) o[nt][i] = 0.f;
    float m0 = -1e30f, m1 = -1e30f, l0 = 0.f, l1 = 0.f;

    const int row0 = qb * 128 + wid * 16 + gq;
    const int row1 = row0 + 8;
    const float scale = 0.125f;                // 1/sqrt(64)
    const int jmax = 2 * qb + 1;

    for (int j = 0; j <= jmax; ++j) {
        __syncthreads();   // prior-iter readers done (orders Q staging on j=0)
        // ---- Stage K (tf32 hi, row-major) and V (fp16 transposed, round 4) ----
#pragma unroll
        for (int t = 0; t < 4; ++t) {
            int idx = tid + t * 256;
            int r  = idx >> 4;                 // kv row 0..63
            int c4 = (idx & 15) << 2;          // d col
            float4 kv = *(const float4*)(K + base + (size_t)(j * 64 + r) * D_MOD + c4);
            float* dk = sKh + r * 68 + c4;
            dk[0] = __uint_as_float(f2tf32(kv.x));
            dk[1] = __uint_as_float(f2tf32(kv.y));
            dk[2] = __uint_as_float(f2tf32(kv.z));
            dk[3] = __uint_as_float(f2tf32(kv.w));
            float4 vv = *(const float4*)(V + base + (size_t)(j * 64 + r) * D_MOD + c4);
            sVt[(c4 + 0) * 72 + r] = __float2half(vv.x);
            sVt[(c4 + 1) * 72 + r] = __float2half(vv.y);
            sVt[(c4 + 2) * 72 + r] = __float2half(vv.z);
            sVt[(c4 + 3) * 72 + r] = __float2half(vv.w);
        }
        __syncthreads();

        // ---- S = Q K^T : (Qh + Ql) . Kh, pure LDS + MMA ----
        float s[8][4];
#pragma unroll
        for (int nt = 0; nt < 8; ++nt)
#pragma unroll
            for (int i = 0; i < 4; ++i) s[nt][i] = 0.f;

        const int qrow = wid * 16 + gq;
#pragma unroll
        for (int c = 0; c < 8; ++c) {
            const int fo = c * 8 + gr;
            const uint32_t* qh = (const uint32_t*)sQh + qrow * 68 + fo;
            const uint32_t* ql = (const uint32_t*)sQl + qrow * 68 + fo;
            uint32_t ah0 = qh[0], ah1 = qh[8 * 68], ah2 = qh[4], ah3 = qh[8 * 68 + 4];
            uint32_t al0 = ql[0], al1 = ql[8 * 68], al2 = ql[4], al3 = ql[8 * 68 + 4];
#pragma unroll
            for (int nt = 0; nt < 8; ++nt) {
                const uint32_t* kp = (const uint32_t*)sKh + (nt * 8 + gq) * 68 + fo;
                uint32_t bh0 = kp[0], bh1 = kp[4];
                MMA_TF32(s[nt], ah0, ah1, ah2, ah3, bh0, bh1);
                MMA_TF32(s[nt], al0, al1, al2, al3, bh0, bh1);
            }
        }

        // ---- scale + causal mask ----
        const bool diag = (j >= 2 * qb);
#pragma unroll
        for (int nt = 0; nt < 8; ++nt) {
            const int colb = j * 64 + nt * 8 + 2 * gr;
#pragma unroll
            for (int e = 0; e < 4; ++e) {
                s[nt][e] *= scale;
                if (diag) {
                    const int col = colb + (e & 1);
                    const int row = (e < 2) ? row0 : row1;
                    if (col > row) s[nt][e] = -1e30f;
                }
            }
        }

        // ---- online softmax ----
        float mt0 = -1e30f, mt1 = -1e30f;
#pragma unroll
        for (int nt = 0; nt < 8; ++nt) {
            mt0 = fmaxf(mt0, fmaxf(s[nt][0], s[nt][1]));
            mt1 = fmaxf(mt1, fmaxf(s[nt][2], s[nt][3]));
        }
        mt0 = fmaxf(mt0, __shfl_xor_sync(0xffffffffu, mt0, 1));
        mt0 = fmaxf(mt0, __shfl_xor_sync(0xffffffffu, mt0, 2));
        mt1 = fmaxf(mt1, __shfl_xor_sync(0xffffffffu, mt1, 1));
        mt1 = fmaxf(mt1, __shfl_xor_sync(0xffffffffu, mt1, 2));
        const float mn0 = fmaxf(m0, mt0);
        const float mn1 = fmaxf(m1, mt1);
        const float alpha0 = __expf(m0 - mn0);
        const float alpha1 = __expf(m1 - mn1);
        m0 = mn0; m1 = mn1;

        float rs0 = 0.f, rs1 = 0.f;
#pragma unroll
        for (int nt = 0; nt < 8; ++nt) {
            s[nt][0] = __expf(s[nt][0] - m0);
            s[nt][1] = __expf(s[nt][1] - m0);
            s[nt][2] = __expf(s[nt][2] - m1);
            s[nt][3] = __expf(s[nt][3] - m1);
            rs0 += s[nt][0] + s[nt][1];
            rs1 += s[nt][2] + s[nt][3];
        }
        rs0 += __shfl_xor_sync(0xffffffffu, rs0, 1);
        rs0 += __shfl_xor_sync(0xffffffffu, rs0, 2);
        rs1 += __shfl_xor_sync(0xffffffffu, rs1, 1);
        rs1 += __shfl_xor_sync(0xffffffffu, rs1, 2);
        l0 = l0 * alpha0 + rs0;
        l1 = l1 * alpha1 + rs1;
#pragma unroll
        for (int nt = 0; nt < 8; ++nt) {
            o[nt][0] *= alpha0; o[nt][1] *= alpha0;
            o[nt][2] *= alpha1; o[nt][3] *= alpha1;
        }

        // ---- O += P V : fp16 m16n8k16, P from registers (round-4 V layout) ----
#pragma unroll
        for (int c = 0; c < 4; ++c) {
            uint32_t pa0 = packh2(s[2 * c][0],     s[2 * c][1]);
            uint32_t pa1 = packh2(s[2 * c][2],     s[2 * c][3]);
            uint32_t pa2 = packh2(s[2 * c + 1][0], s[2 * c + 1][1]);
            uint32_t pa3 = packh2(s[2 * c + 1][2], s[2 * c + 1][3]);
#pragma unroll
            for (int nt = 0; nt < 8; ++nt) {
                const __half* vp = sVt + (nt * 8 + gq) * 72 + c * 16 + 2 * gr;
                uint32_t vb0 = *(const uint32_t*)vp;
                uint32_t vb1 = *(const uint32_t*)(vp + 8);
                MMA_F16(o[nt], pa0, pa1, pa2, pa3, vb0, vb1);
            }
        }
    }

    // ---- epilogue ----
    const float inv0 = 1.0f / l0;
    const float inv1 = 1.0f / l1;
#pragma unroll
    for (int nt = 0; nt < 8; ++nt) {
        const int dv = nt * 8 + 2 * gr;
        float2 w0, w1;
        w0.x = o[nt][0] * inv0; w0.y = o[nt][1] * inv0;
        w1.x = o[nt][2] * inv1; w1.y = o[nt][3] * inv1;
        *(float2*)(O + base + (size_t)row0 * D_MOD + dv) = w0;
        *(float2*)(O + base + (size_t)row1 * D_MOD + dv) = w1;
    }
}

// ---------------------------------------------------------------------------
extern "C" void kernel_launch(void* const* d_in, const int* in_sizes, int n_in,
                              void* d_out, int out_size)
{
    const float* query = (const float*)d_in[0];
    const float* key_  = (const float*)d_in[1];
    const float* value = (const float*)d_in[2];
    const float* Wq = (const float*)d_in[3];
    const float* bq = (const float*)d_in[4];
    const float* Wk = (const float*)d_in[5];
    const float* bk = (const float*)d_in[6];
    const float* Wv = (const float*)d_in[7];
    const float* bv = (const float*)d_in[8];
    const float* Wo = (const float*)d_in[9];
    const float* bo = (const float*)d_in[10];
    // d_in[11] = causal mask (bool) — causality implemented analytically.

    float *Qp, *Kp, *Vp, *Op;
    cudaGetSymbolAddress((void**)&Qp, g_Q);
    cudaGetSymbolAddress((void**)&Kp, g_K);
    cudaGetSymbolAddress((void**)&Vp, g_V);
    cudaGetSymbolAddress((void**)&Op, g_O);

    cudaFuncSetAttribute(sgemm_tf32_kernel,
                         cudaFuncAttributeMaxDynamicSharedMemorySize, GEMM_SMEM_BYTES);
    cudaFuncSetAttribute(flash_tc_kernel,
                         cudaFuncAttributeMaxDynamicSharedMemorySize, FLASH_SMEM_BYTES);

    dim3 gg(D_MOD / 128, MROWS / 128);  // (8, 64)
    sgemm_tf32_kernel<<<gg, 256, GEMM_SMEM_BYTES>>>(query, Wq, bq, Qp, MROWS, D_MOD, D_MOD);
    sgemm_tf32_kernel<<<gg, 256, GEMM_SMEM_BYTES>>>(key_,  Wk, bk, Kp, MROWS, D_MOD, D_MOD);
    sgemm_tf32_kernel<<<gg, 256, GEMM_SMEM_BYTES>>>(value, Wv, bv, Vp, MROWS, D_MOD, D_MOD);

    flash_tc_kernel<<<dim3(S_LEN / 128, NH, B_SZ), 256, FLASH_SMEM_BYTES>>>(Qp, Kp, Vp, Op);

    sgemm_tf32_kernel<<<gg, 256, GEMM_SMEM_BYTES>>>(Op, Wo, bo, (float*)d_out, MROWS, D_MOD, D_MOD);
}

// round 8
// speedup vs baseline: 3.6335x; 1.1255x over previous
#include <cuda_runtime.h>
#include <cuda_fp16.h>
#include <math.h>
#include <stdint.h>

#define B_SZ   4
#define S_LEN  2048
#define D_MOD  1024
#define NH     16
#define DKH    64
#define MROWS  (B_SZ * S_LEN)   // 8192

// Scratch (allocation-free rule: __device__ globals)
__device__ float g_Q[MROWS * D_MOD];
__device__ float g_K[MROWS * D_MOD];
__device__ float g_V[MROWS * D_MOD];
__device__ float g_O[MROWS * D_MOD];

__device__ __forceinline__ uint32_t f2tf32(float x) {
    uint32_t r;
    asm("cvt.rna.tf32.f32 %0, %1;" : "=r"(r) : "f"(x));
    return r;
}
__device__ __forceinline__ uint32_t packh2(float x, float y) {
    __half2 h = __floats2half2_rn(x, y);
    return *(uint32_t*)&h;
}

#define MMA_TF32(ACC, A0, A1, A2, A3, B0, B1)                                 \
    asm volatile(                                                             \
        "mma.sync.aligned.m16n8k8.row.col.f32.tf32.tf32.f32 "                 \
        "{%0,%1,%2,%3}, {%4,%5,%6,%7}, {%8,%9}, {%0,%1,%2,%3};"               \
        : "+f"((ACC)[0]), "+f"((ACC)[1]), "+f"((ACC)[2]), "+f"((ACC)[3])      \
        : "r"(A0), "r"(A1), "r"(A2), "r"(A3), "r"(B0), "r"(B1))

#define MMA_F16(ACC, A0, A1, A2, A3, B0, B1)                                  \
    asm volatile(                                                             \
        "mma.sync.aligned.m16n8k16.row.col.f32.f16.f16.f32 "                  \
        "{%0,%1,%2,%3}, {%4,%5,%6,%7}, {%8,%9}, {%0,%1,%2,%3};"               \
        : "+f"((ACC)[0]), "+f"((ACC)[1]), "+f"((ACC)[2]), "+f"((ACC)[3])      \
        : "r"(A0), "r"(A1), "r"(A2), "r"(A3), "r"(B0), "r"(B1))

// ---------------------------------------------------------------------------
// TF32 tensor-core GEMM body, double-buffered: C = A @ W^T + bias
// M=8192, N=K=1024 hardcoded. 128x128 tile, BK=32, 256 threads.
// ---------------------------------------------------------------------------
#define GEMM_SMEM_BYTES (4 * 128 * 36 * 4)

__device__ __forceinline__ void sgemm_body(
    const float* __restrict__ A, const float* __restrict__ W,
    const float* __restrict__ bias, float* __restrict__ C)
{
    const int M = MROWS, N = D_MOD, K = D_MOD;
    extern __shared__ uint32_t sm_u[];
    uint32_t* const Ast0 = sm_u;
    uint32_t* const Ast1 = sm_u + 128 * 36;
    uint32_t* const Wst0 = sm_u + 2 * 128 * 36;
    uint32_t* const Wst1 = sm_u + 3 * 128 * 36;

    const int bm = blockIdx.y * 128;
    const int bn = blockIdx.x * 128;
    const int tid  = threadIdx.x;
    const int wid  = tid >> 5;
    const int lane = tid & 31;
    const int wm = (wid & 1) * 64;
    const int wn = (wid >> 1) * 32;
    const int lr  = tid >> 3;
    const int lc4 = (tid & 7) << 2;
    const int gq = lane >> 2;
    const int gr = lane & 3;

    float acc[4][4][4];
#pragma unroll
    for (int mt = 0; mt < 4; ++mt)
#pragma unroll
        for (int nt = 0; nt < 4; ++nt)
#pragma unroll
            for (int i = 0; i < 4; ++i) acc[mt][nt][i] = 0.f;

    const float* Ag = A + (size_t)(bm + lr) * K + lc4;
    const float* Wg = W + (size_t)(bn + lr) * K + lc4;

    float4 av[4], wv[4];
#pragma unroll
    for (int p = 0; p < 4; ++p) {
        av[p] = *(const float4*)(Ag + (size_t)(p * 32) * K);
        wv[p] = *(const float4*)(Wg + (size_t)(p * 32) * K);
    }
#pragma unroll
    for (int p = 0; p < 4; ++p) {
        uint32_t* as = Ast0 + (lr + p * 32) * 36 + lc4;
        uint32_t* ws = Wst0 + (lr + p * 32) * 36 + lc4;
        as[0] = f2tf32(av[p].x); as[1] = f2tf32(av[p].y);
        as[2] = f2tf32(av[p].z); as[3] = f2tf32(av[p].w);
        ws[0] = f2tf32(wv[p].x); ws[1] = f2tf32(wv[p].y);
        ws[2] = f2tf32(wv[p].z); ws[3] = f2tf32(wv[p].w);
    }
    __syncthreads();

    const int nIter = K >> 5;
    for (int it = 0; it < nIter; ++it) {
        const bool more = (it + 1 < nIter);
        if (more) {
            const int k1 = (it + 1) << 5;
#pragma unroll
            for (int p = 0; p < 4; ++p) {
                av[p] = *(const float4*)(Ag + (size_t)(p * 32) * K + k1);
                wv[p] = *(const float4*)(Wg + (size_t)(p * 32) * K + k1);
            }
        }

        const uint32_t* Acur = (it & 1) ? Ast1 : Ast0;
        const uint32_t* Wcur = (it & 1) ? Wst1 : Wst0;
#pragma unroll
        for (int c = 0; c < 4; ++c) {
            const int kk = c * 8 + gr;
            uint32_t a[4][4], b[4][2];
#pragma unroll
            for (int mt = 0; mt < 4; ++mt) {
                const int r0 = wm + mt * 16 + gq;
                a[mt][0] = Acur[r0 * 36 + kk];
                a[mt][1] = Acur[(r0 + 8) * 36 + kk];
                a[mt][2] = Acur[r0 * 36 + kk + 4];
                a[mt][3] = Acur[(r0 + 8) * 36 + kk + 4];
            }
#pragma unroll
            for (int nt = 0; nt < 4; ++nt) {
                const int n0 = wn + nt * 8 + gq;
                b[nt][0] = Wcur[n0 * 36 + kk];
                b[nt][1] = Wcur[n0 * 36 + kk + 4];
            }
#pragma unroll
            for (int mt = 0; mt < 4; ++mt)
#pragma unroll
                for (int nt = 0; nt < 4; ++nt)
                    MMA_TF32(acc[mt][nt], a[mt][0], a[mt][1], a[mt][2], a[mt][3],
                             b[nt][0], b[nt][1]);
        }

        if (more) {
            __syncthreads();
            uint32_t* Anx = ((it + 1) & 1) ? Ast1 : Ast0;
            uint32_t* Wnx = ((it + 1) & 1) ? Wst1 : Wst0;
#pragma unroll
            for (int p = 0; p < 4; ++p) {
                uint32_t* as = Anx + (lr + p * 32) * 36 + lc4;
                uint32_t* ws = Wnx + (lr + p * 32) * 36 + lc4;
                as[0] = f2tf32(av[p].x); as[1] = f2tf32(av[p].y);
                as[2] = f2tf32(av[p].z); as[3] = f2tf32(av[p].w);
                ws[0] = f2tf32(wv[p].x); ws[1] = f2tf32(wv[p].y);
                ws[2] = f2tf32(wv[p].z); ws[3] = f2tf32(wv[p].w);
            }
            __syncthreads();
        }
    }

    const int c2 = gr * 2;
#pragma unroll
    for (int mt = 0; mt < 4; ++mt) {
#pragma unroll
        for (int nt = 0; nt < 4; ++nt) {
            const int col = bn + wn + nt * 8 + c2;
            const float b0 = bias[col], b1 = bias[col + 1];
            const size_t row0 = (size_t)(bm + wm + mt * 16 + gq);
            float2 v0, v1;
            v0.x = acc[mt][nt][0] + b0; v0.y = acc[mt][nt][1] + b1;
            v1.x = acc[mt][nt][2] + b0; v1.y = acc[mt][nt][3] + b1;
            *(float2*)(C + row0 * N + col)       = v0;
            *(float2*)(C + (row0 + 8) * N + col) = v1;
        }
    }
}

// Fused Q/K/V projection: gridDim.z selects which projection this block does.
__global__ __launch_bounds__(256, 2) void sgemm_qkv_kernel(
    const float* __restrict__ Aq, const float* __restrict__ Ak,
    const float* __restrict__ Av,
    const float* __restrict__ Wq, const float* __restrict__ Wk,
    const float* __restrict__ Wv,
    const float* __restrict__ bq, const float* __restrict__ bk,
    const float* __restrict__ bv,
    float* __restrict__ Cq, float* __restrict__ Ck, float* __restrict__ Cv)
{
    if (blockIdx.z == 0)      sgemm_body(Aq, Wq, bq, Cq);
    else if (blockIdx.z == 1) sgemm_body(Ak, Wk, bk, Ck);
    else                      sgemm_body(Av, Wv, bv, Cv);
}

__global__ __launch_bounds__(256, 2) void sgemm_tf32_kernel(
    const float* __restrict__ A, const float* __restrict__ W,
    const float* __restrict__ bias, float* __restrict__ C)
{
    sgemm_body(A, W, bias, C);
}

// ---------------------------------------------------------------------------
// Tensor-core flash attention v4: single-tf32 QK (Ql plane dropped).
// BM=128, BN=64, DK=64, 8 warps x m16.
// Q pre-converted to tf32 ONCE per CTA (row-major stride 68). K pre-converted
// per tile (stride 68). Inner loop = pure LDS + MMA: 1 tf32 MMA per (c,nt).
// PV: fp16 m16n8k16, V layout [dv][72] (round-4, proven).
// Smem: sQh[128][68]f32 + sKh[64][68]f32 + sVt[64][72]f16 = 61440 B.
// ---------------------------------------------------------------------------
#define FLASH_SMEM_BYTES (61440)

__global__ __launch_bounds__(256, 2) void flash_tc_kernel(
    const float* __restrict__ Q, const float* __restrict__ K,
    const float* __restrict__ V, float* __restrict__ O)
{
    extern __shared__ char smraw[];
    float*  sQh = (float*)smraw;               // [128][68] tf32 bits
    float*  sKh = sQh + 128 * 68;              // [64][68]  tf32 bits
    __half* sVt = (__half*)(sKh + 64 * 68);    // [dv=64][kv stride 72]

    const int qb  = blockIdx.x;
    const int h   = blockIdx.y;
    const int b   = blockIdx.z;
    const int tid = threadIdx.x;
    const int wid = tid >> 5;
    const int lane = tid & 31;
    const int gq = lane >> 2;    // 0..7
    const int gr = lane & 3;     // 0..3
    const size_t base = (size_t)b * S_LEN * D_MOD + (size_t)h * DKH;

    // ---- Stage Q once: tf32-converted, row-major stride 68 ----
#pragma unroll
    for (int t = 0; t < 8; ++t) {
        int idx = tid + t * 256;
        int r  = idx >> 4;
        int c4 = (idx & 15) << 2;
        float4 v = *(const float4*)(Q + base + (size_t)(qb * 128 + r) * D_MOD + c4);
        float* dh = sQh + r * 68 + c4;
        dh[0] = __uint_as_float(f2tf32(v.x));
        dh[1] = __uint_as_float(f2tf32(v.y));
        dh[2] = __uint_as_float(f2tf32(v.z));
        dh[3] = __uint_as_float(f2tf32(v.w));
    }

    float o[8][4];
#pragma unroll
    for (int nt = 0; nt < 8; ++nt)
#pragma unroll
        for (int i = 0; i < 4; ++i) o[nt][i] = 0.f;
    float m0 = -1e30f, m1 = -1e30f, l0 = 0.f, l1 = 0.f;

    const int row0 = qb * 128 + wid * 16 + gq;
    const int row1 = row0 + 8;
    const float scale = 0.125f;                // 1/sqrt(64)
    const int jmax = 2 * qb + 1;

    for (int j = 0; j <= jmax; ++j) {
        __syncthreads();   // prior-iter readers done (orders Q staging on j=0)
        // ---- Stage K (tf32, row-major) and V (fp16 transposed) ----
#pragma unroll
        for (int t = 0; t < 4; ++t) {
            int idx = tid + t * 256;
            int r  = idx >> 4;                 // kv row 0..63
            int c4 = (idx & 15) << 2;          // d col
            float4 kv = *(const float4*)(K + base + (size_t)(j * 64 + r) * D_MOD + c4);
            float* dk = sKh + r * 68 + c4;
            dk[0] = __uint_as_float(f2tf32(kv.x));
            dk[1] = __uint_as_float(f2tf32(kv.y));
            dk[2] = __uint_as_float(f2tf32(kv.z));
            dk[3] = __uint_as_float(f2tf32(kv.w));
            float4 vv = *(const float4*)(V + base + (size_t)(j * 64 + r) * D_MOD + c4);
            sVt[(c4 + 0) * 72 + r] = __float2half(vv.x);
            sVt[(c4 + 1) * 72 + r] = __float2half(vv.y);
            sVt[(c4 + 2) * 72 + r] = __float2half(vv.z);
            sVt[(c4 + 3) * 72 + r] = __float2half(vv.w);
        }
        __syncthreads();

        // ---- S = Q K^T : single tf32 MMA per (c,nt), pure LDS + MMA ----
        float s[8][4];
#pragma unroll
        for (int nt = 0; nt < 8; ++nt)
#pragma unroll
            for (int i = 0; i < 4; ++i) s[nt][i] = 0.f;

        const int qrow = wid * 16 + gq;
#pragma unroll
        for (int c = 0; c < 8; ++c) {
            const int fo = c * 8 + gr;
            const uint32_t* qh = (const uint32_t*)sQh + qrow * 68 + fo;
            uint32_t ah0 = qh[0], ah1 = qh[8 * 68], ah2 = qh[4], ah3 = qh[8 * 68 + 4];
#pragma unroll
            for (int nt = 0; nt < 8; ++nt) {
                const uint32_t* kp = (const uint32_t*)sKh + (nt * 8 + gq) * 68 + fo;
                MMA_TF32(s[nt], ah0, ah1, ah2, ah3, kp[0], kp[4]);
            }
        }

        // ---- scale + causal mask ----
        const bool diag = (j >= 2 * qb);
#pragma unroll
        for (int nt = 0; nt < 8; ++nt) {
            const int colb = j * 64 + nt * 8 + 2 * gr;
#pragma unroll
            for (int e = 0; e < 4; ++e) {
                s[nt][e] *= scale;
                if (diag) {
                    const int col = colb + (e & 1);
                    const int row = (e < 2) ? row0 : row1;
                    if (col > row) s[nt][e] = -1e30f;
                }
            }
        }

        // ---- online softmax ----
        float mt0 = -1e30f, mt1 = -1e30f;
#pragma unroll
        for (int nt = 0; nt < 8; ++nt) {
            mt0 = fmaxf(mt0, fmaxf(s[nt][0], s[nt][1]));
            mt1 = fmaxf(mt1, fmaxf(s[nt][2], s[nt][3]));
        }
        mt0 = fmaxf(mt0, __shfl_xor_sync(0xffffffffu, mt0, 1));
        mt0 = fmaxf(mt0, __shfl_xor_sync(0xffffffffu, mt0, 2));
        mt1 = fmaxf(mt1, __shfl_xor_sync(0xffffffffu, mt1, 1));
        mt1 = fmaxf(mt1, __shfl_xor_sync(0xffffffffu, mt1, 2));
        const float mn0 = fmaxf(m0, mt0);
        const float mn1 = fmaxf(m1, mt1);
        const float alpha0 = __expf(m0 - mn0);
        const float alpha1 = __expf(m1 - mn1);
        m0 = mn0; m1 = mn1;

        float rs0 = 0.f, rs1 = 0.f;
#pragma unroll
        for (int nt = 0; nt < 8; ++nt) {
            s[nt][0] = __expf(s[nt][0] - m0);
            s[nt][1] = __expf(s[nt][1] - m0);
            s[nt][2] = __expf(s[nt][2] - m1);
            s[nt][3] = __expf(s[nt][3] - m1);
            rs0 += s[nt][0] + s[nt][1];
            rs1 += s[nt][2] + s[nt][3];
        }
        rs0 += __shfl_xor_sync(0xffffffffu, rs0, 1);
        rs0 += __shfl_xor_sync(0xffffffffu, rs0, 2);
        rs1 += __shfl_xor_sync(0xffffffffu, rs1, 1);
        rs1 += __shfl_xor_sync(0xffffffffu, rs1, 2);
        l0 = l0 * alpha0 + rs0;
        l1 = l1 * alpha1 + rs1;
#pragma unroll
        for (int nt = 0; nt < 8; ++nt) {
            o[nt][0] *= alpha0; o[nt][1] *= alpha0;
            o[nt][2] *= alpha1; o[nt][3] *= alpha1;
        }

        // ---- O += P V : fp16 m16n8k16, P from registers ----
#pragma unroll
        for (int c = 0; c < 4; ++c) {
            uint32_t pa0 = packh2(s[2 * c][0],     s[2 * c][1]);
            uint32_t pa1 = packh2(s[2 * c][2],     s[2 * c][3]);
            uint32_t pa2 = packh2(s[2 * c + 1][0], s[2 * c + 1][1]);
            uint32_t pa3 = packh2(s[2 * c + 1][2], s[2 * c + 1][3]);
#pragma unroll
            for (int nt = 0; nt < 8; ++nt) {
                const __half* vp = sVt + (nt * 8 + gq) * 72 + c * 16 + 2 * gr;
                uint32_t vb0 = *(const uint32_t*)vp;
                uint32_t vb1 = *(const uint32_t*)(vp + 8);
                MMA_F16(o[nt], pa0, pa1, pa2, pa3, vb0, vb1);
            }
        }
    }

    // ---- epilogue ----
    const float inv0 = 1.0f / l0;
    const float inv1 = 1.0f / l1;
#pragma unroll
    for (int nt = 0; nt < 8; ++nt) {
        const int dv = nt * 8 + 2 * gr;
        float2 w0, w1;
        w0.x = o[nt][0] * inv0; w0.y = o[nt][1] * inv0;
        w1.x = o[nt][2] * inv1; w1.y = o[nt][3] * inv1;
        *(float2*)(O + base + (size_t)row0 * D_MOD + dv) = w0;
        *(float2*)(O + base + (size_t)row1 * D_MOD + dv) = w1;
    }
}

// ---------------------------------------------------------------------------
extern "C" void kernel_launch(void* const* d_in, const int* in_sizes, int n_in,
                              void* d_out, int out_size)
{
    const float* query = (const float*)d_in[0];
    const float* key_  = (const float*)d_in[1];
    const float* value = (const float*)d_in[2];
    const float* Wq = (const float*)d_in[3];
    const float* bq = (const float*)d_in[4];
    const float* Wk = (const float*)d_in[5];
    const float* bk = (const float*)d_in[6];
    const float* Wv = (const float*)d_in[7];
    const float* bv = (const float*)d_in[8];
    const float* Wo = (const float*)d_in[9];
    const float* bo = (const float*)d_in[10];
    // d_in[11] = causal mask (bool) — causality implemented analytically.

    float *Qp, *Kp, *Vp, *Op;
    cudaGetSymbolAddress((void**)&Qp, g_Q);
    cudaGetSymbolAddress((void**)&Kp, g_K);
    cudaGetSymbolAddress((void**)&Vp, g_V);
    cudaGetSymbolAddress((void**)&Op, g_O);

    cudaFuncSetAttribute(sgemm_qkv_kernel,
                         cudaFuncAttributeMaxDynamicSharedMemorySize, GEMM_SMEM_BYTES);
    cudaFuncSetAttribute(sgemm_tf32_kernel,
                         cudaFuncAttributeMaxDynamicSharedMemorySize, GEMM_SMEM_BYTES);
    cudaFuncSetAttribute(flash_tc_kernel,
                         cudaFuncAttributeMaxDynamicSharedMemorySize, FLASH_SMEM_BYTES);

    dim3 gqkv(D_MOD / 128, MROWS / 128, 3);  // (8, 64, 3) fused Q/K/V
    sgemm_qkv_kernel<<<gqkv, 256, GEMM_SMEM_BYTES>>>(
        query, key_, value, Wq, Wk, Wv, bq, bk, bv, Qp, Kp, Vp);

    flash_tc_kernel<<<dim3(S_LEN / 128, NH, B_SZ), 256, FLASH_SMEM_BYTES>>>(Qp, Kp, Vp, Op);

    dim3 gg(D_MOD / 128, MROWS / 128);       // (8, 64)
    sgemm_tf32_kernel<<<gg, 256, GEMM_SMEM_BYTES>>>(Op, Wo, bo, (float*)d_out);
}

// round 9
// speedup vs baseline: 4.0238x; 1.1074x over previous
#include <cuda_runtime.h>
#include <cuda_fp16.h>
#include <math.h>
#include <stdint.h>

#define B_SZ   4
#define S_LEN  2048
#define D_MOD  1024
#define NH     16
#define DKH    64
#define MROWS  (B_SZ * S_LEN)   // 8192

// Scratch (allocation-free rule: __device__ globals)
__device__ float g_Q[MROWS * D_MOD];
__device__ float g_K[MROWS * D_MOD];
__device__ float g_V[MROWS * D_MOD];
__device__ float g_O[MROWS * D_MOD];

__device__ __forceinline__ uint32_t f2tf32(float x) {
    uint32_t r;
    asm("cvt.rna.tf32.f32 %0, %1;" : "=r"(r) : "f"(x));
    return r;
}
__device__ __forceinline__ uint32_t packh2(float x, float y) {
    __half2 h = __floats2half2_rn(x, y);
    return *(uint32_t*)&h;
}
__device__ __forceinline__ uint32_t smem_u32(const void* p) {
    uint32_t a;
    asm("{ .reg .u64 t; cvta.to.shared.u64 t, %1; cvt.u32.u64 %0, t; }"
        : "=r"(a) : "l"(p));
    return a;
}

#define MMA_TF32(ACC, A0, A1, A2, A3, B0, B1)                                 \
    asm volatile(                                                             \
        "mma.sync.aligned.m16n8k8.row.col.f32.tf32.tf32.f32 "                 \
        "{%0,%1,%2,%3}, {%4,%5,%6,%7}, {%8,%9}, {%0,%1,%2,%3};"               \
        : "+f"((ACC)[0]), "+f"((ACC)[1]), "+f"((ACC)[2]), "+f"((ACC)[3])      \
        : "r"(A0), "r"(A1), "r"(A2), "r"(A3), "r"(B0), "r"(B1))

#define MMA_F16(ACC, A0, A1, A2, A3, B0, B1)                                  \
    asm volatile(                                                             \
        "mma.sync.aligned.m16n8k16.row.col.f32.f16.f16.f32 "                  \
        "{%0,%1,%2,%3}, {%4,%5,%6,%7}, {%8,%9}, {%0,%1,%2,%3};"               \
        : "+f"((ACC)[0]), "+f"((ACC)[1]), "+f"((ACC)[2]), "+f"((ACC)[3])      \
        : "r"(A0), "r"(A1), "r"(A2), "r"(A3), "r"(B0), "r"(B1))

#define LDMATRIX_X4_TRANS(R0, R1, R2, R3, ADDR)                               \
    asm volatile(                                                             \
        "ldmatrix.sync.aligned.m8n8.x4.trans.shared.b16 {%0,%1,%2,%3}, [%4];" \
        : "=r"(R0), "=r"(R1), "=r"(R2), "=r"(R3) : "r"(ADDR))

// ---------------------------------------------------------------------------
// TF32 tensor-core GEMM body, double-buffered: C = A @ W^T + bias
// M=8192, N=K=1024 hardcoded. 128x128 tile, BK=32, 256 threads. (unchanged)
// ---------------------------------------------------------------------------
#define GEMM_SMEM_BYTES (4 * 128 * 36 * 4)

__device__ __forceinline__ void sgemm_body(
    const float* __restrict__ A, const float* __restrict__ W,
    const float* __restrict__ bias, float* __restrict__ C)
{
    const int M = MROWS, N = D_MOD, K = D_MOD;
    extern __shared__ uint32_t sm_u[];
    uint32_t* const Ast0 = sm_u;
    uint32_t* const Ast1 = sm_u + 128 * 36;
    uint32_t* const Wst0 = sm_u + 2 * 128 * 36;
    uint32_t* const Wst1 = sm_u + 3 * 128 * 36;

    const int bm = blockIdx.y * 128;
    const int bn = blockIdx.x * 128;
    const int tid  = threadIdx.x;
    const int wid  = tid >> 5;
    const int lane = tid & 31;
    const int wm = (wid & 1) * 64;
    const int wn = (wid >> 1) * 32;
    const int lr  = tid >> 3;
    const int lc4 = (tid & 7) << 2;
    const int gq = lane >> 2;
    const int gr = lane & 3;

    float acc[4][4][4];
#pragma unroll
    for (int mt = 0; mt < 4; ++mt)
#pragma unroll
        for (int nt = 0; nt < 4; ++nt)
#pragma unroll
            for (int i = 0; i < 4; ++i) acc[mt][nt][i] = 0.f;

    const float* Ag = A + (size_t)(bm + lr) * K + lc4;
    const float* Wg = W + (size_t)(bn + lr) * K + lc4;

    float4 av[4], wv[4];
#pragma unroll
    for (int p = 0; p < 4; ++p) {
        av[p] = *(const float4*)(Ag + (size_t)(p * 32) * K);
        wv[p] = *(const float4*)(Wg + (size_t)(p * 32) * K);
    }
#pragma unroll
    for (int p = 0; p < 4; ++p) {
        uint32_t* as = Ast0 + (lr + p * 32) * 36 + lc4;
        uint32_t* ws = Wst0 + (lr + p * 32) * 36 + lc4;
        as[0] = f2tf32(av[p].x); as[1] = f2tf32(av[p].y);
        as[2] = f2tf32(av[p].z); as[3] = f2tf32(av[p].w);
        ws[0] = f2tf32(wv[p].x); ws[1] = f2tf32(wv[p].y);
        ws[2] = f2tf32(wv[p].z); ws[3] = f2tf32(wv[p].w);
    }
    __syncthreads();

    const int nIter = K >> 5;
    for (int it = 0; it < nIter; ++it) {
        const bool more = (it + 1 < nIter);
        if (more) {
            const int k1 = (it + 1) << 5;
#pragma unroll
            for (int p = 0; p < 4; ++p) {
                av[p] = *(const float4*)(Ag + (size_t)(p * 32) * K + k1);
                wv[p] = *(const float4*)(Wg + (size_t)(p * 32) * K + k1);
            }
        }

        const uint32_t* Acur = (it & 1) ? Ast1 : Ast0;
        const uint32_t* Wcur = (it & 1) ? Wst1 : Wst0;
#pragma unroll
        for (int c = 0; c < 4; ++c) {
            const int kk = c * 8 + gr;
            uint32_t a[4][4], b[4][2];
#pragma unroll
            for (int mt = 0; mt < 4; ++mt) {
                const int r0 = wm + mt * 16 + gq;
                a[mt][0] = Acur[r0 * 36 + kk];
                a[mt][1] = Acur[(r0 + 8) * 36 + kk];
                a[mt][2] = Acur[r0 * 36 + kk + 4];
                a[mt][3] = Acur[(r0 + 8) * 36 + kk + 4];
            }
#pragma unroll
            for (int nt = 0; nt < 4; ++nt) {
                const int n0 = wn + nt * 8 + gq;
                b[nt][0] = Wcur[n0 * 36 + kk];
                b[nt][1] = Wcur[n0 * 36 + kk + 4];
            }
#pragma unroll
            for (int mt = 0; mt < 4; ++mt)
#pragma unroll
                for (int nt = 0; nt < 4; ++nt)
                    MMA_TF32(acc[mt][nt], a[mt][0], a[mt][1], a[mt][2], a[mt][3],
                             b[nt][0], b[nt][1]);
        }

        if (more) {
            __syncthreads();
            uint32_t* Anx = ((it + 1) & 1) ? Ast1 : Ast0;
            uint32_t* Wnx = ((it + 1) & 1) ? Wst1 : Wst0;
#pragma unroll
            for (int p = 0; p < 4; ++p) {
                uint32_t* as = Anx + (lr + p * 32) * 36 + lc4;
                uint32_t* ws = Wnx + (lr + p * 32) * 36 + lc4;
                as[0] = f2tf32(av[p].x); as[1] = f2tf32(av[p].y);
                as[2] = f2tf32(av[p].z); as[3] = f2tf32(av[p].w);
                ws[0] = f2tf32(wv[p].x); ws[1] = f2tf32(wv[p].y);
                ws[2] = f2tf32(wv[p].z); ws[3] = f2tf32(wv[p].w);
            }
            __syncthreads();
        }
    }

    const int c2 = gr * 2;
#pragma unroll
    for (int mt = 0; mt < 4; ++mt) {
#pragma unroll
        for (int nt = 0; nt < 4; ++nt) {
            const int col = bn + wn + nt * 8 + c2;
            const float b0 = bias[col], b1 = bias[col + 1];
            const size_t row0 = (size_t)(bm + wm + mt * 16 + gq);
            float2 v0, v1;
            v0.x = acc[mt][nt][0] + b0; v0.y = acc[mt][nt][1] + b1;
            v1.x = acc[mt][nt][2] + b0; v1.y = acc[mt][nt][3] + b1;
            *(float2*)(C + row0 * N + col)       = v0;
            *(float2*)(C + (row0 + 8) * N + col) = v1;
        }
    }
}

// Fused Q/K/V projection: gridDim.z selects which projection this block does.
__global__ __launch_bounds__(256, 2) void sgemm_qkv_kernel(
    const float* __restrict__ Aq, const float* __restrict__ Ak,
    const float* __restrict__ Av,
    const float* __restrict__ Wq, const float* __restrict__ Wk,
    const float* __restrict__ Wv,
    const float* __restrict__ bq, const float* __restrict__ bk,
    const float* __restrict__ bv,
    float* __restrict__ Cq, float* __restrict__ Ck, float* __restrict__ Cv)
{
    if (blockIdx.z == 0)      sgemm_body(Aq, Wq, bq, Cq);
    else if (blockIdx.z == 1) sgemm_body(Ak, Wk, bk, Ck);
    else                      sgemm_body(Av, Wv, bv, Cv);
}

__global__ __launch_bounds__(256, 2) void sgemm_tf32_kernel(
    const float* __restrict__ A, const float* __restrict__ W,
    const float* __restrict__ bias, float* __restrict__ C)
{
    sgemm_body(A, W, bias, C);
}

// ---------------------------------------------------------------------------
// Tensor-core flash attention v5: V staged ROW-MAJOR fp16 [kv][72 halfwords]
// via packed STS.64 (conflict-free) and PV B-fragments via ldmatrix.x4.trans
// (2 n-tiles per instr, conflict-free: row stride 144B tiles all 32 banks).
// QK path identical to v4 (single tf32, stride-68 planes).
// Smem: sQh[128][68]f32 + sKh[64][68]f32 + sV[64][72]f16 = 61440 B.
// ---------------------------------------------------------------------------
#define FLASH_SMEM_BYTES (61440)

__global__ __launch_bounds__(256, 2) void flash_tc_kernel(
    const float* __restrict__ Q, const float* __restrict__ K,
    const float* __restrict__ V, float* __restrict__ O)
{
    extern __shared__ char smraw[];
    float*  sQh = (float*)smraw;               // [128][68] tf32 bits
    float*  sKh = sQh + 128 * 68;              // [64][68]  tf32 bits
    __half* sV  = (__half*)(sKh + 64 * 68);    // [kv=64][stride 72] fp16 row-major

    const int qb  = blockIdx.x;
    const int h   = blockIdx.y;
    const int b   = blockIdx.z;
    const int tid = threadIdx.x;
    const int wid = tid >> 5;
    const int lane = tid & 31;
    const int gq = lane >> 2;    // 0..7
    const int gr = lane & 3;     // 0..3
    const size_t base = (size_t)b * S_LEN * D_MOD + (size_t)h * DKH;

    // ldmatrix address base: row = lane&15 (kv within 16-chunk), col-half = lane>>4
    const uint32_t vmat_base = smem_u32(sV) + (uint32_t)(lane & 15) * 144
                             + (uint32_t)((lane >> 4) << 4);

    // ---- Stage Q once: tf32-converted, row-major stride 68, STS.128 ----
#pragma unroll
    for (int t = 0; t < 8; ++t) {
        int idx = tid + t * 256;
        int r  = idx >> 4;
        int c4 = (idx & 15) << 2;
        float4 v = *(const float4*)(Q + base + (size_t)(qb * 128 + r) * D_MOD + c4);
        float4 cv;
        cv.x = __uint_as_float(f2tf32(v.x));
        cv.y = __uint_as_float(f2tf32(v.y));
        cv.z = __uint_as_float(f2tf32(v.z));
        cv.w = __uint_as_float(f2tf32(v.w));
        *(float4*)(sQh + r * 68 + c4) = cv;
    }

    float o[8][4];
#pragma unroll
    for (int nt = 0; nt < 8; ++nt)
#pragma unroll
        for (int i = 0; i < 4; ++i) o[nt][i] = 0.f;
    float m0 = -1e30f, m1 = -1e30f, l0 = 0.f, l1 = 0.f;

    const int row0 = qb * 128 + wid * 16 + gq;
    const int row1 = row0 + 8;
    const float scale = 0.125f;                // 1/sqrt(64)
    const int jmax = 2 * qb + 1;

    for (int j = 0; j <= jmax; ++j) {
        __syncthreads();   // prior-iter readers done (orders Q staging on j=0)
        // ---- Stage K (tf32, STS.128) and V (fp16 row-major, packed STS.64) ----
#pragma unroll
        for (int t = 0; t < 4; ++t) {
            int idx = tid + t * 256;
            int r  = idx >> 4;                 // kv row 0..63
            int c4 = (idx & 15) << 2;          // d col
            float4 kv = *(const float4*)(K + base + (size_t)(j * 64 + r) * D_MOD + c4);
            float4 ck;
            ck.x = __uint_as_float(f2tf32(kv.x));
            ck.y = __uint_as_float(f2tf32(kv.y));
            ck.z = __uint_as_float(f2tf32(kv.z));
            ck.w = __uint_as_float(f2tf32(kv.w));
            *(float4*)(sKh + r * 68 + c4) = ck;
            float4 vv = *(const float4*)(V + base + (size_t)(j * 64 + r) * D_MOD + c4);
            uint2 pv;
            pv.x = packh2(vv.x, vv.y);
            pv.y = packh2(vv.z, vv.w);
            *(uint2*)(sV + r * 72 + c4) = pv;
        }
        __syncthreads();

        // ---- S = Q K^T : single tf32 MMA per (c,nt), pure LDS + MMA ----
        float s[8][4];
#pragma unroll
        for (int nt = 0; nt < 8; ++nt)
#pragma unroll
            for (int i = 0; i < 4; ++i) s[nt][i] = 0.f;

        const int qrow = wid * 16 + gq;
#pragma unroll
        for (int c = 0; c < 8; ++c) {
            const int fo = c * 8 + gr;
            const uint32_t* qh = (const uint32_t*)sQh + qrow * 68 + fo;
            uint32_t ah0 = qh[0], ah1 = qh[8 * 68], ah2 = qh[4], ah3 = qh[8 * 68 + 4];
#pragma unroll
            for (int nt = 0; nt < 8; ++nt) {
                const uint32_t* kp = (const uint32_t*)sKh + (nt * 8 + gq) * 68 + fo;
                MMA_TF32(s[nt], ah0, ah1, ah2, ah3, kp[0], kp[4]);
            }
        }

        // ---- scale + causal mask ----
        const bool diag = (j >= 2 * qb);
#pragma unroll
        for (int nt = 0; nt < 8; ++nt) {
            const int colb = j * 64 + nt * 8 + 2 * gr;
#pragma unroll
            for (int e = 0; e < 4; ++e) {
                s[nt][e] *= scale;
                if (diag) {
                    const int col = colb + (e & 1);
                    const int row = (e < 2) ? row0 : row1;
                    if (col > row) s[nt][e] = -1e30f;
                }
            }
        }

        // ---- online softmax ----
        float mt0 = -1e30f, mt1 = -1e30f;
#pragma unroll
        for (int nt = 0; nt < 8; ++nt) {
            mt0 = fmaxf(mt0, fmaxf(s[nt][0], s[nt][1]));
            mt1 = fmaxf(mt1, fmaxf(s[nt][2], s[nt][3]));
        }
        mt0 = fmaxf(mt0, __shfl_xor_sync(0xffffffffu, mt0, 1));
        mt0 = fmaxf(mt0, __shfl_xor_sync(0xffffffffu, mt0, 2));
        mt1 = fmaxf(mt1, __shfl_xor_sync(0xffffffffu, mt1, 1));
        mt1 = fmaxf(mt1, __shfl_xor_sync(0xffffffffu, mt1, 2));
        const float mn0 = fmaxf(m0, mt0);
        const float mn1 = fmaxf(m1, mt1);
        const float alpha0 = __expf(m0 - mn0);
        const float alpha1 = __expf(m1 - mn1);
        m0 = mn0; m1 = mn1;

        float rs0 = 0.f, rs1 = 0.f;
#pragma unroll
        for (int nt = 0; nt < 8; ++nt) {
            s[nt][0] = __expf(s[nt][0] - m0);
            s[nt][1] = __expf(s[nt][1] - m0);
            s[nt][2] = __expf(s[nt][2] - m1);
            s[nt][3] = __expf(s[nt][3] - m1);
            rs0 += s[nt][0] + s[nt][1];
            rs1 += s[nt][2] + s[nt][3];
        }
        rs0 += __shfl_xor_sync(0xffffffffu, rs0, 1);
        rs0 += __shfl_xor_sync(0xffffffffu, rs0, 2);
        rs1 += __shfl_xor_sync(0xffffffffu, rs1, 1);
        rs1 += __shfl_xor_sync(0xffffffffu, rs1, 2);
        l0 = l0 * alpha0 + rs0;
        l1 = l1 * alpha1 + rs1;
#pragma unroll
        for (int nt = 0; nt < 8; ++nt) {
            o[nt][0] *= alpha0; o[nt][1] *= alpha0;
            o[nt][2] *= alpha1; o[nt][3] *= alpha1;
        }

        // ---- O += P V : fp16 m16n8k16, B-frags via ldmatrix.x4.trans ----
#pragma unroll
        for (int c = 0; c < 4; ++c) {
            uint32_t pa0 = packh2(s[2 * c][0],     s[2 * c][1]);
            uint32_t pa1 = packh2(s[2 * c][2],     s[2 * c][3]);
            uint32_t pa2 = packh2(s[2 * c + 1][0], s[2 * c + 1][1]);
            uint32_t pa3 = packh2(s[2 * c + 1][2], s[2 * c + 1][3]);
            const uint32_t abase = vmat_base + (uint32_t)(c * 16 * 144);
#pragma unroll
            for (int ntp = 0; ntp < 4; ++ntp) {
                uint32_t r0, r1, r2, r3;
                LDMATRIX_X4_TRANS(r0, r1, r2, r3, abase + ntp * 32);
                MMA_F16(o[2 * ntp],     pa0, pa1, pa2, pa3, r0, r1);
                MMA_F16(o[2 * ntp + 1], pa0, pa1, pa2, pa3, r2, r3);
            }
        }
    }

    // ---- epilogue ----
    const float inv0 = 1.0f / l0;
    const float inv1 = 1.0f / l1;
#pragma unroll
    for (int nt = 0; nt < 8; ++nt) {
        const int dv = nt * 8 + 2 * gr;
        float2 w0, w1;
        w0.x = o[nt][0] * inv0; w0.y = o[nt][1] * inv0;
        w1.x = o[nt][2] * inv1; w1.y = o[nt][3] * inv1;
        *(float2*)(O + base + (size_t)row0 * D_MOD + dv) = w0;
        *(float2*)(O + base + (size_t)row1 * D_MOD + dv) = w1;
    }
}

// ---------------------------------------------------------------------------
extern "C" void kernel_launch(void* const* d_in, const int* in_sizes, int n_in,
                              void* d_out, int out_size)
{
    const float* query = (const float*)d_in[0];
    const float* key_  = (const float*)d_in[1];
    const float* value = (const float*)d_in[2];
    const float* Wq = (const float*)d_in[3];
    const float* bq = (const float*)d_in[4];
    const float* Wk = (const float*)d_in[5];
    const float* bk = (const float*)d_in[6];
    const float* Wv = (const float*)d_in[7];
    const float* bv = (const float*)d_in[8];
    const float* Wo = (const float*)d_in[9];
    const float* bo = (const float*)d_in[10];
    // d_in[11] = causal mask (bool) — causality implemented analytically.

    float *Qp, *Kp, *Vp, *Op;
    cudaGetSymbolAddress((void**)&Qp, g_Q);
    cudaGetSymbolAddress((void**)&Kp, g_K);
    cudaGetSymbolAddress((void**)&Vp, g_V);
    cudaGetSymbolAddress((void**)&Op, g_O);

    cudaFuncSetAttribute(sgemm_qkv_kernel,
                         cudaFuncAttributeMaxDynamicSharedMemorySize, GEMM_SMEM_BYTES);
    cudaFuncSetAttribute(sgemm_tf32_kernel,
                         cudaFuncAttributeMaxDynamicSharedMemorySize, GEMM_SMEM_BYTES);
    cudaFuncSetAttribute(flash_tc_kernel,
                         cudaFuncAttributeMaxDynamicSharedMemorySize, FLASH_SMEM_BYTES);

    dim3 gqkv(D_MOD / 128, MROWS / 128, 3);  // (8, 64, 3) fused Q/K/V
    sgemm_qkv_kernel<<<gqkv, 256, GEMM_SMEM_BYTES>>>(
        query, key_, value, Wq, Wk, Wv, bq, bk, bv, Qp, Kp, Vp);

    flash_tc_kernel<<<dim3(S_LEN / 128, NH, B_SZ), 256, FLASH_SMEM_BYTES>>>(Qp, Kp, Vp, Op);

    dim3 gg(D_MOD / 128, MROWS / 128);       // (8, 64)
    sgemm_tf32_kernel<<<gg, 256, GEMM_SMEM_BYTES>>>(Op, Wo, bo, (float*)d_out);
}

// round 10
// speedup vs baseline: 5.0614x; 1.2579x over previous
#include <cuda_runtime.h>
#include <cuda_fp16.h>
#include <math.h>
#include <stdint.h>

#define B_SZ   4
#define S_LEN  2048
#define D_MOD  1024
#define NH     16
#define DKH    64
#define MROWS  (B_SZ * S_LEN)   // 8192

// Scratch (allocation-free rule: __device__ globals)
__device__ float g_Q[MROWS * D_MOD];
__device__ float g_K[MROWS * D_MOD];
__device__ float g_V[MROWS * D_MOD];
__device__ float g_O[MROWS * D_MOD];

__device__ __forceinline__ uint32_t f2tf32(float x) {
    uint32_t r;
    asm("cvt.rna.tf32.f32 %0, %1;" : "=r"(r) : "f"(x));
    return r;
}
__device__ __forceinline__ uint32_t packh2(float x, float y) {
    __half2 h = __floats2half2_rn(x, y);
    return *(uint32_t*)&h;
}
__device__ __forceinline__ uint32_t smem_u32(const void* p) {
    uint32_t a;
    asm("{ .reg .u64 t; cvta.to.shared.u64 t, %1; cvt.u32.u64 %0, t; }"
        : "=r"(a) : "l"(p));
    return a;
}

#define MMA_TF32(ACC, A0, A1, A2, A3, B0, B1)                                 \
    asm volatile(                                                             \
        "mma.sync.aligned.m16n8k8.row.col.f32.tf32.tf32.f32 "                 \
        "{%0,%1,%2,%3}, {%4,%5,%6,%7}, {%8,%9}, {%0,%1,%2,%3};"               \
        : "+f"((ACC)[0]), "+f"((ACC)[1]), "+f"((ACC)[2]), "+f"((ACC)[3])      \
        : "r"(A0), "r"(A1), "r"(A2), "r"(A3), "r"(B0), "r"(B1))

#define MMA_F16(ACC, A0, A1, A2, A3, B0, B1)                                  \
    asm volatile(                                                             \
        "mma.sync.aligned.m16n8k16.row.col.f32.f16.f16.f32 "                  \
        "{%0,%1,%2,%3}, {%4,%5,%6,%7}, {%8,%9}, {%0,%1,%2,%3};"               \
        : "+f"((ACC)[0]), "+f"((ACC)[1]), "+f"((ACC)[2]), "+f"((ACC)[3])      \
        : "r"(A0), "r"(A1), "r"(A2), "r"(A3), "r"(B0), "r"(B1))

#define LDMATRIX_X4(R0, R1, R2, R3, ADDR)                                     \
    asm volatile(                                                             \
        "ldmatrix.sync.aligned.m8n8.x4.shared.b16 {%0,%1,%2,%3}, [%4];"       \
        : "=r"(R0), "=r"(R1), "=r"(R2), "=r"(R3) : "r"(ADDR))

#define LDMATRIX_X4_TRANS(R0, R1, R2, R3, ADDR)                               \
    asm volatile(                                                             \
        "ldmatrix.sync.aligned.m8n8.x4.trans.shared.b16 {%0,%1,%2,%3}, [%4];" \
        : "=r"(R0), "=r"(R1), "=r"(R2), "=r"(R3) : "r"(ADDR))

// ---------------------------------------------------------------------------
// FP16 tensor-core GEMM body, double-buffered: C = A @ W^T + bias (fp32 acc).
// M=8192, N=K=1024. 128x128 tile, BK=32, 256 threads (8 warps 2m x 4n),
// warp 64x32 via 4x4 tiles of mma.sync.m16n8k16.f16.
// Smem: fp16 [128][40] per stage (stride 40 halfs = 80 B, 16B-aligned;
// ldmatrix row banks 20*r mod 32 cover all 32 banks -> conflict-free).
// 2 stages x (A + W) = 4 * 10240 B = 40960 B.
// ---------------------------------------------------------------------------
#define GEMM_SMEM_BYTES (40960)

__device__ __forceinline__ void sgemm_body(
    const float* __restrict__ A, const float* __restrict__ W,
    const float* __restrict__ bias, float* __restrict__ C)
{
    const int N = D_MOD, K = D_MOD;
    extern __shared__ char smch[];
    __half* const Ast0 = (__half*)smch;
    __half* const Ast1 = Ast0 + 128 * 40;
    __half* const Wst0 = Ast1 + 128 * 40;
    __half* const Wst1 = Wst0 + 128 * 40;

    const int bm = blockIdx.y * 128;
    const int bn = blockIdx.x * 128;
    const int tid  = threadIdx.x;
    const int wid  = tid >> 5;
    const int lane = tid & 31;
    const int wm = (wid & 1) * 64;     // warp m-offset
    const int wn = (wid >> 1) * 32;    // warp n-offset
    const int lr  = tid >> 3;          // staging row 0..31
    const int lc4 = (tid & 7) << 2;    // staging k-col (halfwords) 0,4,...,28
    const int gq = lane >> 2;
    const int gr = lane & 3;

    // ldmatrix lane -> (row within 16, k-half) for A fragments
    const int lm_row = (lane & 7) + ((lane >> 3) & 1) * 8;   // 0..15
    const int lm_k8  = (lane >> 4) << 3;                     // 0 or 8 halves

    float acc[4][4][4];
#pragma unroll
    for (int mt = 0; mt < 4; ++mt)
#pragma unroll
        for (int nt = 0; nt < 4; ++nt)
#pragma unroll
            for (int i = 0; i < 4; ++i) acc[mt][nt][i] = 0.f;

    const float* Ag = A + (size_t)(bm + lr) * K + lc4;
    const float* Wg = W + (size_t)(bn + lr) * K + lc4;

    float4 av[4], wv[4];
#pragma unroll
    for (int p = 0; p < 4; ++p) {
        av[p] = *(const float4*)(Ag + (size_t)(p * 32) * K);
        wv[p] = *(const float4*)(Wg + (size_t)(p * 32) * K);
    }
#pragma unroll
    for (int p = 0; p < 4; ++p) {
        uint2 pa, pw;
        pa.x = packh2(av[p].x, av[p].y); pa.y = packh2(av[p].z, av[p].w);
        pw.x = packh2(wv[p].x, wv[p].y); pw.y = packh2(wv[p].z, wv[p].w);
        *(uint2*)(Ast0 + (lr + p * 32) * 40 + lc4) = pa;
        *(uint2*)(Wst0 + (lr + p * 32) * 40 + lc4) = pw;
    }
    __syncthreads();

    const int nIter = K >> 5;          // 32
    for (int it = 0; it < nIter; ++it) {
        const bool more = (it + 1 < nIter);
        if (more) {
            const int k1 = (it + 1) << 5;
#pragma unroll
            for (int p = 0; p < 4; ++p) {
                av[p] = *(const float4*)(Ag + (size_t)(p * 32) * K + k1);
                wv[p] = *(const float4*)(Wg + (size_t)(p * 32) * K + k1);
            }
        }

        const __half* Acur = (it & 1) ? Ast1 : Ast0;
        const __half* Wcur = (it & 1) ? Wst1 : Wst0;
#pragma unroll
        for (int c = 0; c < 2; ++c) {          // two k16 chunks per BK=32
            uint32_t a[4][4], b[4][2];
#pragma unroll
            for (int mt = 0; mt < 4; ++mt) {
                const uint32_t addr = smem_u32(
                    Acur + (wm + mt * 16 + lm_row) * 40 + c * 16 + lm_k8);
                LDMATRIX_X4(a[mt][0], a[mt][1], a[mt][2], a[mt][3], addr);
            }
#pragma unroll
            for (int nt = 0; nt < 4; ++nt) {
                const __half* wp = Wcur + (wn + nt * 8 + gq) * 40 + c * 16 + 2 * gr;
                b[nt][0] = *(const uint32_t*)wp;
                b[nt][1] = *(const uint32_t*)(wp + 8);
            }
#pragma unroll
            for (int mt = 0; mt < 4; ++mt)
#pragma unroll
                for (int nt = 0; nt < 4; ++nt)
                    MMA_F16(acc[mt][nt], a[mt][0], a[mt][1], a[mt][2], a[mt][3],
                            b[nt][0], b[nt][1]);
        }

        if (more) {
            __syncthreads();
            __half* Anx = ((it + 1) & 1) ? Ast1 : Ast0;
            __half* Wnx = ((it + 1) & 1) ? Wst1 : Wst0;
#pragma unroll
            for (int p = 0; p < 4; ++p) {
                uint2 pa, pw;
                pa.x = packh2(av[p].x, av[p].y); pa.y = packh2(av[p].z, av[p].w);
                pw.x = packh2(wv[p].x, wv[p].y); pw.y = packh2(wv[p].z, wv[p].w);
                *(uint2*)(Anx + (lr + p * 32) * 40 + lc4) = pa;
                *(uint2*)(Wnx + (lr + p * 32) * 40 + lc4) = pw;
            }
            __syncthreads();
        }
    }

    // Epilogue: m16n8 acc layout: c0/c1 at (row gq, cols 2gr,2gr+1), c2/c3 row gq+8.
    const int c2 = gr * 2;
#pragma unroll
    for (int mt = 0; mt < 4; ++mt) {
#pragma unroll
        for (int nt = 0; nt < 4; ++nt) {
            const int col = bn + wn + nt * 8 + c2;
            const float b0 = bias[col], b1 = bias[col + 1];
            const size_t row0 = (size_t)(bm + wm + mt * 16 + gq);
            float2 v0, v1;
            v0.x = acc[mt][nt][0] + b0; v0.y = acc[mt][nt][1] + b1;
            v1.x = acc[mt][nt][2] + b0; v1.y = acc[mt][nt][3] + b1;
            *(float2*)(C + row0 * N + col)       = v0;
            *(float2*)(C + (row0 + 8) * N + col) = v1;
        }
    }
}

// Fused Q/K/V projection: gridDim.z selects which projection this block does.
__global__ __launch_bounds__(256, 2) void sgemm_qkv_kernel(
    const float* __restrict__ Aq, const float* __restrict__ Ak,
    const float* __restrict__ Av,
    const float* __restrict__ Wq, const float* __restrict__ Wk,
    const float* __restrict__ Wv,
    const float* __restrict__ bq, const float* __restrict__ bk,
    const float* __restrict__ bv,
    float* __restrict__ Cq, float* __restrict__ Ck, float* __restrict__ Cv)
{
    if (blockIdx.z == 0)      sgemm_body(Aq, Wq, bq, Cq);
    else if (blockIdx.z == 1) sgemm_body(Ak, Wk, bk, Ck);
    else                      sgemm_body(Av, Wv, bv, Cv);
}

__global__ __launch_bounds__(256, 2) void sgemm_f16_kernel(
    const float* __restrict__ A, const float* __restrict__ W,
    const float* __restrict__ bias, float* __restrict__ C)
{
    sgemm_body(A, W, bias, C);
}

// ---------------------------------------------------------------------------
// Tensor-core flash attention v5 (unchanged from round 9).
// Smem: sQh[128][68]f32 + sKh[64][68]f32 + sV[64][72]f16 = 61440 B.
// ---------------------------------------------------------------------------
#define FLASH_SMEM_BYTES (61440)

__global__ __launch_bounds__(256, 2) void flash_tc_kernel(
    const float* __restrict__ Q, const float* __restrict__ K,
    const float* __restrict__ V, float* __restrict__ O)
{
    extern __shared__ char smraw[];
    float*  sQh = (float*)smraw;               // [128][68] tf32 bits
    float*  sKh = sQh + 128 * 68;              // [64][68]  tf32 bits
    __half* sV  = (__half*)(sKh + 64 * 68);    // [kv=64][stride 72] fp16 row-major

    const int qb  = blockIdx.x;
    const int h   = blockIdx.y;
    const int b   = blockIdx.z;
    const int tid = threadIdx.x;
    const int wid = tid >> 5;
    const int lane = tid & 31;
    const int gq = lane >> 2;    // 0..7
    const int gr = lane & 3;     // 0..3
    const size_t base = (size_t)b * S_LEN * D_MOD + (size_t)h * DKH;

    const uint32_t vmat_base = smem_u32(sV) + (uint32_t)(lane & 15) * 144
                             + (uint32_t)((lane >> 4) << 4);

    // ---- Stage Q once: tf32-converted, row-major stride 68, STS.128 ----
#pragma unroll
    for (int t = 0; t < 8; ++t) {
        int idx = tid + t * 256;
        int r  = idx >> 4;
        int c4 = (idx & 15) << 2;
        float4 v = *(const float4*)(Q + base + (size_t)(qb * 128 + r) * D_MOD + c4);
        float4 cv;
        cv.x = __uint_as_float(f2tf32(v.x));
        cv.y = __uint_as_float(f2tf32(v.y));
        cv.z = __uint_as_float(f2tf32(v.z));
        cv.w = __uint_as_float(f2tf32(v.w));
        *(float4*)(sQh + r * 68 + c4) = cv;
    }

    float o[8][4];
#pragma unroll
    for (int nt = 0; nt < 8; ++nt)
#pragma unroll
        for (int i = 0; i < 4; ++i) o[nt][i] = 0.f;
    float m0 = -1e30f, m1 = -1e30f, l0 = 0.f, l1 = 0.f;

    const int row0 = qb * 128 + wid * 16 + gq;
    const int row1 = row0 + 8;
    const float scale = 0.125f;                // 1/sqrt(64)
    const int jmax = 2 * qb + 1;

    for (int j = 0; j <= jmax; ++j) {
        __syncthreads();
#pragma unroll
        for (int t = 0; t < 4; ++t) {
            int idx = tid + t * 256;
            int r  = idx >> 4;
            int c4 = (idx & 15) << 2;
            float4 kv = *(const float4*)(K + base + (size_t)(j * 64 + r) * D_MOD + c4);
            float4 ck;
            ck.x = __uint_as_float(f2tf32(kv.x));
            ck.y = __uint_as_float(f2tf32(kv.y));
            ck.z = __uint_as_float(f2tf32(kv.z));
            ck.w = __uint_as_float(f2tf32(kv.w));
            *(float4*)(sKh + r * 68 + c4) = ck;
            float4 vv = *(const float4*)(V + base + (size_t)(j * 64 + r) * D_MOD + c4);
            uint2 pv;
            pv.x = packh2(vv.x, vv.y);
            pv.y = packh2(vv.z, vv.w);
            *(uint2*)(sV + r * 72 + c4) = pv;
        }
        __syncthreads();

        float s[8][4];
#pragma unroll
        for (int nt = 0; nt < 8; ++nt)
#pragma unroll
            for (int i = 0; i < 4; ++i) s[nt][i] = 0.f;

        const int qrow = wid * 16 + gq;
#pragma unroll
        for (int c = 0; c < 8; ++c) {
            const int fo = c * 8 + gr;
            const uint32_t* qh = (const uint32_t*)sQh + qrow * 68 + fo;
            uint32_t ah0 = qh[0], ah1 = qh[8 * 68], ah2 = qh[4], ah3 = qh[8 * 68 + 4];
#pragma unroll
            for (int nt = 0; nt < 8; ++nt) {
                const uint32_t* kp = (const uint32_t*)sKh + (nt * 8 + gq) * 68 + fo;
                MMA_TF32(s[nt], ah0, ah1, ah2, ah3, kp[0], kp[4]);
            }
        }

        const bool diag = (j >= 2 * qb);
#pragma unroll
        for (int nt = 0; nt < 8; ++nt) {
            const int colb = j * 64 + nt * 8 + 2 * gr;
#pragma unroll
            for (int e = 0; e < 4; ++e) {
                s[nt][e] *= scale;
                if (diag) {
                    const int col = colb + (e & 1);
                    const int row = (e < 2) ? row0 : row1;
                    if (col > row) s[nt][e] = -1e30f;
                }
            }
        }

        float mt0 = -1e30f, mt1 = -1e30f;
#pragma unroll
        for (int nt = 0; nt < 8; ++nt) {
            mt0 = fmaxf(mt0, fmaxf(s[nt][0], s[nt][1]));
            mt1 = fmaxf(mt1, fmaxf(s[nt][2], s[nt][3]));
        }
        mt0 = fmaxf(mt0, __shfl_xor_sync(0xffffffffu, mt0, 1));
        mt0 = fmaxf(mt0, __shfl_xor_sync(0xffffffffu, mt0, 2));
        mt1 = fmaxf(mt1, __shfl_xor_sync(0xffffffffu, mt1, 1));
        mt1 = fmaxf(mt1, __shfl_xor_sync(0xffffffffu, mt1, 2));
        const float mn0 = fmaxf(m0, mt0);
        const float mn1 = fmaxf(m1, mt1);
        const float alpha0 = __expf(m0 - mn0);
        const float alpha1 = __expf(m1 - mn1);
        m0 = mn0; m1 = mn1;

        float rs0 = 0.f, rs1 = 0.f;
#pragma unroll
        for (int nt = 0; nt < 8; ++nt) {
            s[nt][0] = __expf(s[nt][0] - m0);
            s[nt][1] = __expf(s[nt][1] - m0);
            s[nt][2] = __expf(s[nt][2] - m1);
            s[nt][3] = __expf(s[nt][3] - m1);
            rs0 += s[nt][0] + s[nt][1];
            rs1 += s[nt][2] + s[nt][3];
        }
        rs0 += __shfl_xor_sync(0xffffffffu, rs0, 1);
        rs0 += __shfl_xor_sync(0xffffffffu, rs0, 2);
        rs1 += __shfl_xor_sync(0xffffffffu, rs1, 1);
        rs1 += __shfl_xor_sync(0xffffffffu, rs1, 2);
        l0 = l0 * alpha0 + rs0;
        l1 = l1 * alpha1 + rs1;
#pragma unroll
        for (int nt = 0; nt < 8; ++nt) {
            o[nt][0] *= alpha0; o[nt][1] *= alpha0;
            o[nt][2] *= alpha1; o[nt][3] *= alpha1;
        }

#pragma unroll
        for (int c = 0; c < 4; ++c) {
            uint32_t pa0 = packh2(s[2 * c][0],     s[2 * c][1]);
            uint32_t pa1 = packh2(s[2 * c][2],     s[2 * c][3]);
            uint32_t pa2 = packh2(s[2 * c + 1][0], s[2 * c + 1][1]);
            uint32_t pa3 = packh2(s[2 * c + 1][2], s[2 * c + 1][3]);
            const uint32_t abase = vmat_base + (uint32_t)(c * 16 * 144);
#pragma unroll
            for (int ntp = 0; ntp < 4; ++ntp) {
                uint32_t r0, r1, r2, r3;
                LDMATRIX_X4_TRANS(r0, r1, r2, r3, abase + ntp * 32);
                MMA_F16(o[2 * ntp],     pa0, pa1, pa2, pa3, r0, r1);
                MMA_F16(o[2 * ntp + 1], pa0, pa1, pa2, pa3, r2, r3);
            }
        }
    }

    const float inv0 = 1.0f / l0;
    const float inv1 = 1.0f / l1;
#pragma unroll
    for (int nt = 0; nt < 8; ++nt) {
        const int dv = nt * 8 + 2 * gr;
        float2 w0, w1;
        w0.x = o[nt][0] * inv0; w0.y = o[nt][1] * inv0;
        w1.x = o[nt][2] * inv1; w1.y = o[nt][3] * inv1;
        *(float2*)(O + base + (size_t)row0 * D_MOD + dv) = w0;
        *(float2*)(O + base + (size_t)row1 * D_MOD + dv) = w1;
    }
}

// ---------------------------------------------------------------------------
extern "C" void kernel_launch(void* const* d_in, const int* in_sizes, int n_in,
                              void* d_out, int out_size)
{
    const float* query = (const float*)d_in[0];
    const float* key_  = (const float*)d_in[1];
    const float* value = (const float*)d_in[2];
    const float* Wq = (const float*)d_in[3];
    const float* bq = (const float*)d_in[4];
    const float* Wk = (const float*)d_in[5];
    const float* bk = (const float*)d_in[6];
    const float* Wv = (const float*)d_in[7];
    const float* bv = (const float*)d_in[8];
    const float* Wo = (const float*)d_in[9];
    const float* bo = (const float*)d_in[10];
    // d_in[11] = causal mask (bool) — causality implemented analytically.

    float *Qp, *Kp, *Vp, *Op;
    cudaGetSymbolAddress((void**)&Qp, g_Q);
    cudaGetSymbolAddress((void**)&Kp, g_K);
    cudaGetSymbolAddress((void**)&Vp, g_V);
    cudaGetSymbolAddress((void**)&Op, g_O);

    cudaFuncSetAttribute(sgemm_qkv_kernel,
                         cudaFuncAttributeMaxDynamicSharedMemorySize, GEMM_SMEM_BYTES);
    cudaFuncSetAttribute(sgemm_f16_kernel,
                         cudaFuncAttributeMaxDynamicSharedMemorySize, GEMM_SMEM_BYTES);
    cudaFuncSetAttribute(flash_tc_kernel,
                         cudaFuncAttributeMaxDynamicSharedMemorySize, FLASH_SMEM_BYTES);

    dim3 gqkv(D_MOD / 128, MROWS / 128, 3);  // (8, 64, 3) fused Q/K/V
    sgemm_qkv_kernel<<<gqkv, 256, GEMM_SMEM_BYTES>>>(
        query, key_, value, Wq, Wk, Wv, bq, bk, bv, Qp, Kp, Vp);

    flash_tc_kernel<<<dim3(S_LEN / 128, NH, B_SZ), 256, FLASH_SMEM_BYTES>>>(Qp, Kp, Vp, Op);

    dim3 gg(D_MOD / 128, MROWS / 128);       // (8, 64)
    sgemm_f16_kernel<<<gg, 256, GEMM_SMEM_BYTES>>>(Op, Wo, bo, (float*)d_out);
}

// round 13
// speedup vs baseline: 5.4403x; 1.0749x over previous
#include <cuda_runtime.h>
#include <cuda_fp16.h>
#include <math.h>
#include <stdint.h>

#define B_SZ   4
#define S_LEN  2048
#define D_MOD  1024
#define NH     16
#define DKH    64
#define MROWS  (B_SZ * S_LEN)   // 8192

// fp16 scratch (allocation-free rule: __device__ globals)
__device__ __half g_Aq16[MROWS * D_MOD];
__device__ __half g_Ak16[MROWS * D_MOD];
__device__ __half g_Av16[MROWS * D_MOD];
__device__ __half g_Wq16[D_MOD * D_MOD];
__device__ __half g_Wk16[D_MOD * D_MOD];
__device__ __half g_Wv16[D_MOD * D_MOD];
__device__ __half g_Wo16[D_MOD * D_MOD];
__device__ __half g_Q16[MROWS * D_MOD];
__device__ __half g_K16[MROWS * D_MOD];
__device__ __half g_V16[MROWS * D_MOD];
__device__ __half g_O16[MROWS * D_MOD];

__device__ __forceinline__ uint32_t packh2(float x, float y) {
    __half2 h = __floats2half2_rn(x, y);
    return *(uint32_t*)&h;
}
__device__ __forceinline__ uint32_t smem_u32(const void* p) {
    uint32_t a;
    asm("{ .reg .u64 t; cvta.to.shared.u64 t, %1; cvt.u32.u64 %0, t; }"
        : "=r"(a) : "l"(p));
    return a;
}

#define MMA_F16(ACC, A0, A1, A2, A3, B0, B1)                                  \
    asm volatile(                                                             \
        "mma.sync.aligned.m16n8k16.row.col.f32.f16.f16.f32 "                  \
        "{%0,%1,%2,%3}, {%4,%5,%6,%7}, {%8,%9}, {%0,%1,%2,%3};"               \
        : "+f"((ACC)[0]), "+f"((ACC)[1]), "+f"((ACC)[2]), "+f"((ACC)[3])      \
        : "r"(A0), "r"(A1), "r"(A2), "r"(A3), "r"(B0), "r"(B1))

#define LDMATRIX_X4(R0, R1, R2, R3, ADDR)                                     \
    asm volatile(                                                             \
        "ldmatrix.sync.aligned.m8n8.x4.shared.b16 {%0,%1,%2,%3}, [%4];"       \
        : "=r"(R0), "=r"(R1), "=r"(R2), "=r"(R3) : "r"(ADDR))

#define LDMATRIX_X4_TRANS(R0, R1, R2, R3, ADDR)                               \
    asm volatile(                                                             \
        "ldmatrix.sync.aligned.m8n8.x4.trans.shared.b16 {%0,%1,%2,%3}, [%4];" \
        : "=r"(R0), "=r"(R1), "=r"(R2), "=r"(R3) : "r"(ADDR))

// ---------------------------------------------------------------------------
// One-time fp32 -> fp16 conversion of inputs and weights (bandwidth-bound).
// blockIdx.y selects the tensor; grid-stride over float4 chunks.
// ---------------------------------------------------------------------------
__global__ __launch_bounds__(256) void cvt_kernel(
    const float* __restrict__ q, const float* __restrict__ k,
    const float* __restrict__ v,
    const float* __restrict__ wq, const float* __restrict__ wk,
    const float* __restrict__ wv, const float* __restrict__ wo,
    __half* __restrict__ q16, __half* __restrict__ k16,
    __half* __restrict__ v16,
    __half* __restrict__ wq16, __half* __restrict__ wk16,
    __half* __restrict__ wv16, __half* __restrict__ wo16)
{
    const float* src; __half* dst; int n;
    switch (blockIdx.y) {
        case 0: src = q;  dst = q16;  n = MROWS * D_MOD; break;
        case 1: src = k;  dst = k16;  n = MROWS * D_MOD; break;
        case 2: src = v;  dst = v16;  n = MROWS * D_MOD; break;
        case 3: src = wq; dst = wq16; n = D_MOD * D_MOD; break;
        case 4: src = wk; dst = wk16; n = D_MOD * D_MOD; break;
        case 5: src = wv; dst = wv16; n = D_MOD * D_MOD; break;
        default: src = wo; dst = wo16; n = D_MOD * D_MOD; break;
    }
    const int n4 = n >> 2;
    const int stride = gridDim.x * blockDim.x;
    for (int i = blockIdx.x * blockDim.x + threadIdx.x; i < n4; i += stride) {
        float4 f = ((const float4*)src)[i];
        uint2 h;
        h.x = packh2(f.x, f.y);
        h.y = packh2(f.z, f.w);
        ((uint2*)dst)[i] = h;
    }
}

// ---------------------------------------------------------------------------
// FP16 GEMM body (all-fp16 operands in gmem), double-buffered:
// C = A @ W^T + bias. 128x128 tile, BK=32, 256 threads (8 warps 2m x 4n),
// warp 64x32 via 4x4 m16n8k16. Smem [128][40] halves per matrix per stage
// (BK=32 halves <= 40: no overflow). Output: fp16 (Ch) or fp32 (Cf).
// ---------------------------------------------------------------------------
#define GEMM_SMEM_BYTES (40960)

__device__ __forceinline__ void sgemm16_body(
    const __half* __restrict__ A, const __half* __restrict__ W,
    const float* __restrict__ bias, __half* __restrict__ Ch,
    float* __restrict__ Cf)
{
    const int N = D_MOD, K = D_MOD;
    extern __shared__ char smch[];
    __half* const Ast0 = (__half*)smch;
    __half* const Ast1 = Ast0 + 128 * 40;
    __half* const Wst0 = Ast1 + 128 * 40;
    __half* const Wst1 = Wst0 + 128 * 40;

    const int bm = blockIdx.y * 128;
    const int bn = blockIdx.x * 128;
    const int tid  = threadIdx.x;
    const int wid  = tid >> 5;
    const int lane = tid & 31;
    const int wm = (wid & 1) * 64;
    const int wn = (wid >> 1) * 32;
    const int lr   = tid >> 3;          // staging row 0..31 (per 32-row group)
    const int lc4h = (tid & 7) << 2;    // staging k-col (halves) 0,4,...,28
    const int gq = lane >> 2;
    const int gr = lane & 3;
    const int lm_row = (lane & 7) + ((lane >> 3) & 1) * 8;
    const int lm_k8  = (lane >> 4) << 3;

    float acc[4][4][4];
#pragma unroll
    for (int mt = 0; mt < 4; ++mt)
#pragma unroll
        for (int nt = 0; nt < 4; ++nt)
#pragma unroll
            for (int i = 0; i < 4; ++i) acc[mt][nt][i] = 0.f;

    const __half* Ag = A + (size_t)(bm + lr) * K + lc4h;
    const __half* Wg = W + (size_t)(bn + lr) * K + lc4h;

    uint2 av[4], wv[4];
#pragma unroll
    for (int p = 0; p < 4; ++p) {
        av[p] = *(const uint2*)(Ag + (size_t)(p * 32) * K);
        wv[p] = *(const uint2*)(Wg + (size_t)(p * 32) * K);
    }
#pragma unroll
    for (int p = 0; p < 4; ++p) {
        *(uint2*)(Ast0 + (lr + p * 32) * 40 + lc4h) = av[p];
        *(uint2*)(Wst0 + (lr + p * 32) * 40 + lc4h) = wv[p];
    }
    __syncthreads();

    const int nIter = K >> 5;           // 32
    for (int it = 0; it < nIter; ++it) {
        const bool more = (it + 1 < nIter);
        if (more) {
            const int k1 = (it + 1) << 5;
#pragma unroll
            for (int p = 0; p < 4; ++p) {
                av[p] = *(const uint2*)(Ag + (size_t)(p * 32) * K + k1);
                wv[p] = *(const uint2*)(Wg + (size_t)(p * 32) * K + k1);
            }
        }

        const __half* Acur = (it & 1) ? Ast1 : Ast0;
        const __half* Wcur = (it & 1) ? Wst1 : Wst0;
#pragma unroll
        for (int c = 0; c < 2; ++c) {
            uint32_t a[4][4], b[4][2];
#pragma unroll
            for (int mt = 0; mt < 4; ++mt) {
                const uint32_t addr = smem_u32(
                    Acur + (wm + mt * 16 + lm_row) * 40 + c * 16 + lm_k8);
                LDMATRIX_X4(a[mt][0], a[mt][1], a[mt][2], a[mt][3], addr);
            }
#pragma unroll
            for (int nt = 0; nt < 4; ++nt) {
                const __half* wp = Wcur + (wn + nt * 8 + gq) * 40 + c * 16 + 2 * gr;
                b[nt][0] = *(const uint32_t*)wp;
                b[nt][1] = *(const uint32_t*)(wp + 8);
            }
#pragma unroll
            for (int mt = 0; mt < 4; ++mt)
#pragma unroll
                for (int nt = 0; nt < 4; ++nt)
                    MMA_F16(acc[mt][nt], a[mt][0], a[mt][1], a[mt][2], a[mt][3],
                            b[nt][0], b[nt][1]);
        }

        if (more) {
            __syncthreads();
            __half* Anx = ((it + 1) & 1) ? Ast1 : Ast0;
            __half* Wnx = ((it + 1) & 1) ? Wst1 : Wst0;
#pragma unroll
            for (int p = 0; p < 4; ++p) {
                *(uint2*)(Anx + (lr + p * 32) * 40 + lc4h) = av[p];
                *(uint2*)(Wnx + (lr + p * 32) * 40 + lc4h) = wv[p];
            }
            __syncthreads();
        }
    }

    const int c2 = gr * 2;
#pragma unroll
    for (int mt = 0; mt < 4; ++mt) {
#pragma unroll
        for (int nt = 0; nt < 4; ++nt) {
            const int col = bn + wn + nt * 8 + c2;
            const float b0 = bias[col], b1 = bias[col + 1];
            const size_t row0 = (size_t)(bm + wm + mt * 16 + gq);
            if (Ch) {
                *(uint32_t*)(Ch + row0 * N + col) =
                    packh2(acc[mt][nt][0] + b0, acc[mt][nt][1] + b1);
                *(uint32_t*)(Ch + (row0 + 8) * N + col) =
                    packh2(acc[mt][nt][2] + b0, acc[mt][nt][3] + b1);
            } else {
                float2 v0, v1;
                v0.x = acc[mt][nt][0] + b0; v0.y = acc[mt][nt][1] + b1;
                v1.x = acc[mt][nt][2] + b0; v1.y = acc[mt][nt][3] + b1;
                *(float2*)(Cf + row0 * N + col)       = v0;
                *(float2*)(Cf + (row0 + 8) * N + col) = v1;
            }
        }
    }
}

// Fused Q/K/V projection (fp16 in, fp16 out).
__global__ __launch_bounds__(256, 2) void sgemm_qkv_kernel(
    const __half* __restrict__ Aq, const __half* __restrict__ Ak,
    const __half* __restrict__ Av,
    const __half* __restrict__ Wq, const __half* __restrict__ Wk,
    const __half* __restrict__ Wv,
    const float* __restrict__ bq, const float* __restrict__ bk,
    const float* __restrict__ bv,
    __half* __restrict__ Cq, __half* __restrict__ Ck, __half* __restrict__ Cv)
{
    if (blockIdx.z == 0)      sgemm16_body(Aq, Wq, bq, Cq, nullptr);
    else if (blockIdx.z == 1) sgemm16_body(Ak, Wk, bk, Ck, nullptr);
    else                      sgemm16_body(Av, Wv, bv, Cv, nullptr);
}

// Output projection (fp16 in, fp32 out to d_out).
__global__ __launch_bounds__(256, 2) void sgemm_o_kernel(
    const __half* __restrict__ A, const __half* __restrict__ W,
    const float* __restrict__ bias, float* __restrict__ C)
{
    sgemm16_body(A, W, bias, nullptr, C);
}

// ---------------------------------------------------------------------------
// Flash attention v6b: all-fp16. BM=128, BN=64, DK=64, 8 warps x m16.
// FIXED from v6: sQ/sK stride 40 -> 72 halfwords (rows hold DK=64 halves).
// QK^T: fp16 m16n8k16, A-frags ldmatrix.x4 on sQ[128][72] (banks 4r ->
// conflict-free), B-frags LDS.32 pairs on sK[64][72] (banks 4gq+gr+8c ->
// conflict-free). PV: ldmatrix.x4.trans on sV[64][72] (proven round 9).
// Smem: sQ 18432 + sK 9216 + sV 9216 = 36864 B.
// ---------------------------------------------------------------------------
#define FLASH_SMEM_BYTES (36864)

__global__ __launch_bounds__(256, 2) void flash_tc_kernel(
    const __half* __restrict__ Q, const __half* __restrict__ K,
    const __half* __restrict__ V, __half* __restrict__ O)
{
    extern __shared__ char smraw[];
    __half* sQ = (__half*)smraw;           // [128][72]
    __half* sK = sQ + 128 * 72;            // [64][72]
    __half* sV = sK + 64 * 72;             // [kv=64][72] row-major

    const int qb  = blockIdx.x;
    const int h   = blockIdx.y;
    const int b   = blockIdx.z;
    const int tid = threadIdx.x;
    const int wid = tid >> 5;
    const int lane = tid & 31;
    const int gq = lane >> 2;    // 0..7
    const int gr = lane & 3;     // 0..3
    const int lm_row = (lane & 7) + ((lane >> 3) & 1) * 8;
    const int lm_k8  = (lane >> 4) << 3;
    const size_t base = (size_t)b * S_LEN * D_MOD + (size_t)h * DKH;

    const uint32_t vmat_base = smem_u32(sV) + (uint32_t)(lane & 15) * 144
                             + (uint32_t)((lane >> 4) << 4);

    // ---- Stage Q once: raw fp16 copy into [128][72] ----
#pragma unroll
    for (int t = 0; t < 4; ++t) {
        int idx = tid + t * 256;
        int r    = idx >> 3;               // 0..127
        int colh = (idx & 7) << 3;         // 0,8,...,56
        uint4 v = *(const uint4*)(Q + base + (size_t)(qb * 128 + r) * D_MOD + colh);
        *(uint4*)(sQ + r * 72 + colh) = v;
    }

    float o[8][4];
#pragma unroll
    for (int nt = 0; nt < 8; ++nt)
#pragma unroll
        for (int i = 0; i < 4; ++i) o[nt][i] = 0.f;
    float m0 = -1e30f, m1 = -1e30f, l0 = 0.f, l1 = 0.f;

    const int row0 = qb * 128 + wid * 16 + gq;
    const int row1 = row0 + 8;
    const float scale = 0.125f;            // 1/sqrt(64)
    const int jmax = 2 * qb + 1;

    for (int j = 0; j <= jmax; ++j) {
        __syncthreads();   // prior-iter readers done (orders Q staging on j=0)
        // ---- Stage K -> [64][72], V -> [64][72], raw fp16 copies ----
#pragma unroll
        for (int t = 0; t < 2; ++t) {
            int idx = tid + t * 256;
            int r    = idx >> 3;           // 0..63
            int colh = (idx & 7) << 3;
            uint4 kv = *(const uint4*)(K + base + (size_t)(j * 64 + r) * D_MOD + colh);
            *(uint4*)(sK + r * 72 + colh) = kv;
            uint4 vv = *(const uint4*)(V + base + (size_t)(j * 64 + r) * D_MOD + colh);
            *(uint4*)(sV + r * 72 + colh) = vv;
        }
        __syncthreads();

        // ---- S = Q K^T : fp16 m16n8k16, 4 k-chunks x 8 n-tiles ----
        float s[8][4];
#pragma unroll
        for (int nt = 0; nt < 8; ++nt)
#pragma unroll
            for (int i = 0; i < 4; ++i) s[nt][i] = 0.f;

        const int qrowb = wid * 16;
#pragma unroll
        for (int c = 0; c < 4; ++c) {
            uint32_t a0, a1, a2, a3;
            const uint32_t addr = smem_u32(
                sQ + (qrowb + lm_row) * 72 + c * 16 + lm_k8);
            LDMATRIX_X4(a0, a1, a2, a3, addr);
#pragma unroll
            for (int nt = 0; nt < 8; ++nt) {
                const __half* kp = sK + (nt * 8 + gq) * 72 + c * 16 + 2 * gr;
                MMA_F16(s[nt], a0, a1, a2, a3,
                        *(const uint32_t*)kp, *(const uint32_t*)(kp + 8));
            }
        }

        // ---- scale + causal mask ----
        const bool diag = (j >= 2 * qb);
#pragma unroll
        for (int nt = 0; nt < 8; ++nt) {
            const int colb = j * 64 + nt * 8 + 2 * gr;
#pragma unroll
            for (int e = 0; e < 4; ++e) {
                s[nt][e] *= scale;
                if (diag) {
                    const int col = colb + (e & 1);
                    const int row = (e < 2) ? row0 : row1;
                    if (col > row) s[nt][e] = -1e30f;
                }
            }
        }

        // ---- online softmax ----
        float mt0 = -1e30f, mt1 = -1e30f;
#pragma unroll
        for (int nt = 0; nt < 8; ++nt) {
            mt0 = fmaxf(mt0, fmaxf(s[nt][0], s[nt][1]));
            mt1 = fmaxf(mt1, fmaxf(s[nt][2], s[nt][3]));
        }
        mt0 = fmaxf(mt0, __shfl_xor_sync(0xffffffffu, mt0, 1));
        mt0 = fmaxf(mt0, __shfl_xor_sync(0xffffffffu, mt0, 2));
        mt1 = fmaxf(mt1, __shfl_xor_sync(0xffffffffu, mt1, 1));
        mt1 = fmaxf(mt1, __shfl_xor_sync(0xffffffffu, mt1, 2));
        const float mn0 = fmaxf(m0, mt0);
        const float mn1 = fmaxf(m1, mt1);
        const float alpha0 = __expf(m0 - mn0);
        const float alpha1 = __expf(m1 - mn1);
        m0 = mn0; m1 = mn1;

        float rs0 = 0.f, rs1 = 0.f;
#pragma unroll
        for (int nt = 0; nt < 8; ++nt) {
            s[nt][0] = __expf(s[nt][0] - m0);
            s[nt][1] = __expf(s[nt][1] - m0);
            s[nt][2] = __expf(s[nt][2] - m1);
            s[nt][3] = __expf(s[nt][3] - m1);
            rs0 += s[nt][0] + s[nt][1];
            rs1 += s[nt][2] + s[nt][3];
        }
        rs0 += __shfl_xor_sync(0xffffffffu, rs0, 1);
        rs0 += __shfl_xor_sync(0xffffffffu, rs0, 2);
        rs1 += __shfl_xor_sync(0xffffffffu, rs1, 1);
        rs1 += __shfl_xor_sync(0xffffffffu, rs1, 2);
        l0 = l0 * alpha0 + rs0;
        l1 = l1 * alpha1 + rs1;
#pragma unroll
        for (int nt = 0; nt < 8; ++nt) {
            o[nt][0] *= alpha0; o[nt][1] *= alpha0;
            o[nt][2] *= alpha1; o[nt][3] *= alpha1;
        }

        // ---- O += P V : fp16 m16n8k16, B-frags via ldmatrix.x4.trans ----
#pragma unroll
        for (int c = 0; c < 4; ++c) {
            uint32_t pa0 = packh2(s[2 * c][0],     s[2 * c][1]);
            uint32_t pa1 = packh2(s[2 * c][2],     s[2 * c][3]);
            uint32_t pa2 = packh2(s[2 * c + 1][0], s[2 * c + 1][1]);
            uint32_t pa3 = packh2(s[2 * c + 1][2], s[2 * c + 1][3]);
            const uint32_t abase = vmat_base + (uint32_t)(c * 16 * 144);
#pragma unroll
            for (int ntp = 0; ntp < 4; ++ntp) {
                uint32_t r0, r1, r2, r3;
                LDMATRIX_X4_TRANS(r0, r1, r2, r3, abase + ntp * 32);
                MMA_F16(o[2 * ntp],     pa0, pa1, pa2, pa3, r0, r1);
                MMA_F16(o[2 * ntp + 1], pa0, pa1, pa2, pa3, r2, r3);
            }
        }
    }

    // ---- epilogue: fp16 output ----
    const float inv0 = 1.0f / l0;
    const float inv1 = 1.0f / l1;
#pragma unroll
    for (int nt = 0; nt < 8; ++nt) {
        const int dv = nt * 8 + 2 * gr;
        *(uint32_t*)(O + base + (size_t)row0 * D_MOD + dv) =
            packh2(o[nt][0] * inv0, o[nt][1] * inv0);
        *(uint32_t*)(O + base + (size_t)row1 * D_MOD + dv) =
            packh2(o[nt][2] * inv1, o[nt][3] * inv1);
    }
}

// ---------------------------------------------------------------------------
extern "C" void kernel_launch(void* const* d_in, const int* in_sizes, int n_in,
                              void* d_out, int out_size)
{
    const float* query = (const float*)d_in[0];
    const float* key_  = (const float*)d_in[1];
    const float* value = (const float*)d_in[2];
    const float* Wq = (const float*)d_in[3];
    const float* bq = (const float*)d_in[4];
    const float* Wk = (const float*)d_in[5];
    const float* bk = (const float*)d_in[6];
    const float* Wv = (const float*)d_in[7];
    const float* bv = (const float*)d_in[8];
    const float* Wo = (const float*)d_in[9];
    const float* bo = (const float*)d_in[10];
    // d_in[11] = causal mask (bool) — causality implemented analytically.

    __half *Aq16, *Ak16, *Av16, *Wq16, *Wk16, *Wv16, *Wo16;
    __half *Q16, *K16, *V16, *O16;
    cudaGetSymbolAddress((void**)&Aq16, g_Aq16);
    cudaGetSymbolAddress((void**)&Ak16, g_Ak16);
    cudaGetSymbolAddress((void**)&Av16, g_Av16);
    cudaGetSymbolAddress((void**)&Wq16, g_Wq16);
    cudaGetSymbolAddress((void**)&Wk16, g_Wk16);
    cudaGetSymbolAddress((void**)&Wv16, g_Wv16);
    cudaGetSymbolAddress((void**)&Wo16, g_Wo16);
    cudaGetSymbolAddress((void**)&Q16, g_Q16);
    cudaGetSymbolAddress((void**)&K16, g_K16);
    cudaGetSymbolAddress((void**)&V16, g_V16);
    cudaGetSymbolAddress((void**)&O16, g_O16);

    cudaFuncSetAttribute(sgemm_qkv_kernel,
                         cudaFuncAttributeMaxDynamicSharedMemorySize, GEMM_SMEM_BYTES);
    cudaFuncSetAttribute(sgemm_o_kernel,
                         cudaFuncAttributeMaxDynamicSharedMemorySize, GEMM_SMEM_BYTES);
    cudaFuncSetAttribute(flash_tc_kernel,
                         cudaFuncAttributeMaxDynamicSharedMemorySize, FLASH_SMEM_BYTES);

    // 1. Convert inputs + weights to fp16 (one pass, bandwidth-bound).
    cvt_kernel<<<dim3(2048, 7), 256>>>(
        query, key_, value, Wq, Wk, Wv, Wo,
        Aq16, Ak16, Av16, Wq16, Wk16, Wv16, Wo16);

    // 2. Fused Q/K/V projections (fp16 -> fp16 scratch).
    dim3 gqkv(D_MOD / 128, MROWS / 128, 3);
    sgemm_qkv_kernel<<<gqkv, 256, GEMM_SMEM_BYTES>>>(
        Aq16, Ak16, Av16, Wq16, Wk16, Wv16, bq, bk, bv, Q16, K16, V16);

    // 3. Flash attention (fp16 -> fp16).
    flash_tc_kernel<<<dim3(S_LEN / 128, NH, B_SZ), 256, FLASH_SMEM_BYTES>>>(
        Q16, K16, V16, O16);

    // 4. Output projection (fp16 -> fp32 d_out).
    dim3 gg(D_MOD / 128, MROWS / 128);
    sgemm_o_kernel<<<gg, 256, GEMM_SMEM_BYTES>>>(O16, Wo16, bo, (float*)d_out);
}

// round 14
// speedup vs baseline: 6.3738x; 1.1716x over previous
#include <cuda_runtime.h>
#include <cuda_fp16.h>
#include <math.h>
#include <stdint.h>

#define B_SZ   4
#define S_LEN  2048
#define D_MOD  1024
#define NH     16
#define DKH    64
#define MROWS  (B_SZ * S_LEN)   // 8192

// fp16 scratch (allocation-free rule: __device__ globals)
__device__ __half g_Aq16[MROWS * D_MOD];
__device__ __half g_Ak16[MROWS * D_MOD];
__device__ __half g_Av16[MROWS * D_MOD];
__device__ __half g_Wq16[D_MOD * D_MOD];
__device__ __half g_Wk16[D_MOD * D_MOD];
__device__ __half g_Wv16[D_MOD * D_MOD];
__device__ __half g_Wo16[D_MOD * D_MOD];
__device__ __half g_Q16[MROWS * D_MOD];
__device__ __half g_K16[MROWS * D_MOD];
__device__ __half g_V16[MROWS * D_MOD];
__device__ __half g_O16[MROWS * D_MOD];

__device__ __forceinline__ uint32_t packh2(float x, float y) {
    __half2 h = __floats2half2_rn(x, y);
    return *(uint32_t*)&h;
}
__device__ __forceinline__ uint32_t smem_u32(const void* p) {
    uint32_t a;
    asm("{ .reg .u64 t; cvta.to.shared.u64 t, %1; cvt.u32.u64 %0, t; }"
        : "=r"(a) : "l"(p));
    return a;
}

#define MMA_F16(ACC, A0, A1, A2, A3, B0, B1)                                  \
    asm volatile(                                                             \
        "mma.sync.aligned.m16n8k16.row.col.f32.f16.f16.f32 "                  \
        "{%0,%1,%2,%3}, {%4,%5,%6,%7}, {%8,%9}, {%0,%1,%2,%3};"               \
        : "+f"((ACC)[0]), "+f"((ACC)[1]), "+f"((ACC)[2]), "+f"((ACC)[3])      \
        : "r"(A0), "r"(A1), "r"(A2), "r"(A3), "r"(B0), "r"(B1))

#define LDMATRIX_X4(R0, R1, R2, R3, ADDR)                                     \
    asm volatile(                                                             \
        "ldmatrix.sync.aligned.m8n8.x4.shared.b16 {%0,%1,%2,%3}, [%4];"       \
        : "=r"(R0), "=r"(R1), "=r"(R2), "=r"(R3) : "r"(ADDR))

#define LDMATRIX_X4_TRANS(R0, R1, R2, R3, ADDR)                               \
    asm volatile(                                                             \
        "ldmatrix.sync.aligned.m8n8.x4.trans.shared.b16 {%0,%1,%2,%3}, [%4];" \
        : "=r"(R0), "=r"(R1), "=r"(R2), "=r"(R3) : "r"(ADDR))

#define CP_ASYNC_CG16(DST, SRC)                                               \
    asm volatile("cp.async.cg.shared.global [%0], [%1], 16;"                  \
                 :: "r"(DST), "l"(SRC))
#define CP_COMMIT()  asm volatile("cp.async.commit_group;" ::: "memory")
#define CP_WAIT_1()  asm volatile("cp.async.wait_group 1;" ::: "memory")

// ---------------------------------------------------------------------------
// One-time fp32 -> fp16 conversion of inputs and weights (bandwidth-bound).
// ---------------------------------------------------------------------------
__global__ __launch_bounds__(256) void cvt_kernel(
    const float* __restrict__ q, const float* __restrict__ k,
    const float* __restrict__ v,
    const float* __restrict__ wq, const float* __restrict__ wk,
    const float* __restrict__ wv, const float* __restrict__ wo,
    __half* __restrict__ q16, __half* __restrict__ k16,
    __half* __restrict__ v16,
    __half* __restrict__ wq16, __half* __restrict__ wk16,
    __half* __restrict__ wv16, __half* __restrict__ wo16)
{
    const float* src; __half* dst; int n;
    switch (blockIdx.y) {
        case 0: src = q;  dst = q16;  n = MROWS * D_MOD; break;
        case 1: src = k;  dst = k16;  n = MROWS * D_MOD; break;
        case 2: src = v;  dst = v16;  n = MROWS * D_MOD; break;
        case 3: src = wq; dst = wq16; n = D_MOD * D_MOD; break;
        case 4: src = wk; dst = wk16; n = D_MOD * D_MOD; break;
        case 5: src = wv; dst = wv16; n = D_MOD * D_MOD; break;
        default: src = wo; dst = wo16; n = D_MOD * D_MOD; break;
    }
    const int n4 = n >> 2;
    const int stride = gridDim.x * blockDim.x;
    for (int i = blockIdx.x * blockDim.x + threadIdx.x; i < n4; i += stride) {
        float4 f = ((const float4*)src)[i];
        uint2 h;
        h.x = packh2(f.x, f.y);
        h.y = packh2(f.z, f.w);
        ((uint2*)dst)[i] = h;
    }
}

// ---------------------------------------------------------------------------
// FP16 GEMM body, cp.async 3-stage pipeline: C = A @ W^T + bias (fp32 acc).
// 128x128 tile, BK=32, 256 threads (8 warps 2m x 4n), warp 64x32 m16n8k16.
// Stage s (s=0..2): A fp16[128][40] @ s*20480, W fp16[128][40] @ s*20480+10240.
// Staging: cp.async.cg 16B, each thread 2 chunks/matrix (rows g_row, g_row+64).
// One __syncthreads per iter; wait_group 1 keeps one stage in flight.
// ---------------------------------------------------------------------------
#define GEMM_SMEM_BYTES (61440)

__device__ __forceinline__ void sgemm16_body(
    const __half* __restrict__ A, const __half* __restrict__ W,
    const float* __restrict__ bias, __half* __restrict__ Ch,
    float* __restrict__ Cf)
{
    const int N = D_MOD, K = D_MOD;
    extern __shared__ char smch[];
    const uint32_t smem_base = smem_u32(smch);

    const int bm = blockIdx.y * 128;
    const int bn = blockIdx.x * 128;
    const int tid  = threadIdx.x;
    const int wid  = tid >> 5;
    const int lane = tid & 31;
    const int wm = (wid & 1) * 64;
    const int wn = (wid >> 1) * 32;
    const int gq = lane >> 2;
    const int gr = lane & 3;
    const int lm_row = (lane & 7) + ((lane >> 3) & 1) * 8;
    const int lm_k8  = (lane >> 4) << 3;

    // cp.async per-thread coordinates: row g_row & g_row+64, 16B chunk g_ch
    const int g_row = tid >> 2;          // 0..63
    const int g_ch  = (tid & 3) << 3;    // halves: 0,8,16,24
    const __half* Agp = A + (size_t)(bm + g_row) * K + g_ch;
    const __half* Wgp = W + (size_t)(bn + g_row) * K + g_ch;
    const uint32_t sA_t = smem_base + (uint32_t)(g_row * 80 + g_ch * 2);
    const uint32_t sW_t = sA_t + 10240;

    auto issue_stage = [&](int s, int k0) {
        const uint32_t so = (uint32_t)(s * 20480);
        CP_ASYNC_CG16(sA_t + so,        Agp + k0);
        CP_ASYNC_CG16(sA_t + so + 5120, Agp + (size_t)64 * K + k0);  // 64 rows * 80 B
        CP_ASYNC_CG16(sW_t + so,        Wgp + k0);
        CP_ASYNC_CG16(sW_t + so + 5120, Wgp + (size_t)64 * K + k0);
        CP_COMMIT();
    };

    float acc[4][4][4];
#pragma unroll
    for (int mt = 0; mt < 4; ++mt)
#pragma unroll
        for (int nt = 0; nt < 4; ++nt)
#pragma unroll
            for (int i = 0; i < 4; ++i) acc[mt][nt][i] = 0.f;

    issue_stage(0, 0);
    issue_stage(1, 32);

    const int nIter = K >> 5;            // 32
    for (int it = 0; it < nIter; ++it) {
        CP_WAIT_1();                     // groups <= it complete -> stage it%3 ready
        __syncthreads();                 // all threads' groups visible; gates reuse

        const int s = it % 3;
        const __half* Acur = (const __half*)(smch + s * 20480);
        const __half* Wcur = Acur + 5120;

#pragma unroll
        for (int c = 0; c < 2; ++c) {
            uint32_t a[4][4], b[4][2];
#pragma unroll
            for (int mt = 0; mt < 4; ++mt) {
                const uint32_t addr = smem_u32(
                    Acur + (wm + mt * 16 + lm_row) * 40 + c * 16 + lm_k8);
                LDMATRIX_X4(a[mt][0], a[mt][1], a[mt][2], a[mt][3], addr);
            }
#pragma unroll
            for (int nt = 0; nt < 4; ++nt) {
                const __half* wp = Wcur + (wn + nt * 8 + gq) * 40 + c * 16 + 2 * gr;
                b[nt][0] = *(const uint32_t*)wp;
                b[nt][1] = *(const uint32_t*)(wp + 8);
            }
#pragma unroll
            for (int mt = 0; mt < 4; ++mt)
#pragma unroll
                for (int nt = 0; nt < 4; ++nt)
                    MMA_F16(acc[mt][nt], a[mt][0], a[mt][1], a[mt][2], a[mt][3],
                            b[nt][0], b[nt][1]);
        }

        if (it + 2 < nIter) issue_stage((it + 2) % 3, (it + 2) * 32);
        else                CP_COMMIT();   // uniform group accounting
    }

    const int c2 = gr * 2;
#pragma unroll
    for (int mt = 0; mt < 4; ++mt) {
#pragma unroll
        for (int nt = 0; nt < 4; ++nt) {
            const int col = bn + wn + nt * 8 + c2;
            const float b0 = bias[col], b1 = bias[col + 1];
            const size_t row0 = (size_t)(bm + wm + mt * 16 + gq);
            if (Ch) {
                *(uint32_t*)(Ch + row0 * N + col) =
                    packh2(acc[mt][nt][0] + b0, acc[mt][nt][1] + b1);
                *(uint32_t*)(Ch + (row0 + 8) * N + col) =
                    packh2(acc[mt][nt][2] + b0, acc[mt][nt][3] + b1);
            } else {
                float2 v0, v1;
                v0.x = acc[mt][nt][0] + b0; v0.y = acc[mt][nt][1] + b1;
                v1.x = acc[mt][nt][2] + b0; v1.y = acc[mt][nt][3] + b1;
                *(float2*)(Cf + row0 * N + col)       = v0;
                *(float2*)(Cf + (row0 + 8) * N + col) = v1;
            }
        }
    }
}

// Fused Q/K/V projection (fp16 in, fp16 out).
__global__ __launch_bounds__(256, 2) void sgemm_qkv_kernel(
    const __half* __restrict__ Aq, const __half* __restrict__ Ak,
    const __half* __restrict__ Av,
    const __half* __restrict__ Wq, const __half* __restrict__ Wk,
    const __half* __restrict__ Wv,
    const float* __restrict__ bq, const float* __restrict__ bk,
    const float* __restrict__ bv,
    __half* __restrict__ Cq, __half* __restrict__ Ck, __half* __restrict__ Cv)
{
    if (blockIdx.z == 0)      sgemm16_body(Aq, Wq, bq, Cq, nullptr);
    else if (blockIdx.z == 1) sgemm16_body(Ak, Wk, bk, Ck, nullptr);
    else                      sgemm16_body(Av, Wv, bv, Cv, nullptr);
}

// Output projection (fp16 in, fp32 out to d_out).
__global__ __launch_bounds__(256, 2) void sgemm_o_kernel(
    const __half* __restrict__ A, const __half* __restrict__ W,
    const float* __restrict__ bias, float* __restrict__ C)
{
    sgemm16_body(A, W, bias, nullptr, C);
}

// ---------------------------------------------------------------------------
// Flash attention v6b (unchanged from round 13, proven).
// Smem: sQ[128][72] + sK[64][72] + sV[64][72] fp16 = 36864 B.
// ---------------------------------------------------------------------------
#define FLASH_SMEM_BYTES (36864)

__global__ __launch_bounds__(256, 2) void flash_tc_kernel(
    const __half* __restrict__ Q, const __half* __restrict__ K,
    const __half* __restrict__ V, __half* __restrict__ O)
{
    extern __shared__ char smraw[];
    __half* sQ = (__half*)smraw;           // [128][72]
    __half* sK = sQ + 128 * 72;            // [64][72]
    __half* sV = sK + 64 * 72;             // [kv=64][72] row-major

    const int qb  = blockIdx.x;
    const int h   = blockIdx.y;
    const int b   = blockIdx.z;
    const int tid = threadIdx.x;
    const int wid = tid >> 5;
    const int lane = tid & 31;
    const int gq = lane >> 2;    // 0..7
    const int gr = lane & 3;     // 0..3
    const int lm_row = (lane & 7) + ((lane >> 3) & 1) * 8;
    const int lm_k8  = (lane >> 4) << 3;
    const size_t base = (size_t)b * S_LEN * D_MOD + (size_t)h * DKH;

    const uint32_t vmat_base = smem_u32(sV) + (uint32_t)(lane & 15) * 144
                             + (uint32_t)((lane >> 4) << 4);

#pragma unroll
    for (int t = 0; t < 4; ++t) {
        int idx = tid + t * 256;
        int r    = idx >> 3;               // 0..127
        int colh = (idx & 7) << 3;         // 0,8,...,56
        uint4 v = *(const uint4*)(Q + base + (size_t)(qb * 128 + r) * D_MOD + colh);
        *(uint4*)(sQ + r * 72 + colh) = v;
    }

    float o[8][4];
#pragma unroll
    for (int nt = 0; nt < 8; ++nt)
#pragma unroll
        for (int i = 0; i < 4; ++i) o[nt][i] = 0.f;
    float m0 = -1e30f, m1 = -1e30f, l0 = 0.f, l1 = 0.f;

    const int row0 = qb * 128 + wid * 16 + gq;
    const int row1 = row0 + 8;
    const float scale = 0.125f;            // 1/sqrt(64)
    const int jmax = 2 * qb + 1;

    for (int j = 0; j <= jmax; ++j) {
        __syncthreads();
#pragma unroll
        for (int t = 0; t < 2; ++t) {
            int idx = tid + t * 256;
            int r    = idx >> 3;           // 0..63
            int colh = (idx & 7) << 3;
            uint4 kv = *(const uint4*)(K + base + (size_t)(j * 64 + r) * D_MOD + colh);
            *(uint4*)(sK + r * 72 + colh) = kv;
            uint4 vv = *(const uint4*)(V + base + (size_t)(j * 64 + r) * D_MOD + colh);
            *(uint4*)(sV + r * 72 + colh) = vv;
        }
        __syncthreads();

        float s[8][4];
#pragma unroll
        for (int nt = 0; nt < 8; ++nt)
#pragma unroll
            for (int i = 0; i < 4; ++i) s[nt][i] = 0.f;

        const int qrowb = wid * 16;
#pragma unroll
        for (int c = 0; c < 4; ++c) {
            uint32_t a0, a1, a2, a3;
            const uint32_t addr = smem_u32(
                sQ + (qrowb + lm_row) * 72 + c * 16 + lm_k8);
            LDMATRIX_X4(a0, a1, a2, a3, addr);
#pragma unroll
            for (int nt = 0; nt < 8; ++nt) {
                const __half* kp = sK + (nt * 8 + gq) * 72 + c * 16 + 2 * gr;
                MMA_F16(s[nt], a0, a1, a2, a3,
                        *(const uint32_t*)kp, *(const uint32_t*)(kp + 8));
            }
        }

        const bool diag = (j >= 2 * qb);
#pragma unroll
        for (int nt = 0; nt < 8; ++nt) {
            const int colb = j * 64 + nt * 8 + 2 * gr;
#pragma unroll
            for (int e = 0; e < 4; ++e) {
                s[nt][e] *= scale;
                if (diag) {
                    const int col = colb + (e & 1);
                    const int row = (e < 2) ? row0 : row1;
                    if (col > row) s[nt][e] = -1e30f;
                }
            }
        }

        float mt0 = -1e30f, mt1 = -1e30f;
#pragma unroll
        for (int nt = 0; nt < 8; ++nt) {
            mt0 = fmaxf(mt0, fmaxf(s[nt][0], s[nt][1]));
            mt1 = fmaxf(mt1, fmaxf(s[nt][2], s[nt][3]));
        }
        mt0 = fmaxf(mt0, __shfl_xor_sync(0xffffffffu, mt0, 1));
        mt0 = fmaxf(mt0, __shfl_xor_sync(0xffffffffu, mt0, 2));
        mt1 = fmaxf(mt1, __shfl_xor_sync(0xffffffffu, mt1, 1));
        mt1 = fmaxf(mt1, __shfl_xor_sync(0xffffffffu, mt1, 2));
        const float mn0 = fmaxf(m0, mt0);
        const float mn1 = fmaxf(m1, mt1);
        const float alpha0 = __expf(m0 - mn0);
        const float alpha1 = __expf(m1 - mn1);
        m0 = mn0; m1 = mn1;

        float rs0 = 0.f, rs1 = 0.f;
#pragma unroll
        for (int nt = 0; nt < 8; ++nt) {
            s[nt][0] = __expf(s[nt][0] - m0);
            s[nt][1] = __expf(s[nt][1] - m0);
            s[nt][2] = __expf(s[nt][2] - m1);
            s[nt][3] = __expf(s[nt][3] - m1);
            rs0 += s[nt][0] + s[nt][1];
            rs1 += s[nt][2] + s[nt][3];
        }
        rs0 += __shfl_xor_sync(0xffffffffu, rs0, 1);
        rs0 += __shfl_xor_sync(0xffffffffu, rs0, 2);
        rs1 += __shfl_xor_sync(0xffffffffu, rs1, 1);
        rs1 += __shfl_xor_sync(0xffffffffu, rs1, 2);
        l0 = l0 * alpha0 + rs0;
        l1 = l1 * alpha1 + rs1;
#pragma unroll
        for (int nt = 0; nt < 8; ++nt) {
            o[nt][0] *= alpha0; o[nt][1] *= alpha0;
            o[nt][2] *= alpha1; o[nt][3] *= alpha1;
        }

#pragma unroll
        for (int c = 0; c < 4; ++c) {
            uint32_t pa0 = packh2(s[2 * c][0],     s[2 * c][1]);
            uint32_t pa1 = packh2(s[2 * c][2],     s[2 * c][3]);
            uint32_t pa2 = packh2(s[2 * c + 1][0], s[2 * c + 1][1]);
            uint32_t pa3 = packh2(s[2 * c + 1][2], s[2 * c + 1][3]);
            const uint32_t abase = vmat_base + (uint32_t)(c * 16 * 144);
#pragma unroll
            for (int ntp = 0; ntp < 4; ++ntp) {
                uint32_t r0, r1, r2, r3;
                LDMATRIX_X4_TRANS(r0, r1, r2, r3, abase + ntp * 32);
                MMA_F16(o[2 * ntp],     pa0, pa1, pa2, pa3, r0, r1);
                MMA_F16(o[2 * ntp + 1], pa0, pa1, pa2, pa3, r2, r3);
            }
        }
    }

    const float inv0 = 1.0f / l0;
    const float inv1 = 1.0f / l1;
#pragma unroll
    for (int nt = 0; nt < 8; ++nt) {
        const int dv = nt * 8 + 2 * gr;
        *(uint32_t*)(O + base + (size_t)row0 * D_MOD + dv) =
            packh2(o[nt][0] * inv0, o[nt][1] * inv0);
        *(uint32_t*)(O + base + (size_t)row1 * D_MOD + dv) =
            packh2(o[nt][2] * inv1, o[nt][3] * inv1);
    }
}

// ---------------------------------------------------------------------------
extern "C" void kernel_launch(void* const* d_in, const int* in_sizes, int n_in,
                              void* d_out, int out_size)
{
    const float* query = (const float*)d_in[0];
    const float* key_  = (const float*)d_in[1];
    const float* value = (const float*)d_in[2];
    const float* Wq = (const float*)d_in[3];
    const float* bq = (const float*)d_in[4];
    const float* Wk = (const float*)d_in[5];
    const float* bk = (const float*)d_in[6];
    const float* Wv = (const float*)d_in[7];
    const float* bv = (const float*)d_in[8];
    const float* Wo = (const float*)d_in[9];
    const float* bo = (const float*)d_in[10];
    // d_in[11] = causal mask (bool) — causality implemented analytically.

    __half *Aq16, *Ak16, *Av16, *Wq16, *Wk16, *Wv16, *Wo16;
    __half *Q16, *K16, *V16, *O16;
    cudaGetSymbolAddress((void**)&Aq16, g_Aq16);
    cudaGetSymbolAddress((void**)&Ak16, g_Ak16);
    cudaGetSymbolAddress((void**)&Av16, g_Av16);
    cudaGetSymbolAddress((void**)&Wq16, g_Wq16);
    cudaGetSymbolAddress((void**)&Wk16, g_Wk16);
    cudaGetSymbolAddress((void**)&Wv16, g_Wv16);
    cudaGetSymbolAddress((void**)&Wo16, g_Wo16);
    cudaGetSymbolAddress((void**)&Q16, g_Q16);
    cudaGetSymbolAddress((void**)&K16, g_K16);
    cudaGetSymbolAddress((void**)&V16, g_V16);
    cudaGetSymbolAddress((void**)&O16, g_O16);

    cudaFuncSetAttribute(sgemm_qkv_kernel,
                         cudaFuncAttributeMaxDynamicSharedMemorySize, GEMM_SMEM_BYTES);
    cudaFuncSetAttribute(sgemm_o_kernel,
                         cudaFuncAttributeMaxDynamicSharedMemorySize, GEMM_SMEM_BYTES);
    cudaFuncSetAttribute(flash_tc_kernel,
                         cudaFuncAttributeMaxDynamicSharedMemorySize, FLASH_SMEM_BYTES);

    // 1. Convert inputs + weights to fp16 (one pass, bandwidth-bound).
    cvt_kernel<<<dim3(2048, 7), 256>>>(
        query, key_, value, Wq, Wk, Wv, Wo,
        Aq16, Ak16, Av16, Wq16, Wk16, Wv16, Wo16);

    // 2. Fused Q/K/V projections (fp16 -> fp16 scratch).
    dim3 gqkv(D_MOD / 128, MROWS / 128, 3);
    sgemm_qkv_kernel<<<gqkv, 256, GEMM_SMEM_BYTES>>>(
        Aq16, Ak16, Av16, Wq16, Wk16, Wv16, bq, bk, bv, Q16, K16, V16);

    // 3. Flash attention (fp16 -> fp16).
    flash_tc_kernel<<<dim3(S_LEN / 128, NH, B_SZ), 256, FLASH_SMEM_BYTES>>>(
        Q16, K16, V16, O16);

    // 4. Output projection (fp16 -> fp32 d_out).
    dim3 gg(D_MOD / 128, MROWS / 128);
    sgemm_o_kernel<<<gg, 256, GEMM_SMEM_BYTES>>>(O16, Wo16, bo, (float*)d_out);
}

// round 15
// speedup vs baseline: 6.5791x; 1.0322x over previous
#include <cuda_runtime.h>
#include <cuda_fp16.h>
#include <math.h>
#include <stdint.h>

#define B_SZ   4
#define S_LEN  2048
#define D_MOD  1024
#define NH     16
#define DKH    64
#define MROWS  (B_SZ * S_LEN)   // 8192

// fp16 scratch (allocation-free rule: __device__ globals)
__device__ __half g_Aq16[MROWS * D_MOD];
__device__ __half g_Ak16[MROWS * D_MOD];
__device__ __half g_Av16[MROWS * D_MOD];
__device__ __half g_Wq16[D_MOD * D_MOD];
__device__ __half g_Wk16[D_MOD * D_MOD];
__device__ __half g_Wv16[D_MOD * D_MOD];
__device__ __half g_Wo16[D_MOD * D_MOD];
__device__ __half g_Q16[MROWS * D_MOD];
__device__ __half g_K16[MROWS * D_MOD];
__device__ __half g_V16[MROWS * D_MOD];
__device__ __half g_O16[MROWS * D_MOD];

__device__ __forceinline__ uint32_t packh2(float x, float y) {
    __half2 h = __floats2half2_rn(x, y);
    return *(uint32_t*)&h;
}
__device__ __forceinline__ uint32_t smem_u32(const void* p) {
    uint32_t a;
    asm("{ .reg .u64 t; cvta.to.shared.u64 t, %1; cvt.u32.u64 %0, t; }"
        : "=r"(a) : "l"(p));
    return a;
}

#define MMA_F16(ACC, A0, A1, A2, A3, B0, B1)                                  \
    asm volatile(                                                             \
        "mma.sync.aligned.m16n8k16.row.col.f32.f16.f16.f32 "                  \
        "{%0,%1,%2,%3}, {%4,%5,%6,%7}, {%8,%9}, {%0,%1,%2,%3};"               \
        : "+f"((ACC)[0]), "+f"((ACC)[1]), "+f"((ACC)[2]), "+f"((ACC)[3])      \
        : "r"(A0), "r"(A1), "r"(A2), "r"(A3), "r"(B0), "r"(B1))

#define LDMATRIX_X4(R0, R1, R2, R3, ADDR)                                     \
    asm volatile(                                                             \
        "ldmatrix.sync.aligned.m8n8.x4.shared.b16 {%0,%1,%2,%3}, [%4];"       \
        : "=r"(R0), "=r"(R1), "=r"(R2), "=r"(R3) : "r"(ADDR))

#define LDMATRIX_X4_TRANS(R0, R1, R2, R3, ADDR)                               \
    asm volatile(                                                             \
        "ldmatrix.sync.aligned.m8n8.x4.trans.shared.b16 {%0,%1,%2,%3}, [%4];" \
        : "=r"(R0), "=r"(R1), "=r"(R2), "=r"(R3) : "r"(ADDR))

#define CP_ASYNC_CG16(DST, SRC)                                               \
    asm volatile("cp.async.cg.shared.global [%0], [%1], 16;"                  \
                 :: "r"(DST), "l"(SRC))
#define CP_COMMIT()  asm volatile("cp.async.commit_group;" ::: "memory")
#define CP_WAIT_0()  asm volatile("cp.async.wait_group 0;" ::: "memory")
#define CP_WAIT_2()  asm volatile("cp.async.wait_group 2;" ::: "memory")

// ---------------------------------------------------------------------------
// One-time fp32 -> fp16 conversion of inputs and weights (bandwidth-bound).
// ---------------------------------------------------------------------------
__global__ __launch_bounds__(256) void cvt_kernel(
    const float* __restrict__ q, const float* __restrict__ k,
    const float* __restrict__ v,
    const float* __restrict__ wq, const float* __restrict__ wk,
    const float* __restrict__ wv, const float* __restrict__ wo,
    __half* __restrict__ q16, __half* __restrict__ k16,
    __half* __restrict__ v16,
    __half* __restrict__ wq16, __half* __restrict__ wk16,
    __half* __restrict__ wv16, __half* __restrict__ wo16)
{
    const float* src; __half* dst; int n;
    switch (blockIdx.y) {
        case 0: src = q;  dst = q16;  n = MROWS * D_MOD; break;
        case 1: src = k;  dst = k16;  n = MROWS * D_MOD; break;
        case 2: src = v;  dst = v16;  n = MROWS * D_MOD; break;
        case 3: src = wq; dst = wq16; n = D_MOD * D_MOD; break;
        case 4: src = wk; dst = wk16; n = D_MOD * D_MOD; break;
        case 5: src = wv; dst = wv16; n = D_MOD * D_MOD; break;
        default: src = wo; dst = wo16; n = D_MOD * D_MOD; break;
    }
    const int n4 = n >> 2;
    const int stride = gridDim.x * blockDim.x;
    for (int i = blockIdx.x * blockDim.x + threadIdx.x; i < n4; i += stride) {
        float4 f = ((const float4*)src)[i];
        uint2 h;
        h.x = packh2(f.x, f.y);
        h.y = packh2(f.z, f.w);
        ((uint2*)dst)[i] = h;
    }
}

// ---------------------------------------------------------------------------
// FP16 GEMM body, cp.async 4-stage pipeline: C = A @ W^T + bias (fp32 acc).
// 128x128 tile, BK=32, 256 threads (8 warps 2m x 4n), warp 64x32 m16n8k16.
// Stage s (0..3): A fp16[128][40] @ s*20480, W @ s*20480+10240.
// wait_group 2 keeps two stages in flight; empty tail commits keep the
// pending-group count invariant (always 3 before the wait).
// ---------------------------------------------------------------------------
#define GEMM_SMEM_BYTES (81920)

__device__ __forceinline__ void sgemm16_body(
    const __half* __restrict__ A, const __half* __restrict__ W,
    const float* __restrict__ bias, __half* __restrict__ Ch,
    float* __restrict__ Cf)
{
    const int N = D_MOD, K = D_MOD;
    extern __shared__ char smch[];
    const uint32_t smem_base = smem_u32(smch);

    const int bm = blockIdx.y * 128;
    const int bn = blockIdx.x * 128;
    const int tid  = threadIdx.x;
    const int wid  = tid >> 5;
    const int lane = tid & 31;
    const int wm = (wid & 1) * 64;
    const int wn = (wid >> 1) * 32;
    const int gq = lane >> 2;
    const int gr = lane & 3;
    const int lm_row = (lane & 7) + ((lane >> 3) & 1) * 8;
    const int lm_k8  = (lane >> 4) << 3;

    // cp.async per-thread coordinates: rows g_row & g_row+64, 16B chunk g_ch
    const int g_row = tid >> 2;          // 0..63
    const int g_ch  = (tid & 3) << 3;    // halves: 0,8,16,24
    const __half* Agp = A + (size_t)(bm + g_row) * K + g_ch;
    const __half* Wgp = W + (size_t)(bn + g_row) * K + g_ch;
    const uint32_t sA_t = smem_base + (uint32_t)(g_row * 80 + g_ch * 2);
    const uint32_t sW_t = sA_t + 10240;

    auto issue_stage = [&](int s, int k0) {
        const uint32_t so = (uint32_t)(s * 20480);
        CP_ASYNC_CG16(sA_t + so,        Agp + k0);
        CP_ASYNC_CG16(sA_t + so + 5120, Agp + (size_t)64 * K + k0);
        CP_ASYNC_CG16(sW_t + so,        Wgp + k0);
        CP_ASYNC_CG16(sW_t + so + 5120, Wgp + (size_t)64 * K + k0);
        CP_COMMIT();
    };

    float acc[4][4][4];
#pragma unroll
    for (int mt = 0; mt < 4; ++mt)
#pragma unroll
        for (int nt = 0; nt < 4; ++nt)
#pragma unroll
            for (int i = 0; i < 4; ++i) acc[mt][nt][i] = 0.f;

    issue_stage(0, 0);
    issue_stage(1, 32);
    issue_stage(2, 64);

    const int nIter = K >> 5;            // 32
    for (int it = 0; it < nIter; ++it) {
        CP_WAIT_2();                     // groups <= it complete
        __syncthreads();

        const int s = it & 3;
        const __half* Acur = (const __half*)(smch + s * 20480);
        const __half* Wcur = Acur + 5120;

#pragma unroll
        for (int c = 0; c < 2; ++c) {
            uint32_t a[4][4], b[4][2];
#pragma unroll
            for (int mt = 0; mt < 4; ++mt) {
                const uint32_t addr = smem_u32(
                    Acur + (wm + mt * 16 + lm_row) * 40 + c * 16 + lm_k8);
                LDMATRIX_X4(a[mt][0], a[mt][1], a[mt][2], a[mt][3], addr);
            }
#pragma unroll
            for (int nt = 0; nt < 4; ++nt) {
                const __half* wp = Wcur + (wn + nt * 8 + gq) * 40 + c * 16 + 2 * gr;
                b[nt][0] = *(const uint32_t*)wp;
                b[nt][1] = *(const uint32_t*)(wp + 8);
            }
#pragma unroll
            for (int mt = 0; mt < 4; ++mt)
#pragma unroll
                for (int nt = 0; nt < 4; ++nt)
                    MMA_F16(acc[mt][nt], a[mt][0], a[mt][1], a[mt][2], a[mt][3],
                            b[nt][0], b[nt][1]);
        }

        if (it + 3 < nIter) issue_stage((it + 3) & 3, (it + 3) * 32);
        else                CP_COMMIT();   // uniform group accounting
    }

    const int c2 = gr * 2;
#pragma unroll
    for (int mt = 0; mt < 4; ++mt) {
#pragma unroll
        for (int nt = 0; nt < 4; ++nt) {
            const int col = bn + wn + nt * 8 + c2;
            const float b0 = bias[col], b1 = bias[col + 1];
            const size_t row0 = (size_t)(bm + wm + mt * 16 + gq);
            if (Ch) {
                *(uint32_t*)(Ch + row0 * N + col) =
                    packh2(acc[mt][nt][0] + b0, acc[mt][nt][1] + b1);
                *(uint32_t*)(Ch + (row0 + 8) * N + col) =
                    packh2(acc[mt][nt][2] + b0, acc[mt][nt][3] + b1);
            } else {
                float2 v0, v1;
                v0.x = acc[mt][nt][0] + b0; v0.y = acc[mt][nt][1] + b1;
                v1.x = acc[mt][nt][2] + b0; v1.y = acc[mt][nt][3] + b1;
                *(float2*)(Cf + row0 * N + col)       = v0;
                *(float2*)(Cf + (row0 + 8) * N + col) = v1;
            }
        }
    }
}

// Fused Q/K/V projection (fp16 in, fp16 out).
__global__ __launch_bounds__(256, 2) void sgemm_qkv_kernel(
    const __half* __restrict__ Aq, const __half* __restrict__ Ak,
    const __half* __restrict__ Av,
    const __half* __restrict__ Wq, const __half* __restrict__ Wk,
    const __half* __restrict__ Wv,
    const float* __restrict__ bq, const float* __restrict__ bk,
    const float* __restrict__ bv,
    __half* __restrict__ Cq, __half* __restrict__ Ck, __half* __restrict__ Cv)
{
    if (blockIdx.z == 0)      sgemm16_body(Aq, Wq, bq, Cq, nullptr);
    else if (blockIdx.z == 1) sgemm16_body(Ak, Wk, bk, Ck, nullptr);
    else                      sgemm16_body(Av, Wv, bv, Cv, nullptr);
}

// Output projection (fp16 in, fp32 out to d_out).
__global__ __launch_bounds__(256, 2) void sgemm_o_kernel(
    const __half* __restrict__ A, const __half* __restrict__ W,
    const float* __restrict__ bias, float* __restrict__ C)
{
    sgemm16_body(A, W, bias, nullptr, C);
}

// ---------------------------------------------------------------------------
// Flash attention v7: K/V double-buffered via cp.async.
// BM=128, BN=64, DK=64, 8 warps x m16. One barrier per j-iter; stage j+1
// issued after the barrier (readers of that buffer finished at the barrier).
// Smem: sQ[128][72] @0 (18432) + stage s in {0,1}: K[64][72] @18432+s*18432,
//       V[64][72] @18432+s*18432+9216. Total 55296 B.
// Compute path byte-identical to v6b.
// ---------------------------------------------------------------------------
#define FLASH_SMEM_BYTES (55296)

__global__ __launch_bounds__(256, 2) void flash_tc_kernel(
    const __half* __restrict__ Q, const __half* __restrict__ K,
    const __half* __restrict__ V, __half* __restrict__ O)
{
    extern __shared__ char smraw[];
    __half* sQ = (__half*)smraw;           // [128][72]
    const uint32_t smem_base = smem_u32(smraw);

    const int qb  = blockIdx.x;
    const int h   = blockIdx.y;
    const int b   = blockIdx.z;
    const int tid = threadIdx.x;
    const int wid = tid >> 5;
    const int lane = tid & 31;
    const int gq = lane >> 2;    // 0..7
    const int gr = lane & 3;     // 0..3
    const int lm_row = (lane & 7) + ((lane >> 3) & 1) * 8;
    const int lm_k8  = (lane >> 4) << 3;
    const size_t base = (size_t)b * S_LEN * D_MOD + (size_t)h * DKH;

    // cp.async staging coords: row fr & fr+32, 16B chunk fch (halves)
    const int fr  = tid >> 3;            // 0..31
    const int fch = (tid & 7) << 3;      // 0,8,...,56
    const uint32_t kv_dst0 = (uint32_t)(fr * 144 + fch * 2);
    const uint32_t kv_dst1 = (uint32_t)((fr + 32) * 144 + fch * 2);

    auto issue_kv = [&](int s, int j) {
        const uint32_t kb = smem_base + 18432u + (uint32_t)s * 18432u;
        const uint32_t vb = kb + 9216u;
        const __half* kp = K + base + (size_t)(j * 64 + fr) * D_MOD + fch;
        const __half* vp = V + base + (size_t)(j * 64 + fr) * D_MOD + fch;
        CP_ASYNC_CG16(kb + kv_dst0, kp);
        CP_ASYNC_CG16(kb + kv_dst1, kp + (size_t)32 * D_MOD);
        CP_ASYNC_CG16(vb + kv_dst0, vp);
        CP_ASYNC_CG16(vb + kv_dst1, vp + (size_t)32 * D_MOD);
        CP_COMMIT();
    };

    // ---- Stage Q once (plain LDG+STS) ----
#pragma unroll
    for (int t = 0; t < 4; ++t) {
        int idx = tid + t * 256;
        int r    = idx >> 3;               // 0..127
        int colh = (idx & 7) << 3;         // 0,8,...,56
        uint4 v = *(const uint4*)(Q + base + (size_t)(qb * 128 + r) * D_MOD + colh);
        *(uint4*)(sQ + r * 72 + colh) = v;
    }

    issue_kv(0, 0);                        // prologue

    float o[8][4];
#pragma unroll
    for (int nt = 0; nt < 8; ++nt)
#pragma unroll
        for (int i = 0; i < 4; ++i) o[nt][i] = 0.f;
    float m0 = -1e30f, m1 = -1e30f, l0 = 0.f, l1 = 0.f;

    const int row0 = qb * 128 + wid * 16 + gq;
    const int row1 = row0 + 8;
    const float scale = 0.125f;            // 1/sqrt(64)
    const int jmax = 2 * qb + 1;

    for (int j = 0; j <= jmax; ++j) {
        CP_WAIT_0();       // stage j complete (only pending group)
        __syncthreads();   // visible to all; readers of buffer (j+1)&1 done
        if (j + 1 <= jmax) issue_kv((j + 1) & 1, j + 1);

        const int s = j & 1;
        __half* sK = (__half*)(smraw + 18432 + s * 18432);
        __half* sV = sK + 4608;            // 9216 B = 4608 halves
        const uint32_t vmat_base = smem_base + 18432u + (uint32_t)s * 18432u
                                 + 9216u + (uint32_t)(lane & 15) * 144u
                                 + (uint32_t)((lane >> 4) << 4);

        // ---- S = Q K^T : fp16 m16n8k16 ----
        float sc[8][4];
#pragma unroll
        for (int nt = 0; nt < 8; ++nt)
#pragma unroll
            for (int i = 0; i < 4; ++i) sc[nt][i] = 0.f;

        const int qrowb = wid * 16;
#pragma unroll
        for (int c = 0; c < 4; ++c) {
            uint32_t a0, a1, a2, a3;
            const uint32_t addr = smem_u32(
                sQ + (qrowb + lm_row) * 72 + c * 16 + lm_k8);
            LDMATRIX_X4(a0, a1, a2, a3, addr);
#pragma unroll
            for (int nt = 0; nt < 8; ++nt) {
                const __half* kp = sK + (nt * 8 + gq) * 72 + c * 16 + 2 * gr;
                MMA_F16(sc[nt], a0, a1, a2, a3,
                        *(const uint32_t*)kp, *(const uint32_t*)(kp + 8));
            }
        }

        // ---- scale + causal mask ----
        const bool diag = (j >= 2 * qb);
#pragma unroll
        for (int nt = 0; nt < 8; ++nt) {
            const int colb = j * 64 + nt * 8 + 2 * gr;
#pragma unroll
            for (int e = 0; e < 4; ++e) {
                sc[nt][e] *= scale;
                if (diag) {
                    const int col = colb + (e & 1);
                    const int row = (e < 2) ? row0 : row1;
                    if (col > row) sc[nt][e] = -1e30f;
                }
            }
        }

        // ---- online softmax ----
        float mt0 = -1e30f, mt1 = -1e30f;
#pragma unroll
        for (int nt = 0; nt < 8; ++nt) {
            mt0 = fmaxf(mt0, fmaxf(sc[nt][0], sc[nt][1]));
            mt1 = fmaxf(mt1, fmaxf(sc[nt][2], sc[nt][3]));
        }
        mt0 = fmaxf(mt0, __shfl_xor_sync(0xffffffffu, mt0, 1));
        mt0 = fmaxf(mt0, __shfl_xor_sync(0xffffffffu, mt0, 2));
        mt1 = fmaxf(mt1, __shfl_xor_sync(0xffffffffu, mt1, 1));
        mt1 = fmaxf(mt1, __shfl_xor_sync(0xffffffffu, mt1, 2));
        const float mn0 = fmaxf(m0, mt0);
        const float mn1 = fmaxf(m1, mt1);
        const float alpha0 = __expf(m0 - mn0);
        const float alpha1 = __expf(m1 - mn1);
        m0 = mn0; m1 = mn1;

        float rs0 = 0.f, rs1 = 0.f;
#pragma unroll
        for (int nt = 0; nt < 8; ++nt) {
            sc[nt][0] = __expf(sc[nt][0] - m0);
            sc[nt][1] = __expf(sc[nt][1] - m0);
            sc[nt][2] = __expf(sc[nt][2] - m1);
            sc[nt][3] = __expf(sc[nt][3] - m1);
            rs0 += sc[nt][0] + sc[nt][1];
            rs1 += sc[nt][2] + sc[nt][3];
        }
        rs0 += __shfl_xor_sync(0xffffffffu, rs0, 1);
        rs0 += __shfl_xor_sync(0xffffffffu, rs0, 2);
        rs1 += __shfl_xor_sync(0xffffffffu, rs1, 1);
        rs1 += __shfl_xor_sync(0xffffffffu, rs1, 2);
        l0 = l0 * alpha0 + rs0;
        l1 = l1 * alpha1 + rs1;
#pragma unroll
        for (int nt = 0; nt < 8; ++nt) {
            o[nt][0] *= alpha0; o[nt][1] *= alpha0;
            o[nt][2] *= alpha1; o[nt][3] *= alpha1;
        }

        // ---- O += P V : fp16 m16n8k16, B-frags via ldmatrix.x4.trans ----
#pragma unroll
        for (int c = 0; c < 4; ++c) {
            uint32_t pa0 = packh2(sc[2 * c][0],     sc[2 * c][1]);
            uint32_t pa1 = packh2(sc[2 * c][2],     sc[2 * c][3]);
            uint32_t pa2 = packh2(sc[2 * c + 1][0], sc[2 * c + 1][1]);
            uint32_t pa3 = packh2(sc[2 * c + 1][2], sc[2 * c + 1][3]);
            const uint32_t abase = vmat_base + (uint32_t)(c * 16 * 144);
#pragma unroll
            for (int ntp = 0; ntp < 4; ++ntp) {
                uint32_t r0, r1, r2, r3;
                LDMATRIX_X4_TRANS(r0, r1, r2, r3, abase + ntp * 32);
                MMA_F16(o[2 * ntp],     pa0, pa1, pa2, pa3, r0, r1);
                MMA_F16(o[2 * ntp + 1], pa0, pa1, pa2, pa3, r2, r3);
            }
        }
    }

    // ---- epilogue: fp16 output ----
    const float inv0 = 1.0f / l0;
    const float inv1 = 1.0f / l1;
#pragma unroll
    for (int nt = 0; nt < 8; ++nt) {
        const int dv = nt * 8 + 2 * gr;
        *(uint32_t*)(O + base + (size_t)row0 * D_MOD + dv) =
            packh2(o[nt][0] * inv0, o[nt][1] * inv0);
        *(uint32_t*)(O + base + (size_t)row1 * D_MOD + dv) =
            packh2(o[nt][2] * inv1, o[nt][3] * inv1);
    }
}

// ---------------------------------------------------------------------------
extern "C" void kernel_launch(void* const* d_in, const int* in_sizes, int n_in,
                              void* d_out, int out_size)
{
    const float* query = (const float*)d_in[0];
    const float* key_  = (const float*)d_in[1];
    const float* value = (const float*)d_in[2];
    const float* Wq = (const float*)d_in[3];
    const float* bq = (const float*)d_in[4];
    const float* Wk = (const float*)d_in[5];
    const float* bk = (const float*)d_in[6];
    const float* Wv = (const float*)d_in[7];
    const float* bv = (const float*)d_in[8];
    const float* Wo = (const float*)d_in[9];
    const float* bo = (const float*)d_in[10];
    // d_in[11] = causal mask (bool) — causality implemented analytically.

    __half *Aq16, *Ak16, *Av16, *Wq16, *Wk16, *Wv16, *Wo16;
    __half *Q16, *K16, *V16, *O16;
    cudaGetSymbolAddress((void**)&Aq16, g_Aq16);
    cudaGetSymbolAddress((void**)&Ak16, g_Ak16);
    cudaGetSymbolAddress((void**)&Av16, g_Av16);
    cudaGetSymbolAddress((void**)&Wq16, g_Wq16);
    cudaGetSymbolAddress((void**)&Wk16, g_Wk16);
    cudaGetSymbolAddress((void**)&Wv16, g_Wv16);
    cudaGetSymbolAddress((void**)&Wo16, g_Wo16);
    cudaGetSymbolAddress((void**)&Q16, g_Q16);
    cudaGetSymbolAddress((void**)&K16, g_K16);
    cudaGetSymbolAddress((void**)&V16, g_V16);
    cudaGetSymbolAddress((void**)&O16, g_O16);

    cudaFuncSetAttribute(sgemm_qkv_kernel,
                         cudaFuncAttributeMaxDynamicSharedMemorySize, GEMM_SMEM_BYTES);
    cudaFuncSetAttribute(sgemm_o_kernel,
                         cudaFuncAttributeMaxDynamicSharedMemorySize, GEMM_SMEM_BYTES);
    cudaFuncSetAttribute(flash_tc_kernel,
                         cudaFuncAttributeMaxDynamicSharedMemorySize, FLASH_SMEM_BYTES);

    // 1. Convert inputs + weights to fp16 (one pass, bandwidth-bound).
    cvt_kernel<<<dim3(2048, 7), 256>>>(
        query, key_, value, Wq, Wk, Wv, Wo,
        Aq16, Ak16, Av16, Wq16, Wk16, Wv16, Wo16);

    // 2. Fused Q/K/V projections (fp16 -> fp16 scratch).
    dim3 gqkv(D_MOD / 128, MROWS / 128, 3);
    sgemm_qkv_kernel<<<gqkv, 256, GEMM_SMEM_BYTES>>>(
        Aq16, Ak16, Av16, Wq16, Wk16, Wv16, bq, bk, bv, Q16, K16, V16);

    // 3. Flash attention (fp16 -> fp16, K/V double-buffered).
    flash_tc_kernel<<<dim3(S_LEN / 128, NH, B_SZ), 256, FLASH_SMEM_BYTES>>>(
        Q16, K16, V16, O16);

    // 4. Output projection (fp16 -> fp32 d_out).
    dim3 gg(D_MOD / 128, MROWS / 128);
    sgemm_o_kernel<<<gg, 256, GEMM_SMEM_BYTES>>>(O16, Wo16, bo, (float*)d_out);
}